// round 7
// baseline (speedup 1.0000x reference)
#include <cuda_runtime.h>
#include <cuda_bf16.h>
#include <math.h>
#include <stdint.h>

// ---------------------------------------------------------------- constants
#define TT     512
#define BB     128
#define DDIM   512
#define HH     64
#define NROWS  (TT * BB)          // 65536 independent (t,b) rows
#define NG     192                // 3 gates (i, g, o) x 64 qubits
#define EPSV   1e-5f

// Arch-specific feature gate: tcgen05 exists only on sm_10xa targets.
#if defined(__CUDA_ARCH__) && (defined(__CUDA_ARCH_FEAT_SM103_ALL) || \
    defined(__CUDA_ARCH_FEAT_SM100_ALL) || defined(__CUDA_ARCH_SPECIFIC__))
#define HAS_TC 1
#endif

// dynamic SMEM layout: A double-buffered, B single, params overlaid on A-buf1
//   A bufs: buf b at b*32768; hi +0 (16KB), lo +16384
//   B:      65536; hi +0 (24KB), lo +24576
//   params: overlay at 32768 (A-buf1; used only after mainloop)
//   ctrl:   114688 (tmem ptr +0, mbar0 +8, mbar1 +16)
#define OFF_A      0
#define OFF_B      65536
#define OFF_PAR    32768
#define OFF_CTRL   114688
#define SMEM_TOTAL 114752

// idesc: kind::f16, bf16 x bf16 -> f32, M=128, N=192
#define IDESC ((1u << 4) | (1u << 7) | (1u << 10) | ((NG / 8) << 17) | ((128 / 16) << 24))

// ---------------------------------------------------------------- scratch
__device__ __nv_bfloat16  g_B0hi[8 * NG * 64];   // W0: 8 K-chunks, SW128 swizzled
__device__ __nv_bfloat16  g_B0lo[8 * NG * 64];
__device__ __nv_bfloat16  g_B1hi[NG * 64];       // W1: 1 K-chunk
__device__ __nv_bfloat16  g_B1lo[NG * 64];

// ================================================================ prolog
__global__ void prep_w_kernel(const float* __restrict__ W0,
                              const float* __restrict__ W1) {
#ifdef HAS_TC
    int idx = blockIdx.x * blockDim.x + threadIdx.x;
    if (idx < 8 * NG * 64) {
        int c   = idx / (NG * 64);
        int rem = idx % (NG * 64);
        int n   = rem / 64, kl = rem % 64;
        float w = W0[(size_t)(64 + n) * (DDIM + HH) + c * 64 + kl];
        __nv_bfloat16 hi = __float2bfloat16(w);
        __nv_bfloat16 lo = __float2bfloat16(w - __bfloat162float(hi));
        uint32_t boff = ((uint32_t)(n >> 3)) * 1024 + ((uint32_t)(n & 7)) * 128 + kl * 2;
        boff ^= ((boff >> 3) & 0x70);
        g_B0hi[(size_t)c * (NG * 64) + boff / 2] = hi;
        g_B0lo[(size_t)c * (NG * 64) + boff / 2] = lo;
    }
    if (idx < NG * 64) {
        int n = idx / 64, kl = idx % 64;
        float w = W1[(size_t)(64 + n) * (HH + HH) + kl];
        __nv_bfloat16 hi = __float2bfloat16(w);
        __nv_bfloat16 lo = __float2bfloat16(w - __bfloat162float(hi));
        uint32_t boff = ((uint32_t)(n >> 3)) * 1024 + ((uint32_t)(n & 7)) * 128 + kl * 2;
        boff ^= ((boff >> 3) & 0x70);
        g_B1hi[boff / 2] = hi;
        g_B1lo[boff / 2] = lo;
    }
#endif
}

// ================================================================ PTX helpers
#ifdef HAS_TC
static __device__ __forceinline__ uint32_t smem_u32(const void* p) {
    uint32_t a;
    asm("{ .reg .u64 t; cvta.to.shared.u64 t, %1; cvt.u32.u64 %0, t; }"
        : "=r"(a) : "l"(p));
    return a;
}
static __device__ __forceinline__ uint32_t elect1() {
    uint32_t p;
    asm volatile("{\n .reg .pred p;\n elect.sync _|p, 0xFFFFFFFF;\n selp.b32 %0,1,0,p;\n}"
                 : "=r"(p));
    return p;
}
static __device__ __forceinline__ uint64_t sdesc(uint32_t addr) {
    return (2ull << 61) | (1ull << 46) | (64ull << 32) | (1ull << 16)
         | ((uint64_t)(addr >> 4) & 0x3FFF);
}
static __device__ __forceinline__ void mma_bf16_ss(uint32_t d, uint64_t ad, uint64_t bd,
                                                   uint32_t idesc, bool accum) {
    uint32_t en = accum ? 1u : 0u;
    asm volatile(
        "{\n\t"
        ".reg .pred p;\n\t"
        "setp.ne.u32 p, %5, 0;\n\t"
        "tcgen05.mma.cta_group::1.kind::f16 [%0], %1, %2, %3, {%4, %4, %4, %4}, p;\n\t"
        "}"
        :: "r"(d), "l"(ad), "l"(bd), "r"(idesc), "r"(0u), "r"(en)
        : "memory");
}
static __device__ __forceinline__ void mbar_wait(uint32_t mbar, uint32_t parity) {
    uint32_t done;
    asm volatile(
        "{\n .reg .pred p;\n"
        " mbarrier.try_wait.parity.acquire.cta.shared::cta.b64 p, [%1], %2;\n"
        " selp.b32 %0, 1, 0, p;\n}"
        : "=r"(done) : "r"(mbar), "r"(parity) : "memory");
    if (!done) {
        asm volatile(
            "{\n .reg .pred P1;\n"
            "WL%=:\n"
            " mbarrier.try_wait.parity.acquire.cta.shared::cta.b64 P1, [%0], %1, 0x989680;\n"
            " @P1 bra.uni WD%=;\n"
            " bra.uni WL%=;\n"
            "WD%=:\n}"
            :: "r"(mbar), "r"(parity) : "memory");
    }
}
#define TC_WAIT_LD() asm volatile("tcgen05.wait::ld.sync.aligned;" ::: "memory")
#define LDTM_X32(r, addr)                                              \
    asm volatile(                                                       \
        "tcgen05.ld.sync.aligned.32x32b.x32.b32 "                       \
        "{%0, %1, %2, %3, %4, %5, %6, %7, "                             \
        " %8, %9, %10, %11, %12, %13, %14, %15, "                       \
        " %16, %17, %18, %19, %20, %21, %22, %23, "                     \
        " %24, %25, %26, %27, %28, %29, %30, %31}, [%32];"              \
        : "=r"((r)[0]),  "=r"((r)[1]),  "=r"((r)[2]),  "=r"((r)[3]),    \
          "=r"((r)[4]),  "=r"((r)[5]),  "=r"((r)[6]),  "=r"((r)[7]),    \
          "=r"((r)[8]),  "=r"((r)[9]),  "=r"((r)[10]), "=r"((r)[11]),   \
          "=r"((r)[12]), "=r"((r)[13]), "=r"((r)[14]), "=r"((r)[15]),   \
          "=r"((r)[16]), "=r"((r)[17]), "=r"((r)[18]), "=r"((r)[19]),   \
          "=r"((r)[20]), "=r"((r)[21]), "=r"((r)[22]), "=r"((r)[23]),   \
          "=r"((r)[24]), "=r"((r)[25]), "=r"((r)[26]), "=r"((r)[27]),   \
          "=r"((r)[28]), "=r"((r)[29]), "=r"((r)[30]), "=r"((r)[31])    \
        : "r"(addr))

static __device__ __forceinline__ float frcp(float x) {
    float y; asm("rcp.approx.f32 %0, %1;" : "=f"(y) : "f"(x)); return y;
}
// sigmoid(q), |q| <= 1: odd Taylor/poly deg-11, err ~2e-7, FMA-only (0 MUFU)
static __device__ __forceinline__ float psig(float q) {
    float u = q * q;
    float p = fmaf(u, -2.1638741e-6f, 2.1358436e-5f);
    p = fmaf(u, p, -2.1081349e-4f);
    p = fmaf(u, p,  2.0833333e-3f);
    p = fmaf(u, p, -2.0833333e-2f);
    p = fmaf(u, p,  0.25f);
    return fmaf(q, p, 0.5f);
}
// tanh(x), 0 <= x <= 0.75: Pade(7,6), err < 1e-8, 1 MUFU rcp + FMAs
static __device__ __forceinline__ float ptanh(float x) {
    float u = x * x;
    float n = fmaf(u + 378.0f, u, 17325.0f);
    n = fmaf(n, u, 135135.0f);
    float d = fmaf(28.0f, u, 3150.0f);
    d = fmaf(d, u, 62370.0f);
    d = fmaf(d, u, 135135.0f);
    return x * n * frcp(d);
}

// ---------------------------------------------------------------- epilogue half
template <bool L0>
static __device__ __forceinline__ void epilogue_half(
    uint32_t tmem, const float* __restrict__ bt,
    const float* __restrict__ gm, const float* __restrict__ bet,
    volatile float* ex0, volatile float* ex1,
    char* ahi, char* alo, float* __restrict__ outp,
    float* __restrict__ hlast, float* __restrict__ clast,
    int half, int rl, int myrow)
{
    float hv[32], cs[32];
    uint32_t* ru = (uint32_t*)cs;
    const int colbase = half * 32;
    const bool tail = (myrow >= NROWS - BB);
    const int tb = myrow - (NROWS - BB);

#pragma unroll
    for (int g = 0; g < 3; g++) {
        LDTM_X32(ru, tmem + g * 64 + colbase);
        TC_WAIT_LD();
#pragma unroll
        for (int j = 0; j < 32; j++)
            cs[j] = __cosf(__uint_as_float(ru[j]) + bt[g * 64 + colbase + j]);
#pragma unroll
        for (int g8 = 0; g8 < 4; g8++)
#pragma unroll
            for (int j = 1; j < 8; j++)
                cs[g8 * 8 + j] *= cs[g8 * 8 + j - 1];
        float pref = 1.0f;
#pragma unroll
        for (int g8 = 0; g8 < 4; g8++) {
            float tot = cs[g8 * 8 + 7];
#pragma unroll
            for (int j = 0; j < 8; j++) cs[g8 * 8 + j] *= pref;
            pref *= tot;
        }
        if (half == 0) ex0[rl] = pref;
        __syncthreads();
        if (half == 1) {
            float p = ex0[rl];
#pragma unroll
            for (int j = 0; j < 32; j++) cs[j] *= p;
        }
        __syncthreads();

        if (g == 0) {
#pragma unroll
            for (int j = 0; j < 32; j++) hv[j] = psig(cs[j]);
        } else if (g == 1) {
#pragma unroll
            for (int j = 0; j < 32; j++) hv[j] *= ptanh(psig(cs[j]));   // c
            if (tail) {
                float4* cd = (float4*)(clast + (size_t)tb * HH) + half * 8;
#pragma unroll
                for (int j = 0; j < 8; j++)
                    cd[j] = make_float4(hv[4*j], hv[4*j+1], hv[4*j+2], hv[4*j+3]);
            }
        } else {
#pragma unroll
            for (int j = 0; j < 32; j++) hv[j] = psig(cs[j]) * ptanh(hv[j]);  // h
        }
    }

    // layernorm across the pair
    float s = 0.0f;
#pragma unroll
    for (int j = 0; j < 32; j++) s += hv[j];
    if (half == 0) ex0[rl] = s; else ex1[rl] = s;
    __syncthreads();
    float mu = (ex0[rl] + ex1[rl]) * (1.0f / 64.0f);
    float q = 0.0f;
#pragma unroll
    for (int j = 0; j < 32; j++) { float d = hv[j] - mu; q += d * d; }
    __syncthreads();
    if (half == 0) ex0[rl] = q; else ex1[rl] = q;
    __syncthreads();
    float rinv = rsqrtf((ex0[rl] + ex1[rl]) * (1.0f / 64.0f) + EPSV);
#pragma unroll
    for (int j = 0; j < 32; j++)
        hv[j] = (hv[j] - mu) * rinv * gm[colbase + j] + bet[colbase + j];

    if (L0) {
#pragma unroll
        for (int j8 = 0; j8 < 4; j8++) {
            __nv_bfloat162 ph[4], pl[4];
#pragma unroll
            for (int p2 = 0; p2 < 4; p2++) {
                float v0 = hv[j8 * 8 + p2 * 2], v1 = hv[j8 * 8 + p2 * 2 + 1];
                __nv_bfloat16 h0 = __float2bfloat16(v0);
                __nv_bfloat16 h1 = __float2bfloat16(v1);
                ph[p2] = __nv_bfloat162(h0, h1);
                pl[p2] = __nv_bfloat162(__float2bfloat16(v0 - __bfloat162float(h0)),
                                        __float2bfloat16(v1 - __bfloat162float(h1)));
            }
            uint32_t off = (uint32_t)rl * 128 + (uint32_t)colbase * 2 + j8 * 16;
            off ^= ((off >> 3) & 0x70);
            *(uint4*)(ahi + off) = *(uint4*)ph;
            *(uint4*)(alo + off) = *(uint4*)pl;
        }
        if (tail) {
            float4* hd = (float4*)(hlast + (size_t)tb * HH) + half * 8;
#pragma unroll
            for (int j = 0; j < 8; j++)
                hd[j] = make_float4(hv[4*j], hv[4*j+1], hv[4*j+2], hv[4*j+3]);
        }
    } else {
        float4* od = (float4*)(outp + (size_t)myrow * HH) + half * 8;
#pragma unroll
        for (int j = 0; j < 8; j++)
            od[j] = make_float4(hv[4*j], hv[4*j+1], hv[4*j+2], hv[4*j+3]);
        if (tail) {
            float4* hd = (float4*)(hlast + (size_t)tb * HH) + half * 8;
#pragma unroll
            for (int j = 0; j < 8; j++)
                hd[j] = make_float4(hv[4*j], hv[4*j+1], hv[4*j+2], hv[4*j+3]);
        }
    }
    __syncthreads();
}
#endif // HAS_TC

// ================================================================ fused kernel
__global__ void __launch_bounds__(256, 2)
qlstm_fused_kernel(const float* __restrict__ x,
                   const float* __restrict__ W0raw,
                   const float* __restrict__ W1raw,
                   const __nv_bfloat16* __restrict__ B0hi_g,
                   const __nv_bfloat16* __restrict__ B0lo_g,
                   const __nv_bfloat16* __restrict__ B1hi_g,
                   const __nv_bfloat16* __restrict__ B1lo_g,
                   const float* __restrict__ b0, const float* __restrict__ th0,
                   const float* __restrict__ g0, const float* __restrict__ be0,
                   const float* __restrict__ b1, const float* __restrict__ th1,
                   const float* __restrict__ g1, const float* __restrict__ be1,
                   float* __restrict__ out,
                   float* __restrict__ h0last, float* __restrict__ c0last,
                   float* __restrict__ h1last, float* __restrict__ c1last)
{
    extern __shared__ __align__(1024) char smem[];
    const int tid = threadIdx.x, wid = tid >> 5, lane = tid & 31;
    const int half = wid >> 2;
    const int rl   = (wid & 3) * 32 + lane;     // local row 0..127
    const int row0 = blockIdx.x * 128;
    const int myrow = row0 + rl;

    // params live in the A-buf1 overlay (valid only after the layer-0 mainloop
    // in the TC path; written at entry in the fallback path)
    float* fp   = (float*)(smem + OFF_PAR);
    float* bt0  = fp;          // 192
    float* bt1  = fp + 192;    // 192
    float* gm0  = fp + 384;    // 64
    float* bet0 = fp + 448;
    float* gm1  = fp + 512;
    float* bet1 = fp + 576;
    float* ex0  = fp + 640;    // 128
    float* ex1  = fp + 768;    // 128

#ifdef HAS_TC
    constexpr int NC = 8;
    const uint32_t sb = smem_u32(smem);
    const uint32_t mb0 = sb + OFF_CTRL + 8;
    const uint32_t mb1 = sb + OFF_CTRL + 16;
    if (wid == 0) {
        asm volatile("tcgen05.alloc.cta_group::1.sync.aligned.shared::cta.b32 [%0], %1;"
                     :: "r"(sb + OFF_CTRL), "r"(256u) : "memory");
        asm volatile("tcgen05.relinquish_alloc_permit.cta_group::1.sync.aligned;");
    }
    if (tid == 0) {
        asm volatile("mbarrier.init.shared.b64 [%0], %1;" :: "r"(mb0), "r"(1u) : "memory");
        asm volatile("mbarrier.init.shared.b64 [%0], %1;" :: "r"(mb1), "r"(1u) : "memory");
    }
    __syncthreads();
    uint32_t tmem;
    asm volatile("ld.shared.b32 %0, [%1];" : "=r"(tmem) : "r"(sb + OFF_CTRL));

    const uint64_t bHd = sdesc(sb + OFF_B);
    const uint64_t bLd = sdesc(sb + OFF_B + 24576);

    // ---------------- layer-0 pipelined K-chunk loop ----------------
    for (int c = 0; c < NC; c++) {
        const uint32_t mbc  = (c & 1) ? mb1 : mb0;         // commit target / A-gate
        const uint32_t mbp  = (c & 1) ? mb0 : mb1;         // commit(c-1) barrier

        // B(c): prefetch to registers (L2 latency overlaps A phase + MMA(c-1))
        uint4 bhr[6], blr[6];
        {
            const uint4* bh = (const uint4*)(B0hi_g + (size_t)c * (NG * 64));
            const uint4* bl = (const uint4*)(B0lo_g + (size_t)c * (NG * 64));
#pragma unroll
            for (int j = 0; j < 6; j++) {
                bhr[j] = bh[tid + j * 256];
                blr[j] = bl[tid + j * 256];
            }
        }

        // A buffer reuse gate: commit(c-2) done
        if (c >= 2) mbar_wait(mbc, ((c >> 1) - 1) & 1);

        // A(c): fp32 -> bf16 hi/lo, SW128-swizzled STS into buf[c&1]
        {
            char* ah = smem + OFF_A + (c & 1) * 32768;
            char* al = ah + 16384;
#pragma unroll
            for (int j = 0; j < 8; j++) {
                int idx = tid + j * 256;
                int r = idx >> 4, s = idx & 15;
                float4 v = *(const float4*)(x + (size_t)(row0 + r) * DDIM + c * 64 + s * 4);
                __nv_bfloat16 hx = __float2bfloat16(v.x);
                __nv_bfloat16 hy = __float2bfloat16(v.y);
                __nv_bfloat16 hz = __float2bfloat16(v.z);
                __nv_bfloat16 hw = __float2bfloat16(v.w);
                __nv_bfloat16 lx = __float2bfloat16(v.x - __bfloat162float(hx));
                __nv_bfloat16 ly = __float2bfloat16(v.y - __bfloat162float(hy));
                __nv_bfloat16 lz = __float2bfloat16(v.z - __bfloat162float(hz));
                __nv_bfloat16 lw = __float2bfloat16(v.w - __bfloat162float(hw));
                uint32_t off = (uint32_t)r * 128 + (uint32_t)s * 8;
                off ^= ((off >> 3) & 0x70);
                *(__nv_bfloat162*)(ah + off)     = __nv_bfloat162(hx, hy);
                *(__nv_bfloat162*)(ah + off + 4) = __nv_bfloat162(hz, hw);
                *(__nv_bfloat162*)(al + off)     = __nv_bfloat162(lx, ly);
                *(__nv_bfloat162*)(al + off + 4) = __nv_bfloat162(lz, lw);
            }
        }

        // B buffer free: commit(c-1) done, then store prefetched B regs
        if (c >= 1) mbar_wait(mbp, ((c - 1) >> 1) & 1);
        {
            uint4* sh = (uint4*)(smem + OFF_B);
            uint4* sl = (uint4*)(smem + OFF_B + 24576);
#pragma unroll
            for (int j = 0; j < 6; j++) {
                sh[tid + j * 256] = bhr[j];
                sl[tid + j * 256] = blr[j];
            }
        }
        __syncthreads();

        if (wid == 0 && elect1()) {
            asm volatile("fence.proxy.async.shared::cta;" ::: "memory");
            uint64_t aH = sdesc(sb + OFF_A + (c & 1) * 32768);
            uint64_t aL = sdesc(sb + OFF_A + (c & 1) * 32768 + 16384);
#pragma unroll
            for (int ks = 0; ks < 4; ks++)
                mma_bf16_ss(tmem, aH + ks * 2, bHd + ks * 2, IDESC, !(c == 0 && ks == 0));
#pragma unroll
            for (int ks = 0; ks < 4; ks++)
                mma_bf16_ss(tmem, aH + ks * 2, bLd + ks * 2, IDESC, true);
#pragma unroll
            for (int ks = 0; ks < 4; ks++)
                mma_bf16_ss(tmem, aL + ks * 2, bHd + ks * 2, IDESC, true);
            asm volatile(
                "tcgen05.commit.cta_group::1.mbarrier::arrive::one.shared::cluster.b64 [%0];"
                :: "r"(mbc) : "memory");
        }
    }

    // final commit: chunk 7 -> mb1, phase idx 3 -> parity 1
    mbar_wait(mb1, 1);
    asm volatile("tcgen05.fence::after_thread_sync;" ::: "memory");

    // B1 into the B buffer + params into the A-buf1 overlay
    {
        const uint4* bh = (const uint4*)B1hi_g;
        const uint4* bl = (const uint4*)B1lo_g;
        uint4* sh = (uint4*)(smem + OFF_B);
        uint4* sl = (uint4*)(smem + OFF_B + 24576);
#pragma unroll
        for (int j = 0; j < 6; j++) {
            sh[tid + j * 256] = bh[tid + j * 256];
            sl[tid + j * 256] = bl[tid + j * 256];
        }
    }
    if (tid < NG) {
        bt0[tid] = b0[64 + tid] + th0[64 + tid];
        bt1[tid] = b1[64 + tid] + th1[64 + tid];
    }
    if (tid >= 192 && tid < 256) {
        int i = tid - 192;
        gm0[i] = g0[i]; bet0[i] = be0[i];
        gm1[i] = g1[i]; bet1[i] = be1[i];
    }
    __syncthreads();

    // ---------------- epilogue 0 (writes layer-1 A tile into buf0) ---------
    char* ah0 = smem + OFF_A;
    char* al0 = smem + OFF_A + 16384;
    epilogue_half<true>(tmem, bt0, gm0, bet0, ex0, ex1, ah0, al0,
                        nullptr, h0last, c0last, half, rl, myrow);

    asm volatile("tcgen05.fence::before_thread_sync;" ::: "memory");
    __syncthreads();

    // ---------------- layer-1 GEMM (K=64, reuse TMEM cols 0-191) ----------
    if (wid == 0 && elect1()) {
        asm volatile("tcgen05.fence::after_thread_sync;" ::: "memory");
        asm volatile("fence.proxy.async.shared::cta;" ::: "memory");
        uint64_t aH = sdesc(sb + OFF_A);
        uint64_t aL = sdesc(sb + OFF_A + 16384);
#pragma unroll
        for (int ks = 0; ks < 4; ks++)
            mma_bf16_ss(tmem, aH + ks * 2, bHd + ks * 2, IDESC, ks != 0);
#pragma unroll
        for (int ks = 0; ks < 4; ks++)
            mma_bf16_ss(tmem, aH + ks * 2, bLd + ks * 2, IDESC, true);
#pragma unroll
        for (int ks = 0; ks < 4; ks++)
            mma_bf16_ss(tmem, aL + ks * 2, bHd + ks * 2, IDESC, true);
        asm volatile(
            "tcgen05.commit.cta_group::1.mbarrier::arrive::one.shared::cluster.b64 [%0];"
            :: "r"(mb0) : "memory");
    }
    // mb0 has completed phases 0..3 (chunks 0,2,4,6); layer-1 is idx 4 -> parity 0
    mbar_wait(mb0, 0);
    asm volatile("tcgen05.fence::after_thread_sync;" ::: "memory");

    // ---------------- epilogue 1 (writes final output) ----------------
    epilogue_half<false>(tmem, bt1, gm1, bet1, ex0, ex1, nullptr, nullptr,
                         out, h1last, c1last, half, rl, myrow);

    asm volatile("tcgen05.fence::before_thread_sync;" ::: "memory");
    __syncthreads();
    if (wid == 0) {
        asm volatile("tcgen05.dealloc.cta_group::1.sync.aligned.b32 %0, %1;"
                     :: "r"(tmem), "r"(256u));
    }

#else  // ---------------- scalar fallback (correctness-only) ----------------
    float* xs = (float*)smem;                    // [128][64] fp32 (0..32KB)
    float* ws = (float*)(smem + 36864);          // [192][64] fp32 (48KB)
    const int colbase = half * 32;
    const bool tail = (myrow >= NROWS - BB);
    const int tb = myrow - (NROWS - BB);

    if (tid < NG) {
        bt0[tid] = b0[64 + tid] + th0[64 + tid];
        bt1[tid] = b1[64 + tid] + th1[64 + tid];
    }
    if (tid >= 192 && tid < 256) {
        int i = tid - 192;
        gm0[i] = g0[i]; bet0[i] = be0[i];
        gm1[i] = g1[i]; bet1[i] = be1[i];
    }
    __syncthreads();

    float z[96];
#pragma unroll
    for (int i = 0; i < 96; i++) z[i] = 0.0f;

    for (int kt = 0; kt < 8; kt++) {
        __syncthreads();
        for (int i = tid; i < 128 * 16; i += 256) {
            int r = i >> 4, s = i & 15;
            *(float4*)&xs[r * 64 + s * 4] =
                *(const float4*)(x + (size_t)(row0 + r) * DDIM + kt * 64 + s * 4);
        }
        for (int i = tid; i < 192 * 16; i += 256) {
            int n = i >> 4, s = i & 15;
            *(float4*)&ws[n * 64 + s * 4] =
                *(const float4*)(W0raw + (size_t)(64 + n) * (DDIM + HH) + kt * 64 + s * 4);
        }
        __syncthreads();
        for (int g = 0; g < 3; g++)
            for (int j = 0; j < 32; j++) {
                int n = g * 64 + colbase + j;
                float acc = z[g * 32 + j];
                for (int k = 0; k < 64; k++)
                    acc = fmaf(xs[rl * 64 + k], ws[n * 64 + k], acc);
                z[g * 32 + j] = acc;
            }
    }

    for (int layer = 0; layer < 2; layer++) {
        const float* bt  = layer ? bt1  : bt0;
        const float* gm  = layer ? gm1  : gm0;
        const float* bet = layer ? bet1 : bet0;
        float* hl = layer ? h1last : h0last;
        float* cl = layer ? c1last : c0last;
        float hv[32];
        for (int g = 0; g < 3; g++) {
            float cs[32];
            for (int j = 0; j < 32; j++)
                cs[j] = cosf(z[g * 32 + j] + bt[g * 64 + colbase + j]);
            for (int j = 1; j < 32; j++) cs[j] *= cs[j - 1];
            if (half == 0) ex0[rl] = cs[31];
            __syncthreads();
            if (half == 1) { float p = ex0[rl]; for (int j = 0; j < 32; j++) cs[j] *= p; }
            __syncthreads();
            if (g == 0)      for (int j = 0; j < 32; j++) hv[j] = 1.0f / (1.0f + expf(-cs[j]));
            else if (g == 1) {
                for (int j = 0; j < 32; j++) hv[j] *= tanhf(1.0f / (1.0f + expf(-cs[j])));
                if (tail) for (int j = 0; j < 32; j++) cl[(size_t)tb * HH + colbase + j] = hv[j];
            } else           for (int j = 0; j < 32; j++) hv[j] = (1.0f / (1.0f + expf(-cs[j]))) * tanhf(hv[j]);
        }
        float s = 0.0f;
        for (int j = 0; j < 32; j++) s += hv[j];
        if (half == 0) ex0[rl] = s; else ex1[rl] = s;
        __syncthreads();
        float mu = (ex0[rl] + ex1[rl]) * (1.0f / 64.0f);
        float q = 0.0f;
        for (int j = 0; j < 32; j++) { float d = hv[j] - mu; q += d * d; }
        __syncthreads();
        if (half == 0) ex0[rl] = q; else ex1[rl] = q;
        __syncthreads();
        float rinv = rsqrtf((ex0[rl] + ex1[rl]) * (1.0f / 64.0f) + EPSV);
        for (int j = 0; j < 32; j++)
            hv[j] = (hv[j] - mu) * rinv * gm[colbase + j] + bet[colbase + j];
        __syncthreads();

        if (layer == 0) {
            for (int j = 0; j < 32; j++) xs[rl * 64 + colbase + j] = hv[j];
            __syncthreads();
            for (int i = tid; i < 192 * 16; i += 256) {
                int n = i >> 4, sdx = i & 15;
                *(float4*)&ws[n * 64 + sdx * 4] =
                    *(const float4*)(W1raw + (size_t)(64 + n) * (HH + HH) + sdx * 4);
            }
            __syncthreads();
            for (int g = 0; g < 3; g++)
                for (int j = 0; j < 32; j++) {
                    int n = g * 64 + colbase + j;
                    float acc = 0.0f;
                    for (int k = 0; k < 64; k++)
                        acc = fmaf(xs[rl * 64 + k], ws[n * 64 + k], acc);
                    z[g * 32 + j] = acc;
                }
            if (tail)
                for (int j = 0; j < 32; j++) hl[(size_t)tb * HH + colbase + j] = hv[j];
        } else {
            for (int j = 0; j < 32; j++) out[(size_t)myrow * HH + colbase + j] = hv[j];
            if (tail) for (int j = 0; j < 32; j++) hl[(size_t)tb * HH + colbase + j] = hv[j];
        }
        __syncthreads();
    }
#endif // HAS_TC
}

// ================================================================ launch
extern "C" void kernel_launch(void* const* d_in, const int* in_sizes, int n_in,
                              void* d_out, int out_size) {
    const float* inputs = (const float*)d_in[0];
    const float* W0  = (const float*)d_in[1];
    const float* b0  = (const float*)d_in[2];
    const float* th0 = (const float*)d_in[3];
    const float* g0  = (const float*)d_in[4];
    const float* be0 = (const float*)d_in[5];
    const float* W1  = (const float*)d_in[6];
    const float* b1  = (const float*)d_in[7];
    const float* th1 = (const float*)d_in[8];
    const float* g1  = (const float*)d_in[9];
    const float* be1 = (const float*)d_in[10];

    float* out = (float*)d_out;
    const size_t out_main = (size_t)NROWS * HH;
    float* h0last = out + out_main;
    float* c0last = h0last + BB * HH;
    float* h1last = c0last + BB * HH;
    float* c1last = h1last + BB * HH;

    __nv_bfloat16 *b0hi, *b0lo, *b1hi, *b1lo;
    cudaGetSymbolAddress((void**)&b0hi, g_B0hi);
    cudaGetSymbolAddress((void**)&b0lo, g_B0lo);
    cudaGetSymbolAddress((void**)&b1hi, g_B1hi);
    cudaGetSymbolAddress((void**)&b1lo, g_B1lo);

    cudaFuncSetAttribute((const void*)qlstm_fused_kernel,
                         cudaFuncAttributeMaxDynamicSharedMemorySize, SMEM_TOTAL);

    prep_w_kernel<<<(8 * NG * 64 + 255) / 256, 256>>>(W0, W1);

    qlstm_fused_kernel<<<NROWS / 128, 256, SMEM_TOTAL>>>(
        inputs, W0, W1, b0hi, b0lo, b1hi, b1lo,
        b0, th0, g0, be0, b1, th1, g1, be1,
        out, h0last, c0last, h1last, c1last);
}

// round 8
// speedup vs baseline: 1.1230x; 1.1230x over previous
#include <cuda_runtime.h>
#include <cuda_bf16.h>
#include <math.h>
#include <stdint.h>

// ---------------------------------------------------------------- constants
#define TT     512
#define BB     128
#define DDIM   512
#define HH     64
#define NROWS  (TT * BB)          // 65536 independent (t,b) rows
#define NG     192                // 3 gates (i, g, o) x 64 qubits
#define EPSV   1e-5f

// Arch-specific feature gate: tcgen05 exists only on sm_10xa targets.
#if defined(__CUDA_ARCH__) && (defined(__CUDA_ARCH_FEAT_SM103_ALL) || \
    defined(__CUDA_ARCH_FEAT_SM100_ALL) || defined(__CUDA_ARCH_SPECIFIC__))
#define HAS_TC 1
#endif

// dynamic SMEM layout (TC path):
//   A:       0 (hi 16KB) / 16384 (lo 16KB)
//   B:   32768 (hi 24KB) / 57344 (lo 24KB)
//   stage: 81920 (32KB raw fp32 x-chunk; params overlay after mainloop)
//   ctrl: 114688 (tmem ptr +0, mbar +8)
#define OFF_A      0
#define OFF_B      32768
#define OFF_STAGE  81920
#define OFF_PAR    81920
#define OFF_CTRL   114688
#define SMEM_TOTAL 114752

// idesc: kind::f16, bf16 x bf16 -> f32, M=128, N=192
#define IDESC ((1u << 4) | (1u << 7) | (1u << 10) | ((NG / 8) << 17) | ((128 / 16) << 24))

// ---------------------------------------------------------------- scratch
__device__ __nv_bfloat16  g_B0hi[8 * NG * 64];   // W0: 8 K-chunks, SW128 swizzled
__device__ __nv_bfloat16  g_B0lo[8 * NG * 64];
__device__ __nv_bfloat16  g_B1hi[NG * 64];       // W1: 1 K-chunk
__device__ __nv_bfloat16  g_B1lo[NG * 64];

// ================================================================ prolog
__global__ void prep_w_kernel(const float* __restrict__ W0,
                              const float* __restrict__ W1) {
#ifdef HAS_TC
    int idx = blockIdx.x * blockDim.x + threadIdx.x;
    if (idx < 8 * NG * 64) {
        int c   = idx / (NG * 64);
        int rem = idx % (NG * 64);
        int n   = rem / 64, kl = rem % 64;
        float w = W0[(size_t)(64 + n) * (DDIM + HH) + c * 64 + kl];
        __nv_bfloat16 hi = __float2bfloat16(w);
        __nv_bfloat16 lo = __float2bfloat16(w - __bfloat162float(hi));
        uint32_t boff = ((uint32_t)(n >> 3)) * 1024 + ((uint32_t)(n & 7)) * 128 + kl * 2;
        boff ^= ((boff >> 3) & 0x70);
        g_B0hi[(size_t)c * (NG * 64) + boff / 2] = hi;
        g_B0lo[(size_t)c * (NG * 64) + boff / 2] = lo;
    }
    if (idx < NG * 64) {
        int n = idx / 64, kl = idx % 64;
        float w = W1[(size_t)(64 + n) * (HH + HH) + kl];
        __nv_bfloat16 hi = __float2bfloat16(w);
        __nv_bfloat16 lo = __float2bfloat16(w - __bfloat162float(hi));
        uint32_t boff = ((uint32_t)(n >> 3)) * 1024 + ((uint32_t)(n & 7)) * 128 + kl * 2;
        boff ^= ((boff >> 3) & 0x70);
        g_B1hi[boff / 2] = hi;
        g_B1lo[boff / 2] = lo;
    }
#endif
}

// ================================================================ PTX helpers
#ifdef HAS_TC
static __device__ __forceinline__ uint32_t smem_u32(const void* p) {
    uint32_t a;
    asm("{ .reg .u64 t; cvta.to.shared.u64 t, %1; cvt.u32.u64 %0, t; }"
        : "=r"(a) : "l"(p));
    return a;
}
static __device__ __forceinline__ uint32_t elect1() {
    uint32_t p;
    asm volatile("{\n .reg .pred p;\n elect.sync _|p, 0xFFFFFFFF;\n selp.b32 %0,1,0,p;\n}"
                 : "=r"(p));
    return p;
}
static __device__ __forceinline__ uint64_t sdesc(uint32_t addr) {
    return (2ull << 61) | (1ull << 46) | (64ull << 32) | (1ull << 16)
         | ((uint64_t)(addr >> 4) & 0x3FFF);
}
static __device__ __forceinline__ void mma_bf16_ss(uint32_t d, uint64_t ad, uint64_t bd,
                                                   uint32_t idesc, bool accum) {
    uint32_t en = accum ? 1u : 0u;
    asm volatile(
        "{\n\t"
        ".reg .pred p;\n\t"
        "setp.ne.u32 p, %5, 0;\n\t"
        "tcgen05.mma.cta_group::1.kind::f16 [%0], %1, %2, %3, {%4, %4, %4, %4}, p;\n\t"
        "}"
        :: "r"(d), "l"(ad), "l"(bd), "r"(idesc), "r"(0u), "r"(en)
        : "memory");
}
static __device__ __forceinline__ void mbar_wait(uint32_t mbar, uint32_t parity) {
    uint32_t done;
    asm volatile(
        "{\n .reg .pred p;\n"
        " mbarrier.try_wait.parity.acquire.cta.shared::cta.b64 p, [%1], %2;\n"
        " selp.b32 %0, 1, 0, p;\n}"
        : "=r"(done) : "r"(mbar), "r"(parity) : "memory");
    if (!done) {
        asm volatile(
            "{\n .reg .pred P1;\n"
            "WL%=:\n"
            " mbarrier.try_wait.parity.acquire.cta.shared::cta.b64 P1, [%0], %1, 0x989680;\n"
            " @P1 bra.uni WD%=;\n"
            " bra.uni WL%=;\n"
            "WD%=:\n}"
            :: "r"(mbar), "r"(parity) : "memory");
    }
}
#define TC_WAIT_LD() asm volatile("tcgen05.wait::ld.sync.aligned;" ::: "memory")
#define LDTM_X32(r, addr)                                              \
    asm volatile(                                                       \
        "tcgen05.ld.sync.aligned.32x32b.x32.b32 "                       \
        "{%0, %1, %2, %3, %4, %5, %6, %7, "                             \
        " %8, %9, %10, %11, %12, %13, %14, %15, "                       \
        " %16, %17, %18, %19, %20, %21, %22, %23, "                     \
        " %24, %25, %26, %27, %28, %29, %30, %31}, [%32];"              \
        : "=r"((r)[0]),  "=r"((r)[1]),  "=r"((r)[2]),  "=r"((r)[3]),    \
          "=r"((r)[4]),  "=r"((r)[5]),  "=r"((r)[6]),  "=r"((r)[7]),    \
          "=r"((r)[8]),  "=r"((r)[9]),  "=r"((r)[10]), "=r"((r)[11]),   \
          "=r"((r)[12]), "=r"((r)[13]), "=r"((r)[14]), "=r"((r)[15]),   \
          "=r"((r)[16]), "=r"((r)[17]), "=r"((r)[18]), "=r"((r)[19]),   \
          "=r"((r)[20]), "=r"((r)[21]), "=r"((r)[22]), "=r"((r)[23]),   \
          "=r"((r)[24]), "=r"((r)[25]), "=r"((r)[26]), "=r"((r)[27]),   \
          "=r"((r)[28]), "=r"((r)[29]), "=r"((r)[30]), "=r"((r)[31])    \
        : "r"(addr))

#define CP_ASYNC16(dst, src) \
    asm volatile("cp.async.cg.shared.global [%0], [%1], 16;" :: "r"(dst), "l"(src) : "memory")
#define CP_COMMIT() asm volatile("cp.async.commit_group;" ::: "memory")
#define CP_WAIT0()  asm volatile("cp.async.wait_group 0;" ::: "memory")

static __device__ __forceinline__ float frcp(float x) {
    float y; asm("rcp.approx.f32 %0, %1;" : "=f"(y) : "f"(x)); return y;
}
// sigmoid(q), |q| <= 1: odd poly deg-11, err ~2e-7, FMA-only (0 MUFU)
static __device__ __forceinline__ float psig(float q) {
    float u = q * q;
    float p = fmaf(u, -2.1638741e-6f, 2.1358436e-5f);
    p = fmaf(u, p, -2.1081349e-4f);
    p = fmaf(u, p,  2.0833333e-3f);
    p = fmaf(u, p, -2.0833333e-2f);
    p = fmaf(u, p,  0.25f);
    return fmaf(q, p, 0.5f);
}
// tanh(x), 0 <= x <= 0.75: Pade(7,6), err < 1e-8, 1 MUFU rcp + FMAs
static __device__ __forceinline__ float ptanh(float x) {
    float u = x * x;
    float n = fmaf(u + 378.0f, u, 17325.0f);
    n = fmaf(n, u, 135135.0f);
    float d = fmaf(28.0f, u, 3150.0f);
    d = fmaf(d, u, 62370.0f);
    d = fmaf(d, u, 135135.0f);
    return x * n * frcp(d);
}

// ---------------------------------------------------------------- epilogue half
template <bool L0>
static __device__ __forceinline__ void epilogue_half(
    uint32_t tmem, const float* __restrict__ bt,
    const float* __restrict__ gm, const float* __restrict__ bet,
    volatile float* ex0, volatile float* ex1,
    char* ahi, char* alo, float* __restrict__ outp,
    float* __restrict__ hlast, float* __restrict__ clast,
    int half, int rl, int myrow)
{
    float hv[32], cs[32];
    uint32_t* ru = (uint32_t*)cs;
    const int colbase = half * 32;
    const bool tail = (myrow >= NROWS - BB);
    const int tb = myrow - (NROWS - BB);

#pragma unroll
    for (int g = 0; g < 3; g++) {
        LDTM_X32(ru, tmem + g * 64 + colbase);
        TC_WAIT_LD();
#pragma unroll
        for (int j = 0; j < 32; j++)
            cs[j] = __cosf(__uint_as_float(ru[j]) + bt[g * 64 + colbase + j]);
#pragma unroll
        for (int g8 = 0; g8 < 4; g8++)
#pragma unroll
            for (int j = 1; j < 8; j++)
                cs[g8 * 8 + j] *= cs[g8 * 8 + j - 1];
        float pref = 1.0f;
#pragma unroll
        for (int g8 = 0; g8 < 4; g8++) {
            float tot = cs[g8 * 8 + 7];
#pragma unroll
            for (int j = 0; j < 8; j++) cs[g8 * 8 + j] *= pref;
            pref *= tot;
        }
        if (half == 0) ex0[rl] = pref;
        __syncthreads();
        if (half == 1) {
            float p = ex0[rl];
#pragma unroll
            for (int j = 0; j < 32; j++) cs[j] *= p;
        }
        __syncthreads();

        if (g == 0) {
#pragma unroll
            for (int j = 0; j < 32; j++) hv[j] = psig(cs[j]);
        } else if (g == 1) {
#pragma unroll
            for (int j = 0; j < 32; j++) hv[j] *= ptanh(psig(cs[j]));   // c
            if (tail) {
                float4* cd = (float4*)(clast + (size_t)tb * HH) + half * 8;
#pragma unroll
                for (int j = 0; j < 8; j++)
                    cd[j] = make_float4(hv[4*j], hv[4*j+1], hv[4*j+2], hv[4*j+3]);
            }
        } else {
#pragma unroll
            for (int j = 0; j < 32; j++) hv[j] = psig(cs[j]) * ptanh(hv[j]);  // h
        }
    }

    // layernorm across the pair
    float s = 0.0f;
#pragma unroll
    for (int j = 0; j < 32; j++) s += hv[j];
    if (half == 0) ex0[rl] = s; else ex1[rl] = s;
    __syncthreads();
    float mu = (ex0[rl] + ex1[rl]) * (1.0f / 64.0f);
    float q = 0.0f;
#pragma unroll
    for (int j = 0; j < 32; j++) { float d = hv[j] - mu; q += d * d; }
    __syncthreads();
    if (half == 0) ex0[rl] = q; else ex1[rl] = q;
    __syncthreads();
    float rinv = rsqrtf((ex0[rl] + ex1[rl]) * (1.0f / 64.0f) + EPSV);
#pragma unroll
    for (int j = 0; j < 32; j++)
        hv[j] = (hv[j] - mu) * rinv * gm[colbase + j] + bet[colbase + j];

    if (L0) {
#pragma unroll
        for (int j8 = 0; j8 < 4; j8++) {
            __nv_bfloat162 ph[4], pl[4];
#pragma unroll
            for (int p2 = 0; p2 < 4; p2++) {
                float v0 = hv[j8 * 8 + p2 * 2], v1 = hv[j8 * 8 + p2 * 2 + 1];
                __nv_bfloat16 h0 = __float2bfloat16(v0);
                __nv_bfloat16 h1 = __float2bfloat16(v1);
                ph[p2] = __nv_bfloat162(h0, h1);
                pl[p2] = __nv_bfloat162(__float2bfloat16(v0 - __bfloat162float(h0)),
                                        __float2bfloat16(v1 - __bfloat162float(h1)));
            }
            uint32_t off = (uint32_t)rl * 128 + (uint32_t)colbase * 2 + j8 * 16;
            off ^= ((off >> 3) & 0x70);
            *(uint4*)(ahi + off) = *(uint4*)ph;
            *(uint4*)(alo + off) = *(uint4*)pl;
        }
        if (tail) {
            float4* hd = (float4*)(hlast + (size_t)tb * HH) + half * 8;
#pragma unroll
            for (int j = 0; j < 8; j++)
                hd[j] = make_float4(hv[4*j], hv[4*j+1], hv[4*j+2], hv[4*j+3]);
        }
    } else {
        float4* od = (float4*)(outp + (size_t)myrow * HH) + half * 8;
#pragma unroll
        for (int j = 0; j < 8; j++)
            od[j] = make_float4(hv[4*j], hv[4*j+1], hv[4*j+2], hv[4*j+3]);
        if (tail) {
            float4* hd = (float4*)(hlast + (size_t)tb * HH) + half * 8;
#pragma unroll
            for (int j = 0; j < 8; j++)
                hd[j] = make_float4(hv[4*j], hv[4*j+1], hv[4*j+2], hv[4*j+3]);
        }
    }
    __syncthreads();
}
#endif // HAS_TC

// ================================================================ fused kernel
__global__ void __launch_bounds__(256, 2)
qlstm_fused_kernel(const float* __restrict__ x,
                   const float* __restrict__ W0raw,
                   const float* __restrict__ W1raw,
                   const __nv_bfloat16* __restrict__ B0hi_g,
                   const __nv_bfloat16* __restrict__ B0lo_g,
                   const __nv_bfloat16* __restrict__ B1hi_g,
                   const __nv_bfloat16* __restrict__ B1lo_g,
                   const float* __restrict__ b0, const float* __restrict__ th0,
                   const float* __restrict__ g0, const float* __restrict__ be0,
                   const float* __restrict__ b1, const float* __restrict__ th1,
                   const float* __restrict__ g1, const float* __restrict__ be1,
                   float* __restrict__ out,
                   float* __restrict__ h0last, float* __restrict__ c0last,
                   float* __restrict__ h1last, float* __restrict__ c1last)
{
    extern __shared__ __align__(1024) char smem[];
    const int tid = threadIdx.x, wid = tid >> 5, lane = tid & 31;
    const int half = wid >> 2;
    const int rl   = (wid & 3) * 32 + lane;     // local row 0..127
    const int row0 = blockIdx.x * 128;
    const int myrow = row0 + rl;

    // params: overlay on staging (TC path: valid after mainloop;
    // fallback path: written at entry, region unused otherwise)
    float* fp   = (float*)(smem + OFF_PAR);
    float* bt0  = fp;          // 192
    float* bt1  = fp + 192;    // 192
    float* gm0  = fp + 384;    // 64
    float* bet0 = fp + 448;
    float* gm1  = fp + 512;
    float* bet1 = fp + 576;
    float* ex0  = fp + 640;    // 128
    float* ex1  = fp + 768;    // 128

#ifdef HAS_TC
    constexpr int NC = 8;
    const uint32_t sb = smem_u32(smem);
    const uint32_t mb = sb + OFF_CTRL + 8;
    if (wid == 0) {
        asm volatile("tcgen05.alloc.cta_group::1.sync.aligned.shared::cta.b32 [%0], %1;"
                     :: "r"(sb + OFF_CTRL), "r"(256u) : "memory");
        asm volatile("tcgen05.relinquish_alloc_permit.cta_group::1.sync.aligned;");
    }
    if (tid == 0) {
        asm volatile("mbarrier.init.shared.b64 [%0], %1;" :: "r"(mb), "r"(1u) : "memory");
    }

    // prefetch x(0) into staging (no barrier needed: staging untouched yet)
    {
        const uint32_t stg = sb + OFF_STAGE;
#pragma unroll
        for (int j = 0; j < 8; j++) {
            int idx = tid + j * 256;              // 2048 x 16B
            int r = idx >> 4, s = idx & 15;
            CP_ASYNC16(stg + (uint32_t)idx * 16,
                       x + (size_t)(row0 + r) * DDIM + s * 4);
        }
        CP_COMMIT();
    }
    __syncthreads();
    uint32_t tmem;
    asm volatile("ld.shared.b32 %0, [%1];" : "=r"(tmem) : "r"(sb + OFF_CTRL));

    const uint64_t aHd = sdesc(sb + OFF_A);
    const uint64_t aLd = sdesc(sb + OFF_A + 16384);
    const uint64_t bHd = sdesc(sb + OFF_B);
    const uint64_t bLd = sdesc(sb + OFF_B + 24576);
    char* ah = smem + OFF_A;
    char* al = smem + OFF_A + 16384;

    // ---------------- layer-0 K-chunk loop (cp.async staged) ----------------
    for (int c = 0; c < NC; c++) {
        if (c > 0) mbar_wait(mb, (c - 1) & 1);    // A,B buffers free
        CP_WAIT0();                               // x(c) staged (own copies)
        __syncthreads();                          // staged data visible to all

        {   // convert staging fp32 -> bf16 hi/lo, SW128-swizzled STS
            const char* stg = smem + OFF_STAGE;
#pragma unroll
            for (int j = 0; j < 8; j++) {
                int idx = tid + j * 256;
                int r = idx >> 4, s = idx & 15;
                float4 v = *(const float4*)(stg + (uint32_t)idx * 16);
                __nv_bfloat16 hx = __float2bfloat16(v.x);
                __nv_bfloat16 hy = __float2bfloat16(v.y);
                __nv_bfloat16 hz = __float2bfloat16(v.z);
                __nv_bfloat16 hw = __float2bfloat16(v.w);
                __nv_bfloat16 lx = __float2bfloat16(v.x - __bfloat162float(hx));
                __nv_bfloat16 ly = __float2bfloat16(v.y - __bfloat162float(hy));
                __nv_bfloat16 lz = __float2bfloat16(v.z - __bfloat162float(hz));
                __nv_bfloat16 lw = __float2bfloat16(v.w - __bfloat162float(hw));
                uint32_t off = (uint32_t)r * 128 + (uint32_t)s * 8;
                off ^= ((off >> 3) & 0x70);
                *(__nv_bfloat162*)(ah + off)     = __nv_bfloat162(hx, hy);
                *(__nv_bfloat162*)(ah + off + 4) = __nv_bfloat162(hz, hw);
                *(__nv_bfloat162*)(al + off)     = __nv_bfloat162(lx, ly);
                *(__nv_bfloat162*)(al + off + 4) = __nv_bfloat162(lz, lw);
            }
        }
        {   // B(c): pre-swizzled raw copy (L2-resident)
            const float4* bh = (const float4*)(B0hi_g + (size_t)c * (NG * 64));
            const float4* bl = (const float4*)(B0lo_g + (size_t)c * (NG * 64));
            float4* sh = (float4*)(smem + OFF_B);
            float4* sl = (float4*)(smem + OFF_B + 24576);
#pragma unroll
            for (int j = 0; j < 6; j++) {
                int idx = tid + j * 256;
                sh[idx] = bh[idx];
                sl[idx] = bl[idx];
            }
        }
        __syncthreads();   // drains STS (=> staging LDS complete) before reuse

        // prefetch x(c+1) into staging — overlaps MMA(c) + commit wait
        if (c + 1 < NC) {
            const uint32_t stg = sb + OFF_STAGE;
#pragma unroll
            for (int j = 0; j < 8; j++) {
                int idx = tid + j * 256;
                int r = idx >> 4, s = idx & 15;
                CP_ASYNC16(stg + (uint32_t)idx * 16,
                           x + (size_t)(row0 + r) * DDIM + (c + 1) * 64 + s * 4);
            }
            CP_COMMIT();
        }

        if (wid == 0 && elect1()) {
            asm volatile("fence.proxy.async.shared::cta;" ::: "memory");
#pragma unroll
            for (int ks = 0; ks < 4; ks++)
                mma_bf16_ss(tmem, aHd + ks * 2, bHd + ks * 2, IDESC, !(c == 0 && ks == 0));
#pragma unroll
            for (int ks = 0; ks < 4; ks++)
                mma_bf16_ss(tmem, aHd + ks * 2, bLd + ks * 2, IDESC, true);
#pragma unroll
            for (int ks = 0; ks < 4; ks++)
                mma_bf16_ss(tmem, aLd + ks * 2, bHd + ks * 2, IDESC, true);
            asm volatile(
                "tcgen05.commit.cta_group::1.mbarrier::arrive::one.shared::cluster.b64 [%0];"
                :: "r"(mb) : "memory");
        }
    }

    mbar_wait(mb, (NC - 1) & 1);
    asm volatile("tcgen05.fence::after_thread_sync;" ::: "memory");

    // B1 into B buffer + params into the staging overlay
    {
        const float4* bh = (const float4*)B1hi_g;
        const float4* bl = (const float4*)B1lo_g;
        float4* sh = (float4*)(smem + OFF_B);
        float4* sl = (float4*)(smem + OFF_B + 24576);
#pragma unroll
        for (int j = 0; j < 6; j++) {
            int idx = tid + j * 256;
            sh[idx] = bh[idx];
            sl[idx] = bl[idx];
        }
    }
    if (tid < NG) {
        bt0[tid] = b0[64 + tid] + th0[64 + tid];
        bt1[tid] = b1[64 + tid] + th1[64 + tid];
    }
    if (tid >= 192 && tid < 256) {
        int i = tid - 192;
        gm0[i] = g0[i]; bet0[i] = be0[i];
        gm1[i] = g1[i]; bet1[i] = be1[i];
    }
    __syncthreads();

    // ---------------- epilogue 0 (writes layer-1 A tile) ----------------
    epilogue_half<true>(tmem, bt0, gm0, bet0, ex0, ex1, ah, al,
                        nullptr, h0last, c0last, half, rl, myrow);

    asm volatile("tcgen05.fence::before_thread_sync;" ::: "memory");
    __syncthreads();

    // ---------------- layer-1 GEMM (K=64, reuse TMEM cols 0-191) ----------
    if (wid == 0 && elect1()) {
        asm volatile("tcgen05.fence::after_thread_sync;" ::: "memory");
        asm volatile("fence.proxy.async.shared::cta;" ::: "memory");
#pragma unroll
        for (int ks = 0; ks < 4; ks++)
            mma_bf16_ss(tmem, aHd + ks * 2, bHd + ks * 2, IDESC, ks != 0);
#pragma unroll
        for (int ks = 0; ks < 4; ks++)
            mma_bf16_ss(tmem, aHd + ks * 2, bLd + ks * 2, IDESC, true);
#pragma unroll
        for (int ks = 0; ks < 4; ks++)
            mma_bf16_ss(tmem, aLd + ks * 2, bHd + ks * 2, IDESC, true);
        asm volatile(
            "tcgen05.commit.cta_group::1.mbarrier::arrive::one.shared::cluster.b64 [%0];"
            :: "r"(mb) : "memory");
    }
    mbar_wait(mb, NC & 1);      // 9th completion -> parity 0
    asm volatile("tcgen05.fence::after_thread_sync;" ::: "memory");

    // ---------------- epilogue 1 (writes final output) ----------------
    epilogue_half<false>(tmem, bt1, gm1, bet1, ex0, ex1, nullptr, nullptr,
                         out, h1last, c1last, half, rl, myrow);

    asm volatile("tcgen05.fence::before_thread_sync;" ::: "memory");
    __syncthreads();
    if (wid == 0) {
        asm volatile("tcgen05.dealloc.cta_group::1.sync.aligned.b32 %0, %1;"
                     :: "r"(tmem), "r"(256u));
    }

#else  // ---------------- scalar fallback (correctness-only) ----------------
    float* xs = (float*)smem;                    // [128][64] fp32 (0..32KB)
    float* ws = (float*)(smem + 32768);          // [192][64] fp32 (32..80KB)
    const int colbase = half * 32;
    const bool tail = (myrow >= NROWS - BB);
    const int tb = myrow - (NROWS - BB);

    if (tid < NG) {
        bt0[tid] = b0[64 + tid] + th0[64 + tid];
        bt1[tid] = b1[64 + tid] + th1[64 + tid];
    }
    if (tid >= 192 && tid < 256) {
        int i = tid - 192;
        gm0[i] = g0[i]; bet0[i] = be0[i];
        gm1[i] = g1[i]; bet1[i] = be1[i];
    }
    __syncthreads();

    float z[96];
#pragma unroll
    for (int i = 0; i < 96; i++) z[i] = 0.0f;

    for (int kt = 0; kt < 8; kt++) {
        __syncthreads();
        for (int i = tid; i < 128 * 16; i += 256) {
            int r = i >> 4, s = i & 15;
            *(float4*)&xs[r * 64 + s * 4] =
                *(const float4*)(x + (size_t)(row0 + r) * DDIM + kt * 64 + s * 4);
        }
        for (int i = tid; i < 192 * 16; i += 256) {
            int n = i >> 4, s = i & 15;
            *(float4*)&ws[n * 64 + s * 4] =
                *(const float4*)(W0raw + (size_t)(64 + n) * (DDIM + HH) + kt * 64 + s * 4);
        }
        __syncthreads();
        for (int g = 0; g < 3; g++)
            for (int j = 0; j < 32; j++) {
                int n = g * 64 + colbase + j;
                float acc = z[g * 32 + j];
                for (int k = 0; k < 64; k++)
                    acc = fmaf(xs[rl * 64 + k], ws[n * 64 + k], acc);
                z[g * 32 + j] = acc;
            }
    }

    for (int layer = 0; layer < 2; layer++) {
        const float* bt  = layer ? bt1  : bt0;
        const float* gm  = layer ? gm1  : gm0;
        const float* bet = layer ? bet1 : bet0;
        float* hl = layer ? h1last : h0last;
        float* cl = layer ? c1last : c0last;
        float hv[32];
        for (int g = 0; g < 3; g++) {
            float cs[32];
            for (int j = 0; j < 32; j++)
                cs[j] = cosf(z[g * 32 + j] + bt[g * 64 + colbase + j]);
            for (int j = 1; j < 32; j++) cs[j] *= cs[j - 1];
            if (half == 0) ex0[rl] = cs[31];
            __syncthreads();
            if (half == 1) { float p = ex0[rl]; for (int j = 0; j < 32; j++) cs[j] *= p; }
            __syncthreads();
            if (g == 0)      for (int j = 0; j < 32; j++) hv[j] = 1.0f / (1.0f + expf(-cs[j]));
            else if (g == 1) {
                for (int j = 0; j < 32; j++) hv[j] *= tanhf(1.0f / (1.0f + expf(-cs[j])));
                if (tail) for (int j = 0; j < 32; j++) cl[(size_t)tb * HH + colbase + j] = hv[j];
            } else           for (int j = 0; j < 32; j++) hv[j] = (1.0f / (1.0f + expf(-cs[j]))) * tanhf(hv[j]);
        }
        float s = 0.0f;
        for (int j = 0; j < 32; j++) s += hv[j];
        if (half == 0) ex0[rl] = s; else ex1[rl] = s;
        __syncthreads();
        float mu = (ex0[rl] + ex1[rl]) * (1.0f / 64.0f);
        float q = 0.0f;
        for (int j = 0; j < 32; j++) { float d = hv[j] - mu; q += d * d; }
        __syncthreads();
        if (half == 0) ex0[rl] = q; else ex1[rl] = q;
        __syncthreads();
        float rinv = rsqrtf((ex0[rl] + ex1[rl]) * (1.0f / 64.0f) + EPSV);
        for (int j = 0; j < 32; j++)
            hv[j] = (hv[j] - mu) * rinv * gm[colbase + j] + bet[colbase + j];
        __syncthreads();

        if (layer == 0) {
            for (int j = 0; j < 32; j++) xs[rl * 64 + colbase + j] = hv[j];
            __syncthreads();
            for (int i = tid; i < 192 * 16; i += 256) {
                int n = i >> 4, sdx = i & 15;
                *(float4*)&ws[n * 64 + sdx * 4] =
                    *(const float4*)(W1raw + (size_t)(64 + n) * (HH + HH) + sdx * 4);
            }
            __syncthreads();
            for (int g = 0; g < 3; g++)
                for (int j = 0; j < 32; j++) {
                    int n = g * 64 + colbase + j;
                    float acc = 0.0f;
                    for (int k = 0; k < 64; k++)
                        acc = fmaf(xs[rl * 64 + k], ws[n * 64 + k], acc);
                    z[g * 32 + j] = acc;
                }
            if (tail)
                for (int j = 0; j < 32; j++) hl[(size_t)tb * HH + colbase + j] = hv[j];
        } else {
            for (int j = 0; j < 32; j++) out[(size_t)myrow * HH + colbase + j] = hv[j];
            if (tail) for (int j = 0; j < 32; j++) hl[(size_t)tb * HH + colbase + j] = hv[j];
        }
        __syncthreads();
    }
#endif // HAS_TC
}

// ================================================================ launch
extern "C" void kernel_launch(void* const* d_in, const int* in_sizes, int n_in,
                              void* d_out, int out_size) {
    const float* inputs = (const float*)d_in[0];
    const float* W0  = (const float*)d_in[1];
    const float* b0  = (const float*)d_in[2];
    const float* th0 = (const float*)d_in[3];
    const float* g0  = (const float*)d_in[4];
    const float* be0 = (const float*)d_in[5];
    const float* W1  = (const float*)d_in[6];
    const float* b1  = (const float*)d_in[7];
    const float* th1 = (const float*)d_in[8];
    const float* g1  = (const float*)d_in[9];
    const float* be1 = (const float*)d_in[10];

    float* out = (float*)d_out;
    const size_t out_main = (size_t)NROWS * HH;
    float* h0last = out + out_main;
    float* c0last = h0last + BB * HH;
    float* h1last = c0last + BB * HH;
    float* c1last = h1last + BB * HH;

    __nv_bfloat16 *b0hi, *b0lo, *b1hi, *b1lo;
    cudaGetSymbolAddress((void**)&b0hi, g_B0hi);
    cudaGetSymbolAddress((void**)&b0lo, g_B0lo);
    cudaGetSymbolAddress((void**)&b1hi, g_B1hi);
    cudaGetSymbolAddress((void**)&b1lo, g_B1lo);

    cudaFuncSetAttribute((const void*)qlstm_fused_kernel,
                         cudaFuncAttributeMaxDynamicSharedMemorySize, SMEM_TOTAL);

    prep_w_kernel<<<(8 * NG * 64 + 255) / 256, 256>>>(W0, W1);

    qlstm_fused_kernel<<<NROWS / 128, 256, SMEM_TOTAL>>>(
        inputs, W0, W1, b0hi, b0lo, b1hi, b1lo,
        b0, th0, g0, be0, b1, th1, g1, be1,
        out, h0last, c0last, h1last, c1last);
}

// round 10
// speedup vs baseline: 1.1902x; 1.0599x over previous
#include <cuda_runtime.h>
#include <cuda_bf16.h>
#include <math.h>
#include <stdint.h>

// ---------------------------------------------------------------- constants
#define TT     512
#define BB     128
#define DDIM   512
#define HH     64
#define NROWS  (TT * BB)          // 65536 independent (t,b) rows
#define NG     192                // 3 gates (i, g, o) x 64 qubits
#define EPSV   1e-5f
#define NTHR   512

// Arch-specific feature gate: tcgen05 exists only on sm_10xa targets.
#if defined(__CUDA_ARCH__) && (defined(__CUDA_ARCH_FEAT_SM103_ALL) || \
    defined(__CUDA_ARCH_FEAT_SM100_ALL) || defined(__CUDA_ARCH_SPECIFIC__))
#define HAS_TC 1
#endif

// dynamic SMEM layout:
//   A:       0 (hi 16KB) / 16384 (lo 16KB)
//   B:   32768 (hi 24KB) / 57344 (lo 24KB)
//   params/exchange: 81920 (4608B)
//   ctrl: 86528 (tmem ptr +0, mbar +8)
#define OFF_A      0
#define OFF_B      32768
#define OFF_PAR    81920
#define OFF_CTRL   86528
#define SMEM_TOTAL 86592

// idesc: kind::f16, bf16 x bf16 -> f32, M=128, N=192
#define IDESC ((1u << 4) | (1u << 7) | (1u << 10) | ((NG / 8) << 17) | ((128 / 16) << 24))

// ---------------------------------------------------------------- scratch
__device__ __nv_bfloat16  g_B0hi[8 * NG * 64];   // W0: 8 K-chunks, SW128 swizzled
__device__ __nv_bfloat16  g_B0lo[8 * NG * 64];
__device__ __nv_bfloat16  g_B1hi[NG * 64];       // W1: 1 K-chunk
__device__ __nv_bfloat16  g_B1lo[NG * 64];

// ================================================================ prolog
__global__ void prep_w_kernel(const float* __restrict__ W0,
                              const float* __restrict__ W1) {
#ifdef HAS_TC
    int idx = blockIdx.x * blockDim.x + threadIdx.x;
    if (idx < 8 * NG * 64) {
        int c   = idx / (NG * 64);
        int rem = idx % (NG * 64);
        int n   = rem / 64, kl = rem % 64;
        float w = W0[(size_t)(64 + n) * (DDIM + HH) + c * 64 + kl];
        __nv_bfloat16 hi = __float2bfloat16(w);
        __nv_bfloat16 lo = __float2bfloat16(w - __bfloat162float(hi));
        uint32_t boff = ((uint32_t)(n >> 3)) * 1024 + ((uint32_t)(n & 7)) * 128 + kl * 2;
        boff ^= ((boff >> 3) & 0x70);
        g_B0hi[(size_t)c * (NG * 64) + boff / 2] = hi;
        g_B0lo[(size_t)c * (NG * 64) + boff / 2] = lo;
    }
    if (idx < NG * 64) {
        int n = idx / 64, kl = idx % 64;
        float w = W1[(size_t)(64 + n) * (HH + HH) + kl];
        __nv_bfloat16 hi = __float2bfloat16(w);
        __nv_bfloat16 lo = __float2bfloat16(w - __bfloat162float(hi));
        uint32_t boff = ((uint32_t)(n >> 3)) * 1024 + ((uint32_t)(n & 7)) * 128 + kl * 2;
        boff ^= ((boff >> 3) & 0x70);
        g_B1hi[boff / 2] = hi;
        g_B1lo[boff / 2] = lo;
    }
#endif
}

// ================================================================ PTX helpers
#ifdef HAS_TC
static __device__ __forceinline__ uint32_t smem_u32(const void* p) {
    uint32_t a;
    asm("{ .reg .u64 t; cvta.to.shared.u64 t, %1; cvt.u32.u64 %0, t; }"
        : "=r"(a) : "l"(p));
    return a;
}
static __device__ __forceinline__ uint32_t elect1() {
    uint32_t p;
    asm volatile("{\n .reg .pred p;\n elect.sync _|p, 0xFFFFFFFF;\n selp.b32 %0,1,0,p;\n}"
                 : "=r"(p));
    return p;
}
static __device__ __forceinline__ uint64_t sdesc(uint32_t addr) {
    return (2ull << 61) | (1ull << 46) | (64ull << 32) | (1ull << 16)
         | ((uint64_t)(addr >> 4) & 0x3FFF);
}
static __device__ __forceinline__ void mma_bf16_ss(uint32_t d, uint64_t ad, uint64_t bd,
                                                   uint32_t idesc, bool accum) {
    uint32_t en = accum ? 1u : 0u;
    asm volatile(
        "{\n\t"
        ".reg .pred p;\n\t"
        "setp.ne.u32 p, %5, 0;\n\t"
        "tcgen05.mma.cta_group::1.kind::f16 [%0], %1, %2, %3, {%4, %4, %4, %4}, p;\n\t"
        "}"
        :: "r"(d), "l"(ad), "l"(bd), "r"(idesc), "r"(0u), "r"(en)
        : "memory");
}
static __device__ __forceinline__ void mbar_wait(uint32_t mbar, uint32_t parity) {
    uint32_t done;
    asm volatile(
        "{\n .reg .pred p;\n"
        " mbarrier.try_wait.parity.acquire.cta.shared::cta.b64 p, [%1], %2;\n"
        " selp.b32 %0, 1, 0, p;\n}"
        : "=r"(done) : "r"(mbar), "r"(parity) : "memory");
    if (!done) {
        asm volatile(
            "{\n .reg .pred P1;\n"
            "WL%=:\n"
            " mbarrier.try_wait.parity.acquire.cta.shared::cta.b64 P1, [%0], %1, 0x989680;\n"
            " @P1 bra.uni WD%=;\n"
            " bra.uni WL%=;\n"
            "WD%=:\n}"
            :: "r"(mbar), "r"(parity) : "memory");
    }
}
#define TC_WAIT_LD() asm volatile("tcgen05.wait::ld.sync.aligned;" ::: "memory")
#define LDTM_X16(r, addr)                                              \
    asm volatile(                                                       \
        "tcgen05.ld.sync.aligned.32x32b.x16.b32 "                       \
        "{%0, %1, %2, %3, %4, %5, %6, %7, "                             \
        " %8, %9, %10, %11, %12, %13, %14, %15}, [%16];"                \
        : "=r"((r)[0]),  "=r"((r)[1]),  "=r"((r)[2]),  "=r"((r)[3]),    \
          "=r"((r)[4]),  "=r"((r)[5]),  "=r"((r)[6]),  "=r"((r)[7]),    \
          "=r"((r)[8]),  "=r"((r)[9]),  "=r"((r)[10]), "=r"((r)[11]),   \
          "=r"((r)[12]), "=r"((r)[13]), "=r"((r)[14]), "=r"((r)[15])    \
        : "r"(addr))

static __device__ __forceinline__ float frcp(float x) {
    float y; asm("rcp.approx.f32 %0, %1;" : "=f"(y) : "f"(x)); return y;
}
// sigmoid(q), |q| <= 1: odd poly deg-11, err ~2e-7, FMA-only (0 MUFU)
static __device__ __forceinline__ float psig(float q) {
    float u = q * q;
    float p = fmaf(u, -2.1638741e-6f, 2.1358436e-5f);
    p = fmaf(u, p, -2.1081349e-4f);
    p = fmaf(u, p,  2.0833333e-3f);
    p = fmaf(u, p, -2.0833333e-2f);
    p = fmaf(u, p,  0.25f);
    return fmaf(q, p, 0.5f);
}
// tanh(x), 0 <= x <= 0.75: Pade(7,6), err < 1e-8, 1 MUFU rcp + FMAs
static __device__ __forceinline__ float ptanh(float x) {
    float u = x * x;
    float n = fmaf(u + 378.0f, u, 17325.0f);
    n = fmaf(n, u, 135135.0f);
    float d = fmaf(28.0f, u, 3150.0f);
    d = fmaf(d, u, 62370.0f);
    d = fmaf(d, u, 135135.0f);
    return x * n * frcp(d);
}

// ---------------------------------------------------------------- epilogue quarter
// Row rl is owned by 4 threads (quarters q=0..3), each handling 16 gate cols.
// Cross-quarter cumprod prefixes and LN partials exchange via exq[4][128].
template <bool L0>
static __device__ __forceinline__ void epilogue_quarter(
    uint32_t tmem, const float* __restrict__ bt,
    const float* __restrict__ gm, const float* __restrict__ bet,
    volatile float* exq,
    char* ahi, char* alo, float* __restrict__ outp,
    float* __restrict__ hlast, float* __restrict__ clast,
    int q, int rl, int myrow)
{
    float hv[16], cs[16];
    uint32_t* ru = (uint32_t*)cs;
    const int colbase = q * 16;
    const bool tail = (myrow >= NROWS - BB);
    const int tb = myrow - (NROWS - BB);

#pragma unroll
    for (int g = 0; g < 3; g++) {
        LDTM_X16(ru, tmem + g * 64 + colbase);
        TC_WAIT_LD();
#pragma unroll
        for (int j = 0; j < 16; j++)
            cs[j] = __cosf(__uint_as_float(ru[j]) + bt[g * 64 + colbase + j]);
        // local inclusive scan of 16: two chains of 8, then splice
#pragma unroll
        for (int g8 = 0; g8 < 2; g8++)
#pragma unroll
            for (int j = 1; j < 8; j++)
                cs[g8 * 8 + j] *= cs[g8 * 8 + j - 1];
        {
            float t0 = cs[7];
#pragma unroll
            for (int j = 0; j < 8; j++) cs[8 + j] *= t0;
        }
        exq[q * 128 + rl] = cs[15];
        __syncthreads();
        if (q > 0) {
            float p = exq[rl];
            if (q >= 2) p *= exq[128 + rl];
            if (q >= 3) p *= exq[256 + rl];
#pragma unroll
            for (int j = 0; j < 16; j++) cs[j] *= p;
        }
        __syncthreads();

        if (g == 0) {
#pragma unroll
            for (int j = 0; j < 16; j++) hv[j] = psig(cs[j]);
        } else if (g == 1) {
#pragma unroll
            for (int j = 0; j < 16; j++) hv[j] *= ptanh(psig(cs[j]));   // c
            if (tail) {
                float4* cd = (float4*)(clast + (size_t)tb * HH) + q * 4;
#pragma unroll
                for (int j = 0; j < 4; j++)
                    cd[j] = make_float4(hv[4*j], hv[4*j+1], hv[4*j+2], hv[4*j+3]);
            }
        } else {
#pragma unroll
            for (int j = 0; j < 16; j++) hv[j] = psig(cs[j]) * ptanh(hv[j]);  // h
        }
    }

    // layernorm across 4 quarters
    float s = 0.0f;
#pragma unroll
    for (int j = 0; j < 16; j++) s += hv[j];
    exq[q * 128 + rl] = s;
    __syncthreads();
    float mu = (exq[rl] + exq[128 + rl] + exq[256 + rl] + exq[384 + rl]) * (1.0f / 64.0f);
    float qq = 0.0f;
#pragma unroll
    for (int j = 0; j < 16; j++) { float d = hv[j] - mu; qq += d * d; }
    __syncthreads();
    exq[q * 128 + rl] = qq;
    __syncthreads();
    float rinv = rsqrtf((exq[rl] + exq[128 + rl] + exq[256 + rl] + exq[384 + rl])
                        * (1.0f / 64.0f) + EPSV);
#pragma unroll
    for (int j = 0; j < 16; j++)
        hv[j] = (hv[j] - mu) * rinv * gm[colbase + j] + bet[colbase + j];

    if (L0) {
        // h_ln -> bf16 hi/lo into SMEM A tile (SW128, layer-1 operand)
#pragma unroll
        for (int j8 = 0; j8 < 2; j8++) {
            __nv_bfloat162 ph[4], pl[4];
#pragma unroll
            for (int p2 = 0; p2 < 4; p2++) {
                float v0 = hv[j8 * 8 + p2 * 2], v1 = hv[j8 * 8 + p2 * 2 + 1];
                __nv_bfloat16 h0 = __float2bfloat16(v0);
                __nv_bfloat16 h1 = __float2bfloat16(v1);
                ph[p2] = __nv_bfloat162(h0, h1);
                pl[p2] = __nv_bfloat162(__float2bfloat16(v0 - __bfloat162float(h0)),
                                        __float2bfloat16(v1 - __bfloat162float(h1)));
            }
            uint32_t off = (uint32_t)rl * 128 + (uint32_t)q * 32 + j8 * 16;
            off ^= ((off >> 3) & 0x70);
            *(uint4*)(ahi + off) = *(uint4*)ph;
            *(uint4*)(alo + off) = *(uint4*)pl;
        }
        if (tail) {
            float4* hd = (float4*)(hlast + (size_t)tb * HH) + q * 4;
#pragma unroll
            for (int j = 0; j < 4; j++)
                hd[j] = make_float4(hv[4*j], hv[4*j+1], hv[4*j+2], hv[4*j+3]);
        }
    } else {
        float4* od = (float4*)(outp + (size_t)myrow * HH) + q * 4;
#pragma unroll
        for (int j = 0; j < 4; j++)
            od[j] = make_float4(hv[4*j], hv[4*j+1], hv[4*j+2], hv[4*j+3]);
        if (tail) {
            float4* hd = (float4*)(hlast + (size_t)tb * HH) + q * 4;
#pragma unroll
            for (int j = 0; j < 4; j++)
                hd[j] = make_float4(hv[4*j], hv[4*j+1], hv[4*j+2], hv[4*j+3]);
        }
    }
    __syncthreads();
}
#endif // HAS_TC

// ================================================================ fused kernel
__global__ void __launch_bounds__(NTHR, 2)
qlstm_fused_kernel(const float* __restrict__ x,
                   const float* __restrict__ W0raw,
                   const float* __restrict__ W1raw,
                   const __nv_bfloat16* __restrict__ B0hi_g,
                   const __nv_bfloat16* __restrict__ B0lo_g,
                   const __nv_bfloat16* __restrict__ B1hi_g,
                   const __nv_bfloat16* __restrict__ B1lo_g,
                   const float* __restrict__ b0, const float* __restrict__ th0,
                   const float* __restrict__ g0, const float* __restrict__ be0,
                   const float* __restrict__ b1, const float* __restrict__ th1,
                   const float* __restrict__ g1, const float* __restrict__ be1,
                   float* __restrict__ out,
                   float* __restrict__ h0last, float* __restrict__ c0last,
                   float* __restrict__ h1last, float* __restrict__ c1last)
{
    extern __shared__ __align__(1024) char smem[];
    const int tid = threadIdx.x, wid = tid >> 5, lane = tid & 31;
    const int q  = wid >> 2;                    // quarter 0..3 (16 gate cols)
    const int rl = (wid & 3) * 32 + lane;       // local row 0..127
    const int row0 = blockIdx.x * 128;
    const int myrow = row0 + rl;

    float* fp   = (float*)(smem + OFF_PAR);
    float* bt0  = fp;          // 192
    float* bt1  = fp + 192;    // 192
    float* gm0  = fp + 384;    // 64
    float* bet0 = fp + 448;
    float* gm1  = fp + 512;
    float* bet1 = fp + 576;
    float* exq  = fp + 640;    // 4 x 128

    if (tid < NG) {
        bt0[tid] = b0[64 + tid] + th0[64 + tid];
        bt1[tid] = b1[64 + tid] + th1[64 + tid];
    }
    if (tid >= 192 && tid < 256) {
        int i = tid - 192;
        gm0[i] = g0[i]; bet0[i] = be0[i];
        gm1[i] = g1[i]; bet1[i] = be1[i];
    }

#ifdef HAS_TC
    constexpr int NC = 8;
    const uint32_t sb = smem_u32(smem);
    const uint32_t mb = sb + OFF_CTRL + 8;
    if (wid == 0) {
        asm volatile("tcgen05.alloc.cta_group::1.sync.aligned.shared::cta.b32 [%0], %1;"
                     :: "r"(sb + OFF_CTRL), "r"(256u) : "memory");
        asm volatile("tcgen05.relinquish_alloc_permit.cta_group::1.sync.aligned;");
    }
    if (tid == 0) {
        asm volatile("mbarrier.init.shared.b64 [%0], %1;" :: "r"(mb), "r"(1u) : "memory");
    }
    __syncthreads();
    uint32_t tmem;
    asm volatile("ld.shared.b32 %0, [%1];" : "=r"(tmem) : "r"(sb + OFF_CTRL));

    const uint64_t aHd = sdesc(sb + OFF_A);
    const uint64_t aLd = sdesc(sb + OFF_A + 16384);
    const uint64_t bHd = sdesc(sb + OFF_B);
    const uint64_t bLd = sdesc(sb + OFF_B + 24576);
    char* ah = smem + OFF_A;
    char* al = smem + OFF_A + 16384;

    // ---------------- layer-0 K-chunk loop (single buffer) ----------------
    for (int c = 0; c < NC; c++) {
        if (c > 0) mbar_wait(mb, (c - 1) & 1);

        {   // A: fp32 -> bf16 hi/lo, SW128-swizzled STS (4 float4 / thread)
#pragma unroll
            for (int j = 0; j < 4; j++) {
                int idx = tid + j * NTHR;
                int r = idx >> 4, s = idx & 15;
                float4 v = *(const float4*)(x + (size_t)(row0 + r) * DDIM + c * 64 + s * 4);
                __nv_bfloat16 hx = __float2bfloat16(v.x);
                __nv_bfloat16 hy = __float2bfloat16(v.y);
                __nv_bfloat16 hz = __float2bfloat16(v.z);
                __nv_bfloat16 hw = __float2bfloat16(v.w);
                __nv_bfloat16 lx = __float2bfloat16(v.x - __bfloat162float(hx));
                __nv_bfloat16 ly = __float2bfloat16(v.y - __bfloat162float(hy));
                __nv_bfloat16 lz = __float2bfloat16(v.z - __bfloat162float(hz));
                __nv_bfloat16 lw = __float2bfloat16(v.w - __bfloat162float(hw));
                uint32_t off = (uint32_t)r * 128 + (uint32_t)s * 8;
                off ^= ((off >> 3) & 0x70);
                *(__nv_bfloat162*)(ah + off)     = __nv_bfloat162(hx, hy);
                *(__nv_bfloat162*)(ah + off + 4) = __nv_bfloat162(hz, hw);
                *(__nv_bfloat162*)(al + off)     = __nv_bfloat162(lx, ly);
                *(__nv_bfloat162*)(al + off + 4) = __nv_bfloat162(lz, lw);
            }
        }
        {   // B(c): pre-swizzled raw copy (3 float4 / thread per buffer)
            const float4* bh = (const float4*)(B0hi_g + (size_t)c * (NG * 64));
            const float4* bl = (const float4*)(B0lo_g + (size_t)c * (NG * 64));
            float4* sh = (float4*)(smem + OFF_B);
            float4* sl = (float4*)(smem + OFF_B + 24576);
#pragma unroll
            for (int j = 0; j < 3; j++) {
                int idx = tid + j * NTHR;
                sh[idx] = bh[idx];
                sl[idx] = bl[idx];
            }
        }
        __syncthreads();

        if (wid == 0 && elect1()) {
            asm volatile("fence.proxy.async.shared::cta;" ::: "memory");
#pragma unroll
            for (int ks = 0; ks < 4; ks++)
                mma_bf16_ss(tmem, aHd + ks * 2, bHd + ks * 2, IDESC, !(c == 0 && ks == 0));
#pragma unroll
            for (int ks = 0; ks < 4; ks++)
                mma_bf16_ss(tmem, aHd + ks * 2, bLd + ks * 2, IDESC, true);
#pragma unroll
            for (int ks = 0; ks < 4; ks++)
                mma_bf16_ss(tmem, aLd + ks * 2, bHd + ks * 2, IDESC, true);
            asm volatile(
                "tcgen05.commit.cta_group::1.mbarrier::arrive::one.shared::cluster.b64 [%0];"
                :: "r"(mb) : "memory");
        }
        if (c + 1 < NC) __syncthreads();
    }

    mbar_wait(mb, (NC - 1) & 1);
    asm volatile("tcgen05.fence::after_thread_sync;" ::: "memory");

    // B1 into the B buffer, overlapped with epilogue-0 start
    {
        const float4* bh = (const float4*)B1hi_g;
        const float4* bl = (const float4*)B1lo_g;
        float4* sh = (float4*)(smem + OFF_B);
        float4* sl = (float4*)(smem + OFF_B + 24576);
#pragma unroll
        for (int j = 0; j < 3; j++) {
            int idx = tid + j * NTHR;
            sh[idx] = bh[idx];
            sl[idx] = bl[idx];
        }
    }

    // ---------------- epilogue 0 (writes layer-1 A tile) ----------------
    epilogue_quarter<true>(tmem, bt0, gm0, bet0, exq, ah, al,
                           nullptr, h0last, c0last, q, rl, myrow);

    asm volatile("tcgen05.fence::before_thread_sync;" ::: "memory");
    __syncthreads();

    // ---------------- layer-1 GEMM (K=64, reuse TMEM cols 0-191) ----------
    if (wid == 0 && elect1()) {
        asm volatile("tcgen05.fence::after_thread_sync;" ::: "memory");
        asm volatile("fence.proxy.async.shared::cta;" ::: "memory");
#pragma unroll
        for (int ks = 0; ks < 4; ks++)
            mma_bf16_ss(tmem, aHd + ks * 2, bHd + ks * 2, IDESC, ks != 0);
#pragma unroll
        for (int ks = 0; ks < 4; ks++)
            mma_bf16_ss(tmem, aHd + ks * 2, bLd + ks * 2, IDESC, true);
#pragma unroll
        for (int ks = 0; ks < 4; ks++)
            mma_bf16_ss(tmem, aLd + ks * 2, bHd + ks * 2, IDESC, true);
        asm volatile(
            "tcgen05.commit.cta_group::1.mbarrier::arrive::one.shared::cluster.b64 [%0];"
            :: "r"(mb) : "memory");
    }
    mbar_wait(mb, NC & 1);      // 9th completion -> parity 0
    asm volatile("tcgen05.fence::after_thread_sync;" ::: "memory");

    // ---------------- epilogue 1 (writes final output) ----------------
    epilogue_quarter<false>(tmem, bt1, gm1, bet1, exq, nullptr, nullptr,
                            out, h1last, c1last, q, rl, myrow);

    asm volatile("tcgen05.fence::before_thread_sync;" ::: "memory");
    __syncthreads();
    if (wid == 0) {
        asm volatile("tcgen05.dealloc.cta_group::1.sync.aligned.b32 %0, %1;"
                     :: "r"(tmem), "r"(256u));
    }

#else  // ---------------- scalar fallback (correctness-only) ----------------
    float* xs = (float*)smem;                    // [128][64] fp32 (0..32KB)
    float* ws = (float*)(smem + 32768);          // [192][64] fp32 (32..80KB)
    const int colbase = q * 16;
    const bool tail = (myrow >= NROWS - BB);
    const int tb = myrow - (NROWS - BB);
    __syncthreads();

    float z[48];
#pragma unroll
    for (int i = 0; i < 48; i++) z[i] = 0.0f;

    for (int kt = 0; kt < 8; kt++) {
        __syncthreads();
        for (int i = tid; i < 128 * 16; i += NTHR) {
            int r = i >> 4, s = i & 15;
            *(float4*)&xs[r * 64 + s * 4] =
                *(const float4*)(x + (size_t)(row0 + r) * DDIM + kt * 64 + s * 4);
        }
        for (int i = tid; i < 192 * 16; i += NTHR) {
            int n = i >> 4, s = i & 15;
            *(float4*)&ws[n * 64 + s * 4] =
                *(const float4*)(W0raw + (size_t)(64 + n) * (DDIM + HH) + kt * 64 + s * 4);
        }
        __syncthreads();
        for (int g = 0; g < 3; g++)
            for (int j = 0; j < 16; j++) {
                int n = g * 64 + colbase + j;
                float acc = z[g * 16 + j];
                for (int k = 0; k < 64; k++)
                    acc = fmaf(xs[rl * 64 + k], ws[n * 64 + k], acc);
                z[g * 16 + j] = acc;
            }
    }

    for (int layer = 0; layer < 2; layer++) {
        const float* bt  = layer ? bt1  : bt0;
        const float* gm  = layer ? gm1  : gm0;
        const float* bet = layer ? bet1 : bet0;
        float* hl = layer ? h1last : h0last;
        float* cl = layer ? c1last : c0last;
        float hv[16];
        for (int g = 0; g < 3; g++) {
            float cs[16];
            for (int j = 0; j < 16; j++)
                cs[j] = cosf(z[g * 16 + j] + bt[g * 64 + colbase + j]);
            for (int j = 1; j < 16; j++) cs[j] *= cs[j - 1];
            exq[q * 128 + rl] = cs[15];
            __syncthreads();
            if (q > 0) {
                float p = exq[rl];
                if (q >= 2) p *= exq[128 + rl];
                if (q >= 3) p *= exq[256 + rl];
                for (int j = 0; j < 16; j++) cs[j] *= p;
            }
            __syncthreads();
            if (g == 0)      for (int j = 0; j < 16; j++) hv[j] = 1.0f / (1.0f + expf(-cs[j]));
            else if (g == 1) {
                for (int j = 0; j < 16; j++) hv[j] *= tanhf(1.0f / (1.0f + expf(-cs[j])));
                if (tail) for (int j = 0; j < 16; j++) cl[(size_t)tb * HH + colbase + j] = hv[j];
            } else           for (int j = 0; j < 16; j++) hv[j] = (1.0f / (1.0f + expf(-cs[j]))) * tanhf(hv[j]);
        }
        float s = 0.0f;
        for (int j = 0; j < 16; j++) s += hv[j];
        exq[q * 128 + rl] = s;
        __syncthreads();
        float mu = (exq[rl] + exq[128 + rl] + exq[256 + rl] + exq[384 + rl]) * (1.0f / 64.0f);
        float qq = 0.0f;
        for (int j = 0; j < 16; j++) { float d = hv[j] - mu; qq += d * d; }
        __syncthreads();
        exq[q * 128 + rl] = qq;
        __syncthreads();
        float rinv = rsqrtf((exq[rl] + exq[128 + rl] + exq[256 + rl] + exq[384 + rl])
                            * (1.0f / 64.0f) + EPSV);
        for (int j = 0; j < 16; j++)
            hv[j] = (hv[j] - mu) * rinv * gm[colbase + j] + bet[colbase + j];
        __syncthreads();

        if (layer == 0) {
            for (int j = 0; j < 16; j++) xs[rl * 64 + colbase + j] = hv[j];
            __syncthreads();
            for (int i = tid; i < 192 * 16; i += NTHR) {
                int n = i >> 4, sdx = i & 15;
                *(float4*)&ws[n * 64 + sdx * 4] =
                    *(const float4*)(W1raw + (size_t)(64 + n) * (HH + HH) + sdx * 4);
            }
            __syncthreads();
            for (int g = 0; g < 3; g++)
                for (int j = 0; j < 16; j++) {
                    int n = g * 64 + colbase + j;
                    float acc = 0.0f;
                    for (int k = 0; k < 64; k++)
                        acc = fmaf(xs[rl * 64 + k], ws[n * 64 + k], acc);
                    z[g * 16 + j] = acc;
                }
            if (tail)
                for (int j = 0; j < 16; j++) hl[(size_t)tb * HH + colbase + j] = hv[j];
        } else {
            for (int j = 0; j < 16; j++) out[(size_t)myrow * HH + colbase + j] = hv[j];
            if (tail) for (int j = 0; j < 16; j++) hl[(size_t)tb * HH + colbase + j] = hv[j];
        }
        __syncthreads();
    }
#endif // HAS_TC
}

// ================================================================ launch
extern "C" void kernel_launch(void* const* d_in, const int* in_sizes, int n_in,
                              void* d_out, int out_size) {
    const float* inputs = (const float*)d_in[0];
    const float* W0  = (const float*)d_in[1];
    const float* b0  = (const float*)d_in[2];
    const float* th0 = (const float*)d_in[3];
    const float* g0  = (const float*)d_in[4];
    const float* be0 = (const float*)d_in[5];
    const float* W1  = (const float*)d_in[6];
    const float* b1  = (const float*)d_in[7];
    const float* th1 = (const float*)d_in[8];
    const float* g1  = (const float*)d_in[9];
    const float* be1 = (const float*)d_in[10];

    float* out = (float*)d_out;
    const size_t out_main = (size_t)NROWS * HH;
    float* h0last = out + out_main;
    float* c0last = h0last + BB * HH;
    float* h1last = c0last + BB * HH;
    float* c1last = h1last + BB * HH;

    __nv_bfloat16 *b0hi, *b0lo, *b1hi, *b1lo;
    cudaGetSymbolAddress((void**)&b0hi, g_B0hi);
    cudaGetSymbolAddress((void**)&b0lo, g_B0lo);
    cudaGetSymbolAddress((void**)&b1hi, g_B1hi);
    cudaGetSymbolAddress((void**)&b1lo, g_B1lo);

    cudaFuncSetAttribute((const void*)qlstm_fused_kernel,
                         cudaFuncAttributeMaxDynamicSharedMemorySize, SMEM_TOTAL);

    prep_w_kernel<<<(8 * NG * 64 + 255) / 256, 256>>>(W0, W1);

    qlstm_fused_kernel<<<NROWS / 128, NTHR, SMEM_TOTAL>>>(
        inputs, W0, W1, b0hi, b0lo, b1hi, b1lo,
        b0, th0, g0, be0, b1, th1, g1, be1,
        out, h0last, c0last, h1last, c1last);
}

// round 11
// speedup vs baseline: 1.1970x; 1.0057x over previous
#include <cuda_runtime.h>
#include <cuda_bf16.h>
#include <math.h>
#include <stdint.h>

// ---------------------------------------------------------------- constants
#define TT     512
#define BB     128
#define DDIM   512
#define HH     64
#define NROWS  (TT * BB)          // 65536 independent (t,b) rows
#define NG     192                // 3 gates (i, g, o) x 64 qubits
#define EPSV   1e-5f
#define NTHR   512

// Arch-specific feature gate: tcgen05 exists only on sm_10xa targets.
#if defined(__CUDA_ARCH__) && (defined(__CUDA_ARCH_FEAT_SM103_ALL) || \
    defined(__CUDA_ARCH_FEAT_SM100_ALL) || defined(__CUDA_ARCH_SPECIFIC__))
#define HAS_TC 1
#endif

// dynamic SMEM layout:
//   A:       0 (hi 16KB) / 16384 (lo 16KB)
//   B:   32768 (hi 24KB) / 57344 (lo 24KB)
//   params/exchange: 81920 (12.8KB: params 640f, gate-exch 3x512f, LN 2x512f)
//   ctrl: 94720 (tmem ptr +0, mbar +8)
#define OFF_A      0
#define OFF_B      32768
#define OFF_PAR    81920
#define OFF_CTRL   94720
#define SMEM_TOTAL 94784

// idesc: kind::f16, bf16 x bf16 -> f32, M=128, N=192
#define IDESC ((1u << 4) | (1u << 7) | (1u << 10) | ((NG / 8) << 17) | ((128 / 16) << 24))

// ---------------------------------------------------------------- scratch
__device__ __nv_bfloat16  g_B0hi[8 * NG * 64];   // W0: 8 K-chunks, SW128 swizzled
__device__ __nv_bfloat16  g_B0lo[8 * NG * 64];
__device__ __nv_bfloat16  g_B1hi[NG * 64];       // W1: 1 K-chunk
__device__ __nv_bfloat16  g_B1lo[NG * 64];

// ================================================================ prolog
__global__ void prep_w_kernel(const float* __restrict__ W0,
                              const float* __restrict__ W1) {
#ifdef HAS_TC
    int idx = blockIdx.x * blockDim.x + threadIdx.x;
    if (idx < 8 * NG * 64) {
        int c   = idx / (NG * 64);
        int rem = idx % (NG * 64);
        int n   = rem / 64, kl = rem % 64;
        float w = W0[(size_t)(64 + n) * (DDIM + HH) + c * 64 + kl];
        __nv_bfloat16 hi = __float2bfloat16(w);
        __nv_bfloat16 lo = __float2bfloat16(w - __bfloat162float(hi));
        uint32_t boff = ((uint32_t)(n >> 3)) * 1024 + ((uint32_t)(n & 7)) * 128 + kl * 2;
        boff ^= ((boff >> 3) & 0x70);
        g_B0hi[(size_t)c * (NG * 64) + boff / 2] = hi;
        g_B0lo[(size_t)c * (NG * 64) + boff / 2] = lo;
    }
    if (idx < NG * 64) {
        int n = idx / 64, kl = idx % 64;
        float w = W1[(size_t)(64 + n) * (HH + HH) + kl];
        __nv_bfloat16 hi = __float2bfloat16(w);
        __nv_bfloat16 lo = __float2bfloat16(w - __bfloat162float(hi));
        uint32_t boff = ((uint32_t)(n >> 3)) * 1024 + ((uint32_t)(n & 7)) * 128 + kl * 2;
        boff ^= ((boff >> 3) & 0x70);
        g_B1hi[boff / 2] = hi;
        g_B1lo[boff / 2] = lo;
    }
#endif
}

// ================================================================ PTX helpers
#ifdef HAS_TC
static __device__ __forceinline__ uint32_t smem_u32(const void* p) {
    uint32_t a;
    asm("{ .reg .u64 t; cvta.to.shared.u64 t, %1; cvt.u32.u64 %0, t; }"
        : "=r"(a) : "l"(p));
    return a;
}
static __device__ __forceinline__ uint32_t elect1() {
    uint32_t p;
    asm volatile("{\n .reg .pred p;\n elect.sync _|p, 0xFFFFFFFF;\n selp.b32 %0,1,0,p;\n}"
                 : "=r"(p));
    return p;
}
static __device__ __forceinline__ uint64_t sdesc(uint32_t addr) {
    return (2ull << 61) | (1ull << 46) | (64ull << 32) | (1ull << 16)
         | ((uint64_t)(addr >> 4) & 0x3FFF);
}
static __device__ __forceinline__ void mma_bf16_ss(uint32_t d, uint64_t ad, uint64_t bd,
                                                   uint32_t idesc, bool accum) {
    uint32_t en = accum ? 1u : 0u;
    asm volatile(
        "{\n\t"
        ".reg .pred p;\n\t"
        "setp.ne.u32 p, %5, 0;\n\t"
        "tcgen05.mma.cta_group::1.kind::f16 [%0], %1, %2, %3, {%4, %4, %4, %4}, p;\n\t"
        "}"
        :: "r"(d), "l"(ad), "l"(bd), "r"(idesc), "r"(0u), "r"(en)
        : "memory");
}
static __device__ __forceinline__ void mbar_wait(uint32_t mbar, uint32_t parity) {
    uint32_t done;
    asm volatile(
        "{\n .reg .pred p;\n"
        " mbarrier.try_wait.parity.acquire.cta.shared::cta.b64 p, [%1], %2;\n"
        " selp.b32 %0, 1, 0, p;\n}"
        : "=r"(done) : "r"(mbar), "r"(parity) : "memory");
    if (!done) {
        asm volatile(
            "{\n .reg .pred P1;\n"
            "WL%=:\n"
            " mbarrier.try_wait.parity.acquire.cta.shared::cta.b64 P1, [%0], %1, 0x989680;\n"
            " @P1 bra.uni WD%=;\n"
            " bra.uni WL%=;\n"
            "WD%=:\n}"
            :: "r"(mbar), "r"(parity) : "memory");
    }
}
// named barrier for a 4-warp row-group (128 threads)
static __device__ __forceinline__ void gbar(int id) {
    asm volatile("bar.sync %0, %1;" :: "r"(id), "r"(128) : "memory");
}
#define TC_WAIT_LD() asm volatile("tcgen05.wait::ld.sync.aligned;" ::: "memory")
#define LDTM_X16(r, addr)                                              \
    asm volatile(                                                       \
        "tcgen05.ld.sync.aligned.32x32b.x16.b32 "                       \
        "{%0, %1, %2, %3, %4, %5, %6, %7, "                             \
        " %8, %9, %10, %11, %12, %13, %14, %15}, [%16];"                \
        : "=r"((r)[0]),  "=r"((r)[1]),  "=r"((r)[2]),  "=r"((r)[3]),    \
          "=r"((r)[4]),  "=r"((r)[5]),  "=r"((r)[6]),  "=r"((r)[7]),    \
          "=r"((r)[8]),  "=r"((r)[9]),  "=r"((r)[10]), "=r"((r)[11]),   \
          "=r"((r)[12]), "=r"((r)[13]), "=r"((r)[14]), "=r"((r)[15])    \
        : "r"(addr))

static __device__ __forceinline__ float frcp(float x) {
    float y; asm("rcp.approx.f32 %0, %1;" : "=f"(y) : "f"(x)); return y;
}
// sigmoid(q), |q| <= 1: odd poly deg-11, err ~2e-7, FMA-only (0 MUFU)
static __device__ __forceinline__ float psig(float q) {
    float u = q * q;
    float p = fmaf(u, -2.1638741e-6f, 2.1358436e-5f);
    p = fmaf(u, p, -2.1081349e-4f);
    p = fmaf(u, p,  2.0833333e-3f);
    p = fmaf(u, p, -2.0833333e-2f);
    p = fmaf(u, p,  0.25f);
    return fmaf(q, p, 0.5f);
}
// tanh(x), 0 <= x <= 0.75: Pade(7,6), err < 1e-8, 1 MUFU rcp + FMAs
static __device__ __forceinline__ float ptanh(float x) {
    float u = x * x;
    float n = fmaf(u + 378.0f, u, 17325.0f);
    n = fmaf(n, u, 135135.0f);
    float d = fmaf(28.0f, u, 3150.0f);
    d = fmaf(d, u, 62370.0f);
    d = fmaf(d, u, 135135.0f);
    return x * n * frcp(d);
}

// ---------------------------------------------------------------- epilogue quarter
// Row rl is owned by 4 threads (quarters q=0..3), each handling 16 gate cols.
// Exchanges use per-gate regions exg[3][512] + LN (exs, exss); synchronization
// is a NAMED barrier over the 4-warp row-group only (id = 1 + (wid&3)).
template <bool L0>
static __device__ __forceinline__ void epilogue_quarter(
    uint32_t tmem, const float* __restrict__ bt,
    const float* __restrict__ gm, const float* __restrict__ bet,
    volatile float* exg, volatile float* exs, volatile float* exss,
    char* ahi, char* alo, float* __restrict__ outp,
    float* __restrict__ hlast, float* __restrict__ clast,
    int q, int rl, int gid, int myrow)
{
    float hv[16], cs[16];
    uint32_t* ru = (uint32_t*)cs;
    const int colbase = q * 16;
    const bool tail = (myrow >= NROWS - BB);
    const int tb = myrow - (NROWS - BB);

#pragma unroll
    for (int g = 0; g < 3; g++) {
        LDTM_X16(ru, tmem + g * 64 + colbase);
        TC_WAIT_LD();
#pragma unroll
        for (int j = 0; j < 16; j++)
            cs[j] = __cosf(__uint_as_float(ru[j]) + bt[g * 64 + colbase + j]);
        // local inclusive scan of 16: two chains of 8, then splice
#pragma unroll
        for (int g8 = 0; g8 < 2; g8++)
#pragma unroll
            for (int j = 1; j < 8; j++)
                cs[g8 * 8 + j] *= cs[g8 * 8 + j - 1];
        {
            float t0 = cs[7];
#pragma unroll
            for (int j = 0; j < 8; j++) cs[8 + j] *= t0;
        }
        exg[g * 512 + q * 128 + rl] = cs[15];
        gbar(gid);
        if (q > 0) {
            float p = exg[g * 512 + rl];
            if (q >= 2) p *= exg[g * 512 + 128 + rl];
            if (q >= 3) p *= exg[g * 512 + 256 + rl];
#pragma unroll
            for (int j = 0; j < 16; j++) cs[j] *= p;
        }

        if (g == 0) {
#pragma unroll
            for (int j = 0; j < 16; j++) hv[j] = psig(cs[j]);
        } else if (g == 1) {
#pragma unroll
            for (int j = 0; j < 16; j++) hv[j] *= ptanh(psig(cs[j]));   // c
            if (tail) {
                float4* cd = (float4*)(clast + (size_t)tb * HH) + q * 4;
#pragma unroll
                for (int j = 0; j < 4; j++)
                    cd[j] = make_float4(hv[4*j], hv[4*j+1], hv[4*j+2], hv[4*j+3]);
            }
        } else {
#pragma unroll
            for (int j = 0; j < 16; j++) hv[j] = psig(cs[j]) * ptanh(hv[j]);  // h
        }
    }

    // layernorm across 4 quarters: one exchange round (sum + sum of squares)
    float s = 0.0f, ssq = 0.0f;
#pragma unroll
    for (int j = 0; j < 16; j++) { s += hv[j]; ssq = fmaf(hv[j], hv[j], ssq); }
    exs[q * 128 + rl]  = s;
    exss[q * 128 + rl] = ssq;
    gbar(gid);
    float mu  = (exs[rl] + exs[128 + rl] + exs[256 + rl] + exs[384 + rl]) * (1.0f / 64.0f);
    float eh2 = (exss[rl] + exss[128 + rl] + exss[256 + rl] + exss[384 + rl]) * (1.0f / 64.0f);
    float rinv = rsqrtf(fmaf(-mu, mu, eh2) + EPSV);
#pragma unroll
    for (int j = 0; j < 16; j++)
        hv[j] = (hv[j] - mu) * rinv * gm[colbase + j] + bet[colbase + j];

    if (L0) {
        // h_ln -> bf16 hi/lo into SMEM A tile (SW128, layer-1 operand)
#pragma unroll
        for (int j8 = 0; j8 < 2; j8++) {
            __nv_bfloat162 ph[4], pl[4];
#pragma unroll
            for (int p2 = 0; p2 < 4; p2++) {
                float v0 = hv[j8 * 8 + p2 * 2], v1 = hv[j8 * 8 + p2 * 2 + 1];
                __nv_bfloat16 h0 = __float2bfloat16(v0);
                __nv_bfloat16 h1 = __float2bfloat16(v1);
                ph[p2] = __nv_bfloat162(h0, h1);
                pl[p2] = __nv_bfloat162(__float2bfloat16(v0 - __bfloat162float(h0)),
                                        __float2bfloat16(v1 - __bfloat162float(h1)));
            }
            uint32_t off = (uint32_t)rl * 128 + (uint32_t)q * 32 + j8 * 16;
            off ^= ((off >> 3) & 0x70);
            *(uint4*)(ahi + off) = *(uint4*)ph;
            *(uint4*)(alo + off) = *(uint4*)pl;
        }
        if (tail) {
            float4* hd = (float4*)(hlast + (size_t)tb * HH) + q * 4;
#pragma unroll
            for (int j = 0; j < 4; j++)
                hd[j] = make_float4(hv[4*j], hv[4*j+1], hv[4*j+2], hv[4*j+3]);
        }
    } else {
        float4* od = (float4*)(outp + (size_t)myrow * HH) + q * 4;
#pragma unroll
        for (int j = 0; j < 4; j++)
            od[j] = make_float4(hv[4*j], hv[4*j+1], hv[4*j+2], hv[4*j+3]);
        if (tail) {
            float4* hd = (float4*)(hlast + (size_t)tb * HH) + q * 4;
#pragma unroll
            for (int j = 0; j < 4; j++)
                hd[j] = make_float4(hv[4*j], hv[4*j+1], hv[4*j+2], hv[4*j+3]);
        }
    }
}
#endif // HAS_TC

// ================================================================ fused kernel
__global__ void __launch_bounds__(NTHR, 2)
qlstm_fused_kernel(const float* __restrict__ x,
                   const float* __restrict__ W0raw,
                   const float* __restrict__ W1raw,
                   const __nv_bfloat16* __restrict__ B0hi_g,
                   const __nv_bfloat16* __restrict__ B0lo_g,
                   const __nv_bfloat16* __restrict__ B1hi_g,
                   const __nv_bfloat16* __restrict__ B1lo_g,
                   const float* __restrict__ b0, const float* __restrict__ th0,
                   const float* __restrict__ g0, const float* __restrict__ be0,
                   const float* __restrict__ b1, const float* __restrict__ th1,
                   const float* __restrict__ g1, const float* __restrict__ be1,
                   float* __restrict__ out,
                   float* __restrict__ h0last, float* __restrict__ c0last,
                   float* __restrict__ h1last, float* __restrict__ c1last)
{
    extern __shared__ __align__(1024) char smem[];
    const int tid = threadIdx.x, wid = tid >> 5, lane = tid & 31;
    const int q  = wid >> 2;                    // quarter 0..3 (16 gate cols)
    const int rl = (wid & 3) * 32 + lane;       // local row 0..127
    const int gid = 1 + (wid & 3);              // named-barrier id for row-group
    const int row0 = blockIdx.x * 128;
    const int myrow = row0 + rl;

    float* fp   = (float*)(smem + OFF_PAR);
    float* bt0  = fp;          // 192
    float* bt1  = fp + 192;    // 192
    float* gm0  = fp + 384;    // 64
    float* bet0 = fp + 448;
    float* gm1  = fp + 512;
    float* bet1 = fp + 576;
    float* exg  = fp + 640;    // 3 x 512 (per-gate exchange)
    float* exs  = fp + 2176;   // 512 (LN sum)
    float* exss = fp + 2688;   // 512 (LN sum of squares)

    if (tid < NG) {
        bt0[tid] = b0[64 + tid] + th0[64 + tid];
        bt1[tid] = b1[64 + tid] + th1[64 + tid];
    }
    if (tid >= 192 && tid < 256) {
        int i = tid - 192;
        gm0[i] = g0[i]; bet0[i] = be0[i];
        gm1[i] = g1[i]; bet1[i] = be1[i];
    }

#ifdef HAS_TC
    constexpr int NC = 8;
    const uint32_t sb = smem_u32(smem);
    const uint32_t mb = sb + OFF_CTRL + 8;
    if (wid == 0) {
        asm volatile("tcgen05.alloc.cta_group::1.sync.aligned.shared::cta.b32 [%0], %1;"
                     :: "r"(sb + OFF_CTRL), "r"(256u) : "memory");
        asm volatile("tcgen05.relinquish_alloc_permit.cta_group::1.sync.aligned;");
    }
    if (tid == 0) {
        asm volatile("mbarrier.init.shared.b64 [%0], %1;" :: "r"(mb), "r"(1u) : "memory");
    }
    __syncthreads();
    uint32_t tmem;
    asm volatile("ld.shared.b32 %0, [%1];" : "=r"(tmem) : "r"(sb + OFF_CTRL));

    const uint64_t aHd = sdesc(sb + OFF_A);
    const uint64_t aLd = sdesc(sb + OFF_A + 16384);
    const uint64_t bHd = sdesc(sb + OFF_B);
    const uint64_t bLd = sdesc(sb + OFF_B + 24576);
    char* ah = smem + OFF_A;
    char* al = smem + OFF_A + 16384;

    // ---------------- layer-0 K-chunk loop (single buffer) ----------------
    // NOTE: no tail barrier per chunk — iteration c+1's mbar_wait(commit(c))
    // already guarantees MMA(c) consumed the buffers (acquire orders the STS).
    for (int c = 0; c < NC; c++) {
        if (c > 0) mbar_wait(mb, (c - 1) & 1);

        {   // A: fp32 -> bf16 hi/lo, SW128-swizzled STS (4 float4 / thread)
#pragma unroll
            for (int j = 0; j < 4; j++) {
                int idx = tid + j * NTHR;
                int r = idx >> 4, s = idx & 15;
                float4 v = *(const float4*)(x + (size_t)(row0 + r) * DDIM + c * 64 + s * 4);
                __nv_bfloat16 hx = __float2bfloat16(v.x);
                __nv_bfloat16 hy = __float2bfloat16(v.y);
                __nv_bfloat16 hz = __float2bfloat16(v.z);
                __nv_bfloat16 hw = __float2bfloat16(v.w);
                __nv_bfloat16 lx = __float2bfloat16(v.x - __bfloat162float(hx));
                __nv_bfloat16 ly = __float2bfloat16(v.y - __bfloat162float(hy));
                __nv_bfloat16 lz = __float2bfloat16(v.z - __bfloat162float(hz));
                __nv_bfloat16 lw = __float2bfloat16(v.w - __bfloat162float(hw));
                uint32_t off = (uint32_t)r * 128 + (uint32_t)s * 8;
                off ^= ((off >> 3) & 0x70);
                *(__nv_bfloat162*)(ah + off)     = __nv_bfloat162(hx, hy);
                *(__nv_bfloat162*)(ah + off + 4) = __nv_bfloat162(hz, hw);
                *(__nv_bfloat162*)(al + off)     = __nv_bfloat162(lx, ly);
                *(__nv_bfloat162*)(al + off + 4) = __nv_bfloat162(lz, lw);
            }
        }
        {   // B(c): pre-swizzled raw copy (3 float4 / thread per buffer)
            const float4* bh = (const float4*)(B0hi_g + (size_t)c * (NG * 64));
            const float4* bl = (const float4*)(B0lo_g + (size_t)c * (NG * 64));
            float4* sh = (float4*)(smem + OFF_B);
            float4* sl = (float4*)(smem + OFF_B + 24576);
#pragma unroll
            for (int j = 0; j < 3; j++) {
                int idx = tid + j * NTHR;
                sh[idx] = bh[idx];
                sl[idx] = bl[idx];
            }
        }
        __syncthreads();

        if (wid == 0 && elect1()) {
            asm volatile("fence.proxy.async.shared::cta;" ::: "memory");
#pragma unroll
            for (int ks = 0; ks < 4; ks++)
                mma_bf16_ss(tmem, aHd + ks * 2, bHd + ks * 2, IDESC, !(c == 0 && ks == 0));
#pragma unroll
            for (int ks = 0; ks < 4; ks++)
                mma_bf16_ss(tmem, aHd + ks * 2, bLd + ks * 2, IDESC, true);
#pragma unroll
            for (int ks = 0; ks < 4; ks++)
                mma_bf16_ss(tmem, aLd + ks * 2, bHd + ks * 2, IDESC, true);
            asm volatile(
                "tcgen05.commit.cta_group::1.mbarrier::arrive::one.shared::cluster.b64 [%0];"
                :: "r"(mb) : "memory");
        }
    }

    mbar_wait(mb, (NC - 1) & 1);
    asm volatile("tcgen05.fence::after_thread_sync;" ::: "memory");

    // B1 into the B buffer, overlapped with epilogue-0 start
    {
        const float4* bh = (const float4*)B1hi_g;
        const float4* bl = (const float4*)B1lo_g;
        float4* sh = (float4*)(smem + OFF_B);
        float4* sl = (float4*)(smem + OFF_B + 24576);
#pragma unroll
        for (int j = 0; j < 3; j++) {
            int idx = tid + j * NTHR;
            sh[idx] = bh[idx];
            sl[idx] = bl[idx];
        }
    }

    // ---------------- epilogue 0 (writes layer-1 A tile) ----------------
    epilogue_quarter<true>(tmem, bt0, gm0, bet0, exg, exs, exss, ah, al,
                           nullptr, h0last, c0last, q, rl, gid, myrow);

    asm volatile("tcgen05.fence::before_thread_sync;" ::: "memory");
    __syncthreads();

    // ---------------- layer-1 GEMM (K=64, reuse TMEM cols 0-191) ----------
    if (wid == 0 && elect1()) {
        asm volatile("tcgen05.fence::after_thread_sync;" ::: "memory");
        asm volatile("fence.proxy.async.shared::cta;" ::: "memory");
#pragma unroll
        for (int ks = 0; ks < 4; ks++)
            mma_bf16_ss(tmem, aHd + ks * 2, bHd + ks * 2, IDESC, ks != 0);
#pragma unroll
        for (int ks = 0; ks < 4; ks++)
            mma_bf16_ss(tmem, aHd + ks * 2, bLd + ks * 2, IDESC, true);
#pragma unroll
        for (int ks = 0; ks < 4; ks++)
            mma_bf16_ss(tmem, aLd + ks * 2, bHd + ks * 2, IDESC, true);
        asm volatile(
            "tcgen05.commit.cta_group::1.mbarrier::arrive::one.shared::cluster.b64 [%0];"
            :: "r"(mb) : "memory");
    }
    mbar_wait(mb, NC & 1);      // 9th completion -> parity 0
    asm volatile("tcgen05.fence::after_thread_sync;" ::: "memory");

    // ---------------- epilogue 1 (writes final output) ----------------
    epilogue_quarter<false>(tmem, bt1, gm1, bet1, exg, exs, exss, nullptr, nullptr,
                            out, h1last, c1last, q, rl, gid, myrow);

    asm volatile("tcgen05.fence::before_thread_sync;" ::: "memory");
    __syncthreads();
    if (wid == 0) {
        asm volatile("tcgen05.dealloc.cta_group::1.sync.aligned.b32 %0, %1;"
                     :: "r"(tmem), "r"(256u));
    }

#else  // ---------------- scalar fallback (correctness-only) ----------------
    float* xs = (float*)smem;                    // [128][64] fp32 (0..32KB)
    float* ws = (float*)(smem + 32768);          // [192][64] fp32 (32..80KB)
    const int colbase = q * 16;
    const bool tail = (myrow >= NROWS - BB);
    const int tb = myrow - (NROWS - BB);
    __syncthreads();

    float z[48];
#pragma unroll
    for (int i = 0; i < 48; i++) z[i] = 0.0f;

    for (int kt = 0; kt < 8; kt++) {
        __syncthreads();
        for (int i = tid; i < 128 * 16; i += NTHR) {
            int r = i >> 4, s = i & 15;
            *(float4*)&xs[r * 64 + s * 4] =
                *(const float4*)(x + (size_t)(row0 + r) * DDIM + kt * 64 + s * 4);
        }
        for (int i = tid; i < 192 * 16; i += NTHR) {
            int n = i >> 4, s = i & 15;
            *(float4*)&ws[n * 64 + s * 4] =
                *(const float4*)(W0raw + (size_t)(64 + n) * (DDIM + HH) + kt * 64 + s * 4);
        }
        __syncthreads();
        for (int g = 0; g < 3; g++)
            for (int j = 0; j < 16; j++) {
                int n = g * 64 + colbase + j;
                float acc = z[g * 16 + j];
                for (int k = 0; k < 64; k++)
                    acc = fmaf(xs[rl * 64 + k], ws[n * 64 + k], acc);
                z[g * 16 + j] = acc;
            }
    }

    for (int layer = 0; layer < 2; layer++) {
        const float* bt  = layer ? bt1  : bt0;
        const float* gm  = layer ? gm1  : gm0;
        const float* bet = layer ? bet1 : bet0;
        float* hl = layer ? h1last : h0last;
        float* cl = layer ? c1last : c0last;
        float hv[16];
        for (int g = 0; g < 3; g++) {
            float cs[16];
            for (int j = 0; j < 16; j++)
                cs[j] = cosf(z[g * 16 + j] + bt[g * 64 + colbase + j]);
            for (int j = 1; j < 16; j++) cs[j] *= cs[j - 1];
            exg[g * 512 + q * 128 + rl] = cs[15];
            __syncthreads();
            if (q > 0) {
                float p = exg[g * 512 + rl];
                if (q >= 2) p *= exg[g * 512 + 128 + rl];
                if (q >= 3) p *= exg[g * 512 + 256 + rl];
                for (int j = 0; j < 16; j++) cs[j] *= p;
            }
            __syncthreads();
            if (g == 0)      for (int j = 0; j < 16; j++) hv[j] = 1.0f / (1.0f + expf(-cs[j]));
            else if (g == 1) {
                for (int j = 0; j < 16; j++) hv[j] *= tanhf(1.0f / (1.0f + expf(-cs[j])));
                if (tail) for (int j = 0; j < 16; j++) cl[(size_t)tb * HH + colbase + j] = hv[j];
            } else           for (int j = 0; j < 16; j++) hv[j] = (1.0f / (1.0f + expf(-cs[j]))) * tanhf(hv[j]);
        }
        float s = 0.0f, ssq = 0.0f;
        for (int j = 0; j < 16; j++) { s += hv[j]; ssq += hv[j] * hv[j]; }
        exs[q * 128 + rl] = s;
        exss[q * 128 + rl] = ssq;
        __syncthreads();
        float mu  = (exs[rl] + exs[128 + rl] + exs[256 + rl] + exs[384 + rl]) * (1.0f / 64.0f);
        float eh2 = (exss[rl] + exss[128 + rl] + exss[256 + rl] + exss[384 + rl]) * (1.0f / 64.0f);
        float rinv = rsqrtf(eh2 - mu * mu + EPSV);
        for (int j = 0; j < 16; j++)
            hv[j] = (hv[j] - mu) * rinv * gm[colbase + j] + bet[colbase + j];
        __syncthreads();

        if (layer == 0) {
            for (int j = 0; j < 16; j++) xs[rl * 64 + colbase + j] = hv[j];
            __syncthreads();
            for (int i = tid; i < 192 * 16; i += NTHR) {
                int n = i >> 4, sdx = i & 15;
                *(float4*)&ws[n * 64 + sdx * 4] =
                    *(const float4*)(W1raw + (size_t)(64 + n) * (HH + HH) + sdx * 4);
            }
            __syncthreads();
            for (int g = 0; g < 3; g++)
                for (int j = 0; j < 16; j++) {
                    int n = g * 64 + colbase + j;
                    float acc = 0.0f;
                    for (int k = 0; k < 64; k++)
                        acc = fmaf(xs[rl * 64 + k], ws[n * 64 + k], acc);
                    z[g * 16 + j] = acc;
                }
            if (tail)
                for (int j = 0; j < 16; j++) hl[(size_t)tb * HH + colbase + j] = hv[j];
        } else {
            for (int j = 0; j < 16; j++) out[(size_t)myrow * HH + colbase + j] = hv[j];
            if (tail) for (int j = 0; j < 16; j++) hl[(size_t)tb * HH + colbase + j] = hv[j];
        }
        __syncthreads();
    }
#endif // HAS_TC
}

// ================================================================ launch
extern "C" void kernel_launch(void* const* d_in, const int* in_sizes, int n_in,
                              void* d_out, int out_size) {
    const float* inputs = (const float*)d_in[0];
    const float* W0  = (const float*)d_in[1];
    const float* b0  = (const float*)d_in[2];
    const float* th0 = (const float*)d_in[3];
    const float* g0  = (const float*)d_in[4];
    const float* be0 = (const float*)d_in[5];
    const float* W1  = (const float*)d_in[6];
    const float* b1  = (const float*)d_in[7];
    const float* th1 = (const float*)d_in[8];
    const float* g1  = (const float*)d_in[9];
    const float* be1 = (const float*)d_in[10];

    float* out = (float*)d_out;
    const size_t out_main = (size_t)NROWS * HH;
    float* h0last = out + out_main;
    float* c0last = h0last + BB * HH;
    float* h1last = c0last + BB * HH;
    float* c1last = h1last + BB * HH;

    __nv_bfloat16 *b0hi, *b0lo, *b1hi, *b1lo;
    cudaGetSymbolAddress((void**)&b0hi, g_B0hi);
    cudaGetSymbolAddress((void**)&b0lo, g_B0lo);
    cudaGetSymbolAddress((void**)&b1hi, g_B1hi);
    cudaGetSymbolAddress((void**)&b1lo, g_B1lo);

    cudaFuncSetAttribute((const void*)qlstm_fused_kernel,
                         cudaFuncAttributeMaxDynamicSharedMemorySize, SMEM_TOTAL);

    prep_w_kernel<<<(8 * NG * 64 + 255) / 256, 256>>>(W0, W1);

    qlstm_fused_kernel<<<NROWS / 128, NTHR, SMEM_TOTAL>>>(
        inputs, W0, W1, b0hi, b0lo, b1hi, b1lo,
        b0, th0, g0, be0, b1, th1, g1, be1,
        out, h0last, c0last, h1last, c1last);
}

// round 12
// speedup vs baseline: 1.2509x; 1.0450x over previous
#include <cuda_runtime.h>
#include <cuda_bf16.h>
#include <math.h>
#include <stdint.h>

// ---------------------------------------------------------------- constants
#define TT     512
#define BB     128
#define DDIM   512
#define HH     64
#define NROWS  (TT * BB)          // 65536 independent (t,b) rows
#define NG     192                // 3 gates (i, g, o) x 64 qubits
#define EPSV   1e-5f
#define NTHR   512

// Arch-specific feature gate: tcgen05 exists only on sm_10xa targets.
#if defined(__CUDA_ARCH__) && (defined(__CUDA_ARCH_FEAT_SM103_ALL) || \
    defined(__CUDA_ARCH_FEAT_SM100_ALL) || defined(__CUDA_ARCH_SPECIFIC__))
#define HAS_TC 1
#endif

// dynamic SMEM layout:
//   A:       0 (hi 16KB) / 16384 (lo 16KB)
//   B:   32768 (hi 24KB) / 57344 (lo 24KB)
//   params/exchange: 81920 (12.8KB: params 640f, gate-exch 3x512f, LN 2x512f)
//   ctrl: 94720 (tmem ptr +0, mbar commit +8, mbar B-data +16)
#define OFF_A      0
#define OFF_B      32768
#define OFF_PAR    81920
#define OFF_CTRL   94720
#define SMEM_TOTAL 94784

// idesc: kind::f16, bf16 x bf16 -> f32, M=128, N=192
#define IDESC ((1u << 4) | (1u << 7) | (1u << 10) | ((NG / 8) << 17) | ((128 / 16) << 24))

#define B_HALF 24576u             // bytes per B half-tile (192 x 64 bf16)

// ---------------------------------------------------------------- scratch
__device__ __nv_bfloat16  g_B0hi[8 * NG * 64];   // W0: 8 K-chunks, SW128 swizzled
__device__ __nv_bfloat16  g_B0lo[8 * NG * 64];
__device__ __nv_bfloat16  g_B1hi[NG * 64];       // W1: 1 K-chunk
__device__ __nv_bfloat16  g_B1lo[NG * 64];

// ================================================================ prolog
__global__ void prep_w_kernel(const float* __restrict__ W0,
                              const float* __restrict__ W1) {
#ifdef HAS_TC
    int idx = blockIdx.x * blockDim.x + threadIdx.x;
    if (idx < 8 * NG * 64) {
        int c   = idx / (NG * 64);
        int rem = idx % (NG * 64);
        int n   = rem / 64, kl = rem % 64;
        float w = W0[(size_t)(64 + n) * (DDIM + HH) + c * 64 + kl];
        __nv_bfloat16 hi = __float2bfloat16(w);
        __nv_bfloat16 lo = __float2bfloat16(w - __bfloat162float(hi));
        uint32_t boff = ((uint32_t)(n >> 3)) * 1024 + ((uint32_t)(n & 7)) * 128 + kl * 2;
        boff ^= ((boff >> 3) & 0x70);
        g_B0hi[(size_t)c * (NG * 64) + boff / 2] = hi;
        g_B0lo[(size_t)c * (NG * 64) + boff / 2] = lo;
    }
    if (idx < NG * 64) {
        int n = idx / 64, kl = idx % 64;
        float w = W1[(size_t)(64 + n) * (HH + HH) + kl];
        __nv_bfloat16 hi = __float2bfloat16(w);
        __nv_bfloat16 lo = __float2bfloat16(w - __bfloat162float(hi));
        uint32_t boff = ((uint32_t)(n >> 3)) * 1024 + ((uint32_t)(n & 7)) * 128 + kl * 2;
        boff ^= ((boff >> 3) & 0x70);
        g_B1hi[boff / 2] = hi;
        g_B1lo[boff / 2] = lo;
    }
#endif
}

// ================================================================ PTX helpers
#ifdef HAS_TC
static __device__ __forceinline__ uint32_t smem_u32(const void* p) {
    uint32_t a;
    asm("{ .reg .u64 t; cvta.to.shared.u64 t, %1; cvt.u32.u64 %0, t; }"
        : "=r"(a) : "l"(p));
    return a;
}
static __device__ __forceinline__ uint32_t elect1() {
    uint32_t p;
    asm volatile("{\n .reg .pred p;\n elect.sync _|p, 0xFFFFFFFF;\n selp.b32 %0,1,0,p;\n}"
                 : "=r"(p));
    return p;
}
static __device__ __forceinline__ uint64_t sdesc(uint32_t addr) {
    return (2ull << 61) | (1ull << 46) | (64ull << 32) | (1ull << 16)
         | ((uint64_t)(addr >> 4) & 0x3FFF);
}
static __device__ __forceinline__ void mma_bf16_ss(uint32_t d, uint64_t ad, uint64_t bd,
                                                   uint32_t idesc, bool accum) {
    uint32_t en = accum ? 1u : 0u;
    asm volatile(
        "{\n\t"
        ".reg .pred p;\n\t"
        "setp.ne.u32 p, %5, 0;\n\t"
        "tcgen05.mma.cta_group::1.kind::f16 [%0], %1, %2, %3, {%4, %4, %4, %4}, p;\n\t"
        "}"
        :: "r"(d), "l"(ad), "l"(bd), "r"(idesc), "r"(0u), "r"(en)
        : "memory");
}
static __device__ __forceinline__ void mbar_wait(uint32_t mbar, uint32_t parity) {
    uint32_t done;
    asm volatile(
        "{\n .reg .pred p;\n"
        " mbarrier.try_wait.parity.acquire.cta.shared::cta.b64 p, [%1], %2;\n"
        " selp.b32 %0, 1, 0, p;\n}"
        : "=r"(done) : "r"(mbar), "r"(parity) : "memory");
    if (!done) {
        asm volatile(
            "{\n .reg .pred P1;\n"
            "WL%=:\n"
            " mbarrier.try_wait.parity.acquire.cta.shared::cta.b64 P1, [%0], %1, 0x989680;\n"
            " @P1 bra.uni WD%=;\n"
            " bra.uni WL%=;\n"
            "WD%=:\n}"
            :: "r"(mbar), "r"(parity) : "memory");
    }
}
// bulk copy gmem->smem (pre-swizzled bytes; no tensor map): UBLKCP
static __device__ __forceinline__ void bulk_g2s(uint32_t dst, const void* src,
                                                uint32_t bytes, uint32_t mbar) {
    asm volatile(
        "cp.async.bulk.shared::cta.global.mbarrier::complete_tx::bytes [%0], [%1], %2, [%3];"
        :: "r"(dst), "l"(src), "r"(bytes), "r"(mbar) : "memory");
}
static __device__ __forceinline__ void mbar_expect_tx(uint32_t mbar, uint32_t bytes) {
    asm volatile("mbarrier.arrive.expect_tx.shared.b64 _, [%0], %1;"
                 :: "r"(mbar), "r"(bytes) : "memory");
}
// named barrier for a 4-warp row-group (128 threads)
static __device__ __forceinline__ void gbar(int id) {
    asm volatile("bar.sync %0, %1;" :: "r"(id), "r"(128) : "memory");
}
#define TC_WAIT_LD() asm volatile("tcgen05.wait::ld.sync.aligned;" ::: "memory")
#define LDTM_X16(r, addr)                                              \
    asm volatile(                                                       \
        "tcgen05.ld.sync.aligned.32x32b.x16.b32 "                       \
        "{%0, %1, %2, %3, %4, %5, %6, %7, "                             \
        " %8, %9, %10, %11, %12, %13, %14, %15}, [%16];"                \
        : "=r"((r)[0]),  "=r"((r)[1]),  "=r"((r)[2]),  "=r"((r)[3]),    \
          "=r"((r)[4]),  "=r"((r)[5]),  "=r"((r)[6]),  "=r"((r)[7]),    \
          "=r"((r)[8]),  "=r"((r)[9]),  "=r"((r)[10]), "=r"((r)[11]),   \
          "=r"((r)[12]), "=r"((r)[13]), "=r"((r)[14]), "=r"((r)[15])    \
        : "r"(addr))

static __device__ __forceinline__ float frcp(float x) {
    float y; asm("rcp.approx.f32 %0, %1;" : "=f"(y) : "f"(x)); return y;
}
// sigmoid(q), |q| <= 1: odd poly deg-11, err ~2e-7, FMA-only (0 MUFU)
static __device__ __forceinline__ float psig(float q) {
    float u = q * q;
    float p = fmaf(u, -2.1638741e-6f, 2.1358436e-5f);
    p = fmaf(u, p, -2.1081349e-4f);
    p = fmaf(u, p,  2.0833333e-3f);
    p = fmaf(u, p, -2.0833333e-2f);
    p = fmaf(u, p,  0.25f);
    return fmaf(q, p, 0.5f);
}
// tanh(x), 0 <= x <= 0.75: Pade(7,6), err < 1e-8, 1 MUFU rcp + FMAs
static __device__ __forceinline__ float ptanh(float x) {
    float u = x * x;
    float n = fmaf(u + 378.0f, u, 17325.0f);
    n = fmaf(n, u, 135135.0f);
    float d = fmaf(28.0f, u, 3150.0f);
    d = fmaf(d, u, 62370.0f);
    d = fmaf(d, u, 135135.0f);
    return x * n * frcp(d);
}

// ---------------------------------------------------------------- epilogue quarter
template <bool L0>
static __device__ __forceinline__ void epilogue_quarter(
    uint32_t tmem, const float* __restrict__ bt,
    const float* __restrict__ gm, const float* __restrict__ bet,
    volatile float* exg, volatile float* exs, volatile float* exss,
    char* ahi, char* alo, float* __restrict__ outp,
    float* __restrict__ hlast, float* __restrict__ clast,
    int q, int rl, int gid, int myrow)
{
    float hv[16], cs[16];
    uint32_t* ru = (uint32_t*)cs;
    const int colbase = q * 16;
    const bool tail = (myrow >= NROWS - BB);
    const int tb = myrow - (NROWS - BB);

#pragma unroll
    for (int g = 0; g < 3; g++) {
        LDTM_X16(ru, tmem + g * 64 + colbase);
        TC_WAIT_LD();
#pragma unroll
        for (int j = 0; j < 16; j++)
            cs[j] = __cosf(__uint_as_float(ru[j]) + bt[g * 64 + colbase + j]);
#pragma unroll
        for (int g8 = 0; g8 < 2; g8++)
#pragma unroll
            for (int j = 1; j < 8; j++)
                cs[g8 * 8 + j] *= cs[g8 * 8 + j - 1];
        {
            float t0 = cs[7];
#pragma unroll
            for (int j = 0; j < 8; j++) cs[8 + j] *= t0;
        }
        exg[g * 512 + q * 128 + rl] = cs[15];
        gbar(gid);
        if (q > 0) {
            float p = exg[g * 512 + rl];
            if (q >= 2) p *= exg[g * 512 + 128 + rl];
            if (q >= 3) p *= exg[g * 512 + 256 + rl];
#pragma unroll
            for (int j = 0; j < 16; j++) cs[j] *= p;
        }

        if (g == 0) {
#pragma unroll
            for (int j = 0; j < 16; j++) hv[j] = psig(cs[j]);
        } else if (g == 1) {
#pragma unroll
            for (int j = 0; j < 16; j++) hv[j] *= ptanh(psig(cs[j]));   // c
            if (tail) {
                float4* cd = (float4*)(clast + (size_t)tb * HH) + q * 4;
#pragma unroll
                for (int j = 0; j < 4; j++)
                    cd[j] = make_float4(hv[4*j], hv[4*j+1], hv[4*j+2], hv[4*j+3]);
            }
        } else {
#pragma unroll
            for (int j = 0; j < 16; j++) hv[j] = psig(cs[j]) * ptanh(hv[j]);  // h
        }
    }

    // layernorm across 4 quarters: one exchange round (sum + sum of squares)
    float s = 0.0f, ssq = 0.0f;
#pragma unroll
    for (int j = 0; j < 16; j++) { s += hv[j]; ssq = fmaf(hv[j], hv[j], ssq); }
    exs[q * 128 + rl]  = s;
    exss[q * 128 + rl] = ssq;
    gbar(gid);
    float mu  = (exs[rl] + exs[128 + rl] + exs[256 + rl] + exs[384 + rl]) * (1.0f / 64.0f);
    float eh2 = (exss[rl] + exss[128 + rl] + exss[256 + rl] + exss[384 + rl]) * (1.0f / 64.0f);
    float rinv = rsqrtf(fmaf(-mu, mu, eh2) + EPSV);
#pragma unroll
    for (int j = 0; j < 16; j++)
        hv[j] = (hv[j] - mu) * rinv * gm[colbase + j] + bet[colbase + j];

    if (L0) {
#pragma unroll
        for (int j8 = 0; j8 < 2; j8++) {
            __nv_bfloat162 ph[4], pl[4];
#pragma unroll
            for (int p2 = 0; p2 < 4; p2++) {
                float v0 = hv[j8 * 8 + p2 * 2], v1 = hv[j8 * 8 + p2 * 2 + 1];
                __nv_bfloat16 h0 = __float2bfloat16(v0);
                __nv_bfloat16 h1 = __float2bfloat16(v1);
                ph[p2] = __nv_bfloat162(h0, h1);
                pl[p2] = __nv_bfloat162(__float2bfloat16(v0 - __bfloat162float(h0)),
                                        __float2bfloat16(v1 - __bfloat162float(h1)));
            }
            uint32_t off = (uint32_t)rl * 128 + (uint32_t)q * 32 + j8 * 16;
            off ^= ((off >> 3) & 0x70);
            *(uint4*)(ahi + off) = *(uint4*)ph;
            *(uint4*)(alo + off) = *(uint4*)pl;
        }
        if (tail) {
            float4* hd = (float4*)(hlast + (size_t)tb * HH) + q * 4;
#pragma unroll
            for (int j = 0; j < 4; j++)
                hd[j] = make_float4(hv[4*j], hv[4*j+1], hv[4*j+2], hv[4*j+3]);
        }
    } else {
        float4* od = (float4*)(outp + (size_t)myrow * HH) + q * 4;
#pragma unroll
        for (int j = 0; j < 4; j++)
            od[j] = make_float4(hv[4*j], hv[4*j+1], hv[4*j+2], hv[4*j+3]);
        if (tail) {
            float4* hd = (float4*)(hlast + (size_t)tb * HH) + q * 4;
#pragma unroll
            for (int j = 0; j < 4; j++)
                hd[j] = make_float4(hv[4*j], hv[4*j+1], hv[4*j+2], hv[4*j+3]);
        }
    }
}
#endif // HAS_TC

// ================================================================ fused kernel
__global__ void __launch_bounds__(NTHR, 2)
qlstm_fused_kernel(const float* __restrict__ x,
                   const float* __restrict__ W0raw,
                   const float* __restrict__ W1raw,
                   const __nv_bfloat16* __restrict__ B0hi_g,
                   const __nv_bfloat16* __restrict__ B0lo_g,
                   const __nv_bfloat16* __restrict__ B1hi_g,
                   const __nv_bfloat16* __restrict__ B1lo_g,
                   const float* __restrict__ b0, const float* __restrict__ th0,
                   const float* __restrict__ g0, const float* __restrict__ be0,
                   const float* __restrict__ b1, const float* __restrict__ th1,
                   const float* __restrict__ g1, const float* __restrict__ be1,
                   float* __restrict__ out,
                   float* __restrict__ h0last, float* __restrict__ c0last,
                   float* __restrict__ h1last, float* __restrict__ c1last)
{
    extern __shared__ __align__(1024) char smem[];
    const int tid = threadIdx.x, wid = tid >> 5, lane = tid & 31;
    const int q  = wid >> 2;                    // quarter 0..3 (16 gate cols)
    const int rl = (wid & 3) * 32 + lane;       // local row 0..127
    const int gid = 1 + (wid & 3);              // named-barrier id for row-group
    const int row0 = blockIdx.x * 128;
    const int myrow = row0 + rl;

    float* fp   = (float*)(smem + OFF_PAR);
    float* bt0  = fp;          // 192
    float* bt1  = fp + 192;    // 192
    float* gm0  = fp + 384;    // 64
    float* bet0 = fp + 448;
    float* gm1  = fp + 512;
    float* bet1 = fp + 576;
    float* exg  = fp + 640;    // 3 x 512 (per-gate exchange)
    float* exs  = fp + 2176;   // 512 (LN sum)
    float* exss = fp + 2688;   // 512 (LN sum of squares)

    if (tid < NG) {
        bt0[tid] = b0[64 + tid] + th0[64 + tid];
        bt1[tid] = b1[64 + tid] + th1[64 + tid];
    }
    if (tid >= 192 && tid < 256) {
        int i = tid - 192;
        gm0[i] = g0[i]; bet0[i] = be0[i];
        gm1[i] = g1[i]; bet1[i] = be1[i];
    }

#ifdef HAS_TC
    constexpr int NC = 8;
    const uint32_t sb  = smem_u32(smem);
    const uint32_t mb  = sb + OFF_CTRL + 8;     // MMA commit barrier
    const uint32_t mbB = sb + OFF_CTRL + 16;    // B-tile TMA data barrier
    if (wid == 0) {
        asm volatile("tcgen05.alloc.cta_group::1.sync.aligned.shared::cta.b32 [%0], %1;"
                     :: "r"(sb + OFF_CTRL), "r"(256u) : "memory");
        asm volatile("tcgen05.relinquish_alloc_permit.cta_group::1.sync.aligned;");
    }
    if (tid == 0) {
        asm volatile("mbarrier.init.shared.b64 [%0], %1;" :: "r"(mb),  "r"(1u) : "memory");
        asm volatile("mbarrier.init.shared.b64 [%0], %1;" :: "r"(mbB), "r"(1u) : "memory");
    }
    __syncthreads();
    uint32_t tmem;
    asm volatile("ld.shared.b32 %0, [%1];" : "=r"(tmem) : "r"(sb + OFF_CTRL));

    const uint64_t aHd = sdesc(sb + OFF_A);
    const uint64_t aLd = sdesc(sb + OFF_A + 16384);
    const uint64_t bHd = sdesc(sb + OFF_B);
    const uint64_t bLd = sdesc(sb + OFF_B + B_HALF);
    char* ah = smem + OFF_A;
    char* al = smem + OFF_A + 16384;

    // ---------------- layer-0 K-chunk loop (B via bulk TMA) ----------------
    for (int c = 0; c < NC; c++) {
        if (c > 0) mbar_wait(mb, (c - 1) & 1);   // A & B buffers free

        // B(c): one-thread bulk TMA (hi + lo halves) onto the data barrier
        if (tid == 0) {
            mbar_expect_tx(mbB, 2 * B_HALF);
            bulk_g2s(sb + OFF_B,          B0hi_g + (size_t)c * (NG * 64), B_HALF, mbB);
            bulk_g2s(sb + OFF_B + B_HALF, B0lo_g + (size_t)c * (NG * 64), B_HALF, mbB);
        }

        {   // A: fp32 -> bf16 hi/lo, SW128-swizzled STS (4 float4 / thread)
#pragma unroll
            for (int j = 0; j < 4; j++) {
                int idx = tid + j * NTHR;
                int r = idx >> 4, s = idx & 15;
                float4 v = *(const float4*)(x + (size_t)(row0 + r) * DDIM + c * 64 + s * 4);
                __nv_bfloat16 hx = __float2bfloat16(v.x);
                __nv_bfloat16 hy = __float2bfloat16(v.y);
                __nv_bfloat16 hz = __float2bfloat16(v.z);
                __nv_bfloat16 hw = __float2bfloat16(v.w);
                __nv_bfloat16 lx = __float2bfloat16(v.x - __bfloat162float(hx));
                __nv_bfloat16 ly = __float2bfloat16(v.y - __bfloat162float(hy));
                __nv_bfloat16 lz = __float2bfloat16(v.z - __bfloat162float(hz));
                __nv_bfloat16 lw = __float2bfloat16(v.w - __bfloat162float(hw));
                uint32_t off = (uint32_t)r * 128 + (uint32_t)s * 8;
                off ^= ((off >> 3) & 0x70);
                *(__nv_bfloat162*)(ah + off)     = __nv_bfloat162(hx, hy);
                *(__nv_bfloat162*)(ah + off + 4) = __nv_bfloat162(hz, hw);
                *(__nv_bfloat162*)(al + off)     = __nv_bfloat162(lx, ly);
                *(__nv_bfloat162*)(al + off + 4) = __nv_bfloat162(lz, lw);
            }
        }
        __syncthreads();                          // A tile complete

        if (wid == 0 && elect1()) {
            mbar_wait(mbB, c & 1);                // B tile delivered
            asm volatile("fence.proxy.async.shared::cta;" ::: "memory");
#pragma unroll
            for (int ks = 0; ks < 4; ks++)
                mma_bf16_ss(tmem, aHd + ks * 2, bHd + ks * 2, IDESC, !(c == 0 && ks == 0));
#pragma unroll
            for (int ks = 0; ks < 4; ks++)
                mma_bf16_ss(tmem, aHd + ks * 2, bLd + ks * 2, IDESC, true);
#pragma unroll
            for (int ks = 0; ks < 4; ks++)
                mma_bf16_ss(tmem, aLd + ks * 2, bHd + ks * 2, IDESC, true);
            asm volatile(
                "tcgen05.commit.cta_group::1.mbarrier::arrive::one.shared::cluster.b64 [%0];"
                :: "r"(mb) : "memory");
        }
    }

    mbar_wait(mb, (NC - 1) & 1);
    asm volatile("tcgen05.fence::after_thread_sync;" ::: "memory");

    // B1 via bulk TMA — overlaps the whole epilogue-0
    if (tid == 0) {
        mbar_expect_tx(mbB, 2 * B_HALF);
        bulk_g2s(sb + OFF_B,          B1hi_g, B_HALF, mbB);
        bulk_g2s(sb + OFF_B + B_HALF, B1lo_g, B_HALF, mbB);
    }

    // ---------------- epilogue 0 (writes layer-1 A tile) ----------------
    epilogue_quarter<true>(tmem, bt0, gm0, bet0, exg, exs, exss, ah, al,
                           nullptr, h0last, c0last, q, rl, gid, myrow);

    asm volatile("tcgen05.fence::before_thread_sync;" ::: "memory");
    __syncthreads();

    // ---------------- layer-1 GEMM (K=64, reuse TMEM cols 0-191) ----------
    if (wid == 0 && elect1()) {
        mbar_wait(mbB, NC & 1);                   // B1 delivered (9th -> parity 0)
        asm volatile("tcgen05.fence::after_thread_sync;" ::: "memory");
        asm volatile("fence.proxy.async.shared::cta;" ::: "memory");
#pragma unroll
        for (int ks = 0; ks < 4; ks++)
            mma_bf16_ss(tmem, aHd + ks * 2, bHd + ks * 2, IDESC, ks != 0);
#pragma unroll
        for (int ks = 0; ks < 4; ks++)
            mma_bf16_ss(tmem, aHd + ks * 2, bLd + ks * 2, IDESC, true);
#pragma unroll
        for (int ks = 0; ks < 4; ks++)
            mma_bf16_ss(tmem, aLd + ks * 2, bHd + ks * 2, IDESC, true);
        asm volatile(
            "tcgen05.commit.cta_group::1.mbarrier::arrive::one.shared::cluster.b64 [%0];"
            :: "r"(mb) : "memory");
    }
    mbar_wait(mb, NC & 1);      // 9th commit completion -> parity 0
    asm volatile("tcgen05.fence::after_thread_sync;" ::: "memory");

    // ---------------- epilogue 1 (writes final output) ----------------
    epilogue_quarter<false>(tmem, bt1, gm1, bet1, exg, exs, exss, nullptr, nullptr,
                            out, h1last, c1last, q, rl, gid, myrow);

    asm volatile("tcgen05.fence::before_thread_sync;" ::: "memory");
    __syncthreads();
    if (wid == 0) {
        asm volatile("tcgen05.dealloc.cta_group::1.sync.aligned.b32 %0, %1;"
                     :: "r"(tmem), "r"(256u));
    }

#else  // ---------------- scalar fallback (correctness-only) ----------------
    float* xs = (float*)smem;                    // [128][64] fp32 (0..32KB)
    float* ws = (float*)(smem + 32768);          // [192][64] fp32 (32..80KB)
    const int colbase = q * 16;
    const bool tail = (myrow >= NROWS - BB);
    const int tb = myrow - (NROWS - BB);
    __syncthreads();

    float z[48];
#pragma unroll
    for (int i = 0; i < 48; i++) z[i] = 0.0f;

    for (int kt = 0; kt < 8; kt++) {
        __syncthreads();
        for (int i = tid; i < 128 * 16; i += NTHR) {
            int r = i >> 4, s = i & 15;
            *(float4*)&xs[r * 64 + s * 4] =
                *(const float4*)(x + (size_t)(row0 + r) * DDIM + kt * 64 + s * 4);
        }
        for (int i = tid; i < 192 * 16; i += NTHR) {
            int n = i >> 4, s = i & 15;
            *(float4*)&ws[n * 64 + s * 4] =
                *(const float4*)(W0raw + (size_t)(64 + n) * (DDIM + HH) + kt * 64 + s * 4);
        }
        __syncthreads();
        for (int g = 0; g < 3; g++)
            for (int j = 0; j < 16; j++) {
                int n = g * 64 + colbase + j;
                float acc = z[g * 16 + j];
                for (int k = 0; k < 64; k++)
                    acc = fmaf(xs[rl * 64 + k], ws[n * 64 + k], acc);
                z[g * 16 + j] = acc;
            }
    }

    for (int layer = 0; layer < 2; layer++) {
        const float* bt  = layer ? bt1  : bt0;
        const float* gm  = layer ? gm1  : gm0;
        const float* bet = layer ? bet1 : bet0;
        float* hl = layer ? h1last : h0last;
        float* cl = layer ? c1last : c0last;
        float hv[16];
        for (int g = 0; g < 3; g++) {
            float cs[16];
            for (int j = 0; j < 16; j++)
                cs[j] = cosf(z[g * 16 + j] + bt[g * 64 + colbase + j]);
            for (int j = 1; j < 16; j++) cs[j] *= cs[j - 1];
            exg[g * 512 + q * 128 + rl] = cs[15];
            __syncthreads();
            if (q > 0) {
                float p = exg[g * 512 + rl];
                if (q >= 2) p *= exg[g * 512 + 128 + rl];
                if (q >= 3) p *= exg[g * 512 + 256 + rl];
                for (int j = 0; j < 16; j++) cs[j] *= p;
            }
            __syncthreads();
            if (g == 0)      for (int j = 0; j < 16; j++) hv[j] = 1.0f / (1.0f + expf(-cs[j]));
            else if (g == 1) {
                for (int j = 0; j < 16; j++) hv[j] *= tanhf(1.0f / (1.0f + expf(-cs[j])));
                if (tail) for (int j = 0; j < 16; j++) cl[(size_t)tb * HH + colbase + j] = hv[j];
            } else           for (int j = 0; j < 16; j++) hv[j] = (1.0f / (1.0f + expf(-cs[j]))) * tanhf(hv[j]);
        }
        float s = 0.0f, ssq = 0.0f;
        for (int j = 0; j < 16; j++) { s += hv[j]; ssq += hv[j] * hv[j]; }
        exs[q * 128 + rl] = s;
        exss[q * 128 + rl] = ssq;
        __syncthreads();
        float mu  = (exs[rl] + exs[128 + rl] + exs[256 + rl] + exs[384 + rl]) * (1.0f / 64.0f);
        float eh2 = (exss[rl] + exss[128 + rl] + exss[256 + rl] + exss[384 + rl]) * (1.0f / 64.0f);
        float rinv = rsqrtf(eh2 - mu * mu + EPSV);
        for (int j = 0; j < 16; j++)
            hv[j] = (hv[j] - mu) * rinv * gm[colbase + j] + bet[colbase + j];
        __syncthreads();

        if (layer == 0) {
            for (int j = 0; j < 16; j++) xs[rl * 64 + colbase + j] = hv[j];
            __syncthreads();
            for (int i = tid; i < 192 * 16; i += NTHR) {
                int n = i >> 4, sdx = i & 15;
                *(float4*)&ws[n * 64 + sdx * 4] =
                    *(const float4*)(W1raw + (size_t)(64 + n) * (HH + HH) + sdx * 4);
            }
            __syncthreads();
            for (int g = 0; g < 3; g++)
                for (int j = 0; j < 16; j++) {
                    int n = g * 64 + colbase + j;
                    float acc = 0.0f;
                    for (int k = 0; k < 64; k++)
                        acc = fmaf(xs[rl * 64 + k], ws[n * 64 + k], acc);
                    z[g * 16 + j] = acc;
                }
            if (tail)
                for (int j = 0; j < 16; j++) hl[(size_t)tb * HH + colbase + j] = hv[j];
        } else {
            for (int j = 0; j < 16; j++) out[(size_t)myrow * HH + colbase + j] = hv[j];
            if (tail) for (int j = 0; j < 16; j++) hl[(size_t)tb * HH + colbase + j] = hv[j];
        }
        __syncthreads();
    }
#endif // HAS_TC
}

// ================================================================ launch
extern "C" void kernel_launch(void* const* d_in, const int* in_sizes, int n_in,
                              void* d_out, int out_size) {
    const float* inputs = (const float*)d_in[0];
    const float* W0  = (const float*)d_in[1];
    const float* b0  = (const float*)d_in[2];
    const float* th0 = (const float*)d_in[3];
    const float* g0  = (const float*)d_in[4];
    const float* be0 = (const float*)d_in[5];
    const float* W1  = (const float*)d_in[6];
    const float* b1  = (const float*)d_in[7];
    const float* th1 = (const float*)d_in[8];
    const float* g1  = (const float*)d_in[9];
    const float* be1 = (const float*)d_in[10];

    float* out = (float*)d_out;
    const size_t out_main = (size_t)NROWS * HH;
    float* h0last = out + out_main;
    float* c0last = h0last + BB * HH;
    float* h1last = c0last + BB * HH;
    float* c1last = h1last + BB * HH;

    __nv_bfloat16 *b0hi, *b0lo, *b1hi, *b1lo;
    cudaGetSymbolAddress((void**)&b0hi, g_B0hi);
    cudaGetSymbolAddress((void**)&b0lo, g_B0lo);
    cudaGetSymbolAddress((void**)&b1hi, g_B1hi);
    cudaGetSymbolAddress((void**)&b1lo, g_B1lo);

    cudaFuncSetAttribute((const void*)qlstm_fused_kernel,
                         cudaFuncAttributeMaxDynamicSharedMemorySize, SMEM_TOTAL);

    prep_w_kernel<<<(8 * NG * 64 + 255) / 256, 256>>>(W0, W1);

    qlstm_fused_kernel<<<NROWS / 128, NTHR, SMEM_TOTAL>>>(
        inputs, W0, W1, b0hi, b0lo, b1hi, b1lo,
        b0, th0, g0, be0, b1, th1, g1, be1,
        out, h0last, c0last, h1last, c1last);
}

// round 13
// speedup vs baseline: 1.3104x; 1.0476x over previous
#include <cuda_runtime.h>
#include <cuda_bf16.h>
#include <math.h>
#include <stdint.h>

// ---------------------------------------------------------------- constants
#define TT     512
#define BB     128
#define DDIM   512
#define HH     64
#define NROWS  (TT * BB)          // 65536 independent (t,b) rows
#define NG     192                // 3 gates (i, g, o) x 64 qubits
#define EPSV   1e-5f
#define NTHR   512

// Arch-specific feature gate: tcgen05 exists only on sm_10xa targets.
#if defined(__CUDA_ARCH__) && (defined(__CUDA_ARCH_FEAT_SM103_ALL) || \
    defined(__CUDA_ARCH_FEAT_SM100_ALL) || defined(__CUDA_ARCH_SPECIFIC__))
#define HAS_TC 1
#endif

// dynamic SMEM layout:
//   A:       0 (hi 16KB) / 16384 (lo 16KB)
//   B:   32768 (hi 24KB) / 57344 (lo 24KB)
//   params/exchange: 81920 (12.8KB: params 640f, gate-exch 3x512f, LN 2x512f)
//   ctrl: 94720 (tmem ptr +0, mbar commit +8, mbar B-data +16)
#define OFF_A      0
#define OFF_B      32768
#define OFF_PAR    81920
#define OFF_CTRL   94720
#define SMEM_TOTAL 94784

// idesc: kind::f16, bf16 x bf16 -> f32, M=128, N=192
#define IDESC ((1u << 4) | (1u << 7) | (1u << 10) | ((NG / 8) << 17) | ((128 / 16) << 24))

#define B_HALF 24576u             // bytes per B half-tile (192 x 64 bf16)

// ---------------------------------------------------------------- scratch
__device__ __nv_bfloat16  g_B0hi[8 * NG * 64];   // W0: 8 K-chunks, SW128 swizzled
__device__ __nv_bfloat16  g_B0lo[8 * NG * 64];
__device__ __nv_bfloat16  g_B1hi[NG * 64];       // W1: 1 K-chunk
__device__ __nv_bfloat16  g_B1lo[NG * 64];

// ================================================================ prolog
__global__ void prep_w_kernel(const float* __restrict__ W0,
                              const float* __restrict__ W1) {
#ifdef HAS_TC
    int idx = blockIdx.x * blockDim.x + threadIdx.x;
    if (idx < 8 * NG * 64) {
        int c   = idx / (NG * 64);
        int rem = idx % (NG * 64);
        int n   = rem / 64, kl = rem % 64;
        float w = W0[(size_t)(64 + n) * (DDIM + HH) + c * 64 + kl];
        __nv_bfloat16 hi = __float2bfloat16(w);
        __nv_bfloat16 lo = __float2bfloat16(w - __bfloat162float(hi));
        uint32_t boff = ((uint32_t)(n >> 3)) * 1024 + ((uint32_t)(n & 7)) * 128 + kl * 2;
        boff ^= ((boff >> 3) & 0x70);
        g_B0hi[(size_t)c * (NG * 64) + boff / 2] = hi;
        g_B0lo[(size_t)c * (NG * 64) + boff / 2] = lo;
    }
    if (idx < NG * 64) {
        int n = idx / 64, kl = idx % 64;
        float w = W1[(size_t)(64 + n) * (HH + HH) + kl];
        __nv_bfloat16 hi = __float2bfloat16(w);
        __nv_bfloat16 lo = __float2bfloat16(w - __bfloat162float(hi));
        uint32_t boff = ((uint32_t)(n >> 3)) * 1024 + ((uint32_t)(n & 7)) * 128 + kl * 2;
        boff ^= ((boff >> 3) & 0x70);
        g_B1hi[boff / 2] = hi;
        g_B1lo[boff / 2] = lo;
    }
#endif
}

// ================================================================ PTX helpers
#ifdef HAS_TC
typedef unsigned long long u64q;

static __device__ __forceinline__ uint32_t smem_u32(const void* p) {
    uint32_t a;
    asm("{ .reg .u64 t; cvta.to.shared.u64 t, %1; cvt.u32.u64 %0, t; }"
        : "=r"(a) : "l"(p));
    return a;
}
static __device__ __forceinline__ uint32_t elect1() {
    uint32_t p;
    asm volatile("{\n .reg .pred p;\n elect.sync _|p, 0xFFFFFFFF;\n selp.b32 %0,1,0,p;\n}"
                 : "=r"(p));
    return p;
}
static __device__ __forceinline__ uint64_t sdesc(uint32_t addr) {
    return (2ull << 61) | (1ull << 46) | (64ull << 32) | (1ull << 16)
         | ((uint64_t)(addr >> 4) & 0x3FFF);
}
static __device__ __forceinline__ void mma_bf16_ss(uint32_t d, uint64_t ad, uint64_t bd,
                                                   uint32_t idesc, bool accum) {
    uint32_t en = accum ? 1u : 0u;
    asm volatile(
        "{\n\t"
        ".reg .pred p;\n\t"
        "setp.ne.u32 p, %5, 0;\n\t"
        "tcgen05.mma.cta_group::1.kind::f16 [%0], %1, %2, %3, {%4, %4, %4, %4}, p;\n\t"
        "}"
        :: "r"(d), "l"(ad), "l"(bd), "r"(idesc), "r"(0u), "r"(en)
        : "memory");
}
static __device__ __forceinline__ void mbar_wait(uint32_t mbar, uint32_t parity) {
    uint32_t done;
    asm volatile(
        "{\n .reg .pred p;\n"
        " mbarrier.try_wait.parity.acquire.cta.shared::cta.b64 p, [%1], %2;\n"
        " selp.b32 %0, 1, 0, p;\n}"
        : "=r"(done) : "r"(mbar), "r"(parity) : "memory");
    if (!done) {
        asm volatile(
            "{\n .reg .pred P1;\n"
            "WL%=:\n"
            " mbarrier.try_wait.parity.acquire.cta.shared::cta.b64 P1, [%0], %1, 0x989680;\n"
            " @P1 bra.uni WD%=;\n"
            " bra.uni WL%=;\n"
            "WD%=:\n}"
            :: "r"(mbar), "r"(parity) : "memory");
    }
}
static __device__ __forceinline__ void bulk_g2s(uint32_t dst, const void* src,
                                                uint32_t bytes, uint32_t mbar) {
    asm volatile(
        "cp.async.bulk.shared::cta.global.mbarrier::complete_tx::bytes [%0], [%1], %2, [%3];"
        :: "r"(dst), "l"(src), "r"(bytes), "r"(mbar) : "memory");
}
static __device__ __forceinline__ void mbar_expect_tx(uint32_t mbar, uint32_t bytes) {
    asm volatile("mbarrier.arrive.expect_tx.shared.b64 _, [%0], %1;"
                 :: "r"(mbar), "r"(bytes) : "memory");
}
static __device__ __forceinline__ void gbar(int id) {
    asm volatile("bar.sync %0, %1;" :: "r"(id), "r"(128) : "memory");
}
#define TC_WAIT_LD() asm volatile("tcgen05.wait::ld.sync.aligned;" ::: "memory")
#define LDTM_X16(r, addr)                                              \
    asm volatile(                                                       \
        "tcgen05.ld.sync.aligned.32x32b.x16.b32 "                       \
        "{%0, %1, %2, %3, %4, %5, %6, %7, "                             \
        " %8, %9, %10, %11, %12, %13, %14, %15}, [%16];"                \
        : "=r"((r)[0]),  "=r"((r)[1]),  "=r"((r)[2]),  "=r"((r)[3]),    \
          "=r"((r)[4]),  "=r"((r)[5]),  "=r"((r)[6]),  "=r"((r)[7]),    \
          "=r"((r)[8]),  "=r"((r)[9]),  "=r"((r)[10]), "=r"((r)[11]),   \
          "=r"((r)[12]), "=r"((r)[13]), "=r"((r)[14]), "=r"((r)[15])    \
        : "r"(addr))

// ---- packed f32x2 (SASS FFMA2/FMUL2/FADD2; PTX-only pattern) ----
static __device__ __forceinline__ u64q pk(float a, float b) {
    u64q r; asm("mov.b64 %0, {%1, %2};" : "=l"(r) : "f"(a), "f"(b)); return r;
}
static __device__ __forceinline__ u64q pk2(float c) { return pk(c, c); }
static __device__ __forceinline__ void upk(u64q v, float& a, float& b) {
    asm("mov.b64 {%0, %1}, %2;" : "=f"(a), "=f"(b) : "l"(v));
}
static __device__ __forceinline__ u64q fma2(u64q a, u64q b, u64q c) {
    u64q r; asm("fma.rn.f32x2 %0, %1, %2, %3;" : "=l"(r) : "l"(a), "l"(b), "l"(c)); return r;
}
static __device__ __forceinline__ u64q mul2(u64q a, u64q b) {
    u64q r; asm("mul.rn.f32x2 %0, %1, %2;" : "=l"(r) : "l"(a), "l"(b)); return r;
}
static __device__ __forceinline__ u64q add2(u64q a, u64q b) {
    u64q r; asm("add.rn.f32x2 %0, %1, %2;" : "=l"(r) : "l"(a), "l"(b)); return r;
}
static __device__ __forceinline__ float frcp(float x) {
    float y; asm("rcp.approx.f32 %0, %1;" : "=f"(y) : "f"(x)); return y;
}
// packed sigmoid(q), |q| <= 1: odd poly deg-11, FMA-only
static __device__ __forceinline__ u64q psig2(u64q q) {
    u64q u = mul2(q, q);
    u64q p = fma2(u, pk2(-2.1638741e-6f), pk2(2.1358436e-5f));
    p = fma2(u, p, pk2(-2.1081349e-4f));
    p = fma2(u, p, pk2(2.0833333e-3f));
    p = fma2(u, p, pk2(-2.0833333e-2f));
    p = fma2(u, p, pk2(0.25f));
    return fma2(q, p, pk2(0.5f));
}
// packed tanh(x), 0 <= x <= 0.75: Pade(7,6); 2 scalar MUFU rcp
static __device__ __forceinline__ u64q ptanh2(u64q x) {
    u64q u = mul2(x, x);
    u64q n = fma2(add2(u, pk2(378.0f)), u, pk2(17325.0f));
    n = fma2(n, u, pk2(135135.0f));
    u64q d = fma2(pk2(28.0f), u, pk2(3150.0f));
    d = fma2(d, u, pk2(62370.0f));
    d = fma2(d, u, pk2(135135.0f));
    float d0, d1; upk(d, d0, d1);
    return mul2(mul2(x, n), pk(frcp(d0), frcp(d1)));
}

// ---------------------------------------------------------------- epilogue quarter
// Pairs (j, j+8) ride the two f32x2 halves: the quarter's two 8-chains scan
// in ONE packed chain, splice = one mul2 by (1, chain0_total).
template <bool L0>
static __device__ __forceinline__ void epilogue_quarter(
    uint32_t tmem, const float* __restrict__ bt,
    const float* __restrict__ gm, const float* __restrict__ bet,
    volatile float* exg, volatile float* exs, volatile float* exss,
    char* ahi, char* alo, float* __restrict__ outp,
    float* __restrict__ hlast, float* __restrict__ clast,
    int q, int rl, int gid, int myrow)
{
    u64q hvp[8];
    float cs[16];
    uint32_t* ru = (uint32_t*)cs;
    const int colbase = q * 16;
    const bool tail = (myrow >= NROWS - BB);
    const int tb = myrow - (NROWS - BB);

#pragma unroll
    for (int g = 0; g < 3; g++) {
        LDTM_X16(ru, tmem + g * 64 + colbase);
        TC_WAIT_LD();
#pragma unroll
        for (int j = 0; j < 16; j++)
            cs[j] = __cosf(__uint_as_float(ru[j]) + bt[g * 64 + colbase + j]);

        u64q pr[8];
#pragma unroll
        for (int j = 0; j < 8; j++) pr[j] = pk(cs[j], cs[8 + j]);
        // packed serial scan of both 8-chains at once
#pragma unroll
        for (int j = 1; j < 8; j++) pr[j] = mul2(pr[j], pr[j - 1]);
        float c0t, c1t; upk(pr[7], c0t, c1t);
        u64q spl = pk(1.0f, c0t);
#pragma unroll
        for (int j = 0; j < 8; j++) pr[j] = mul2(pr[j], spl);

        exg[g * 512 + q * 128 + rl] = c0t * c1t;   // quarter total
        gbar(gid);
        if (q > 0) {
            float p = exg[g * 512 + rl];
            if (q >= 2) p *= exg[g * 512 + 128 + rl];
            if (q >= 3) p *= exg[g * 512 + 256 + rl];
            u64q pp = pk2(p);
#pragma unroll
            for (int j = 0; j < 8; j++) pr[j] = mul2(pr[j], pp);
        }

        if (g == 0) {
#pragma unroll
            for (int j = 0; j < 8; j++) hvp[j] = psig2(pr[j]);
        } else if (g == 1) {
#pragma unroll
            for (int j = 0; j < 8; j++)
                hvp[j] = mul2(hvp[j], ptanh2(psig2(pr[j])));     // c
            if (tail) {
                float h[16];
#pragma unroll
                for (int j = 0; j < 8; j++) upk(hvp[j], h[j], h[8 + j]);
                float4* cd = (float4*)(clast + (size_t)tb * HH) + q * 4;
#pragma unroll
                for (int j = 0; j < 4; j++)
                    cd[j] = make_float4(h[4*j], h[4*j+1], h[4*j+2], h[4*j+3]);
            }
        } else {
#pragma unroll
            for (int j = 0; j < 8; j++)
                hvp[j] = mul2(psig2(pr[j]), ptanh2(hvp[j]));     // h
        }
    }

    // layernorm: packed partial sums, one exchange round
    u64q ps = hvp[0], pss = mul2(hvp[0], hvp[0]);
#pragma unroll
    for (int j = 1; j < 8; j++) {
        ps  = add2(ps, hvp[j]);
        pss = fma2(hvp[j], hvp[j], pss);
    }
    float sa, sb, qa, qb;
    upk(ps, sa, sb); upk(pss, qa, qb);
    exs[q * 128 + rl]  = sa + sb;
    exss[q * 128 + rl] = qa + qb;
    gbar(gid);
    float mu  = (exs[rl] + exs[128 + rl] + exs[256 + rl] + exs[384 + rl]) * (1.0f / 64.0f);
    float eh2 = (exss[rl] + exss[128 + rl] + exss[256 + rl] + exss[384 + rl]) * (1.0f / 64.0f);
    float rinv = rsqrtf(fmaf(-mu, mu, eh2) + EPSV);

    // affine: (hv - mu)*rinv*gm + bet, packed
    u64q rp  = pk2(rinv);
    u64q mrp = pk2(-mu * rinv);
    float h[16];
#pragma unroll
    for (int j = 0; j < 8; j++) {
        u64q t   = fma2(hvp[j], rp, mrp);
        u64q gmp = pk(gm[colbase + j],  gm[colbase + 8 + j]);
        u64q bep = pk(bet[colbase + j], bet[colbase + 8 + j]);
        u64q r   = fma2(t, gmp, bep);
        upk(r, h[j], h[8 + j]);
    }

    if (L0) {
        // h_ln -> bf16 hi/lo into SMEM A tile (SW128, layer-1 operand)
#pragma unroll
        for (int j8 = 0; j8 < 2; j8++) {
            __nv_bfloat162 ph[4], pl[4];
#pragma unroll
            for (int p2 = 0; p2 < 4; p2++) {
                float v0 = h[j8 * 8 + p2 * 2], v1 = h[j8 * 8 + p2 * 2 + 1];
                __nv_bfloat16 h0 = __float2bfloat16(v0);
                __nv_bfloat16 h1 = __float2bfloat16(v1);
                ph[p2] = __nv_bfloat162(h0, h1);
                pl[p2] = __nv_bfloat162(__float2bfloat16(v0 - __bfloat162float(h0)),
                                        __float2bfloat16(v1 - __bfloat162float(h1)));
            }
            uint32_t off = (uint32_t)rl * 128 + (uint32_t)q * 32 + j8 * 16;
            off ^= ((off >> 3) & 0x70);
            *(uint4*)(ahi + off) = *(uint4*)ph;
            *(uint4*)(alo + off) = *(uint4*)pl;
        }
        if (tail) {
            float4* hd = (float4*)(hlast + (size_t)tb * HH) + q * 4;
#pragma unroll
            for (int j = 0; j < 4; j++)
                hd[j] = make_float4(h[4*j], h[4*j+1], h[4*j+2], h[4*j+3]);
        }
    } else {
        float4* od = (float4*)(outp + (size_t)myrow * HH) + q * 4;
#pragma unroll
        for (int j = 0; j < 4; j++)
            od[j] = make_float4(h[4*j], h[4*j+1], h[4*j+2], h[4*j+3]);
        if (tail) {
            float4* hd = (float4*)(hlast + (size_t)tb * HH) + q * 4;
#pragma unroll
            for (int j = 0; j < 4; j++)
                hd[j] = make_float4(h[4*j], h[4*j+1], h[4*j+2], h[4*j+3]);
        }
    }
}
#endif // HAS_TC

// ================================================================ fused kernel
__global__ void __launch_bounds__(NTHR, 2)
qlstm_fused_kernel(const float* __restrict__ x,
                   const float* __restrict__ W0raw,
                   const float* __restrict__ W1raw,
                   const __nv_bfloat16* __restrict__ B0hi_g,
                   const __nv_bfloat16* __restrict__ B0lo_g,
                   const __nv_bfloat16* __restrict__ B1hi_g,
                   const __nv_bfloat16* __restrict__ B1lo_g,
                   const float* __restrict__ b0, const float* __restrict__ th0,
                   const float* __restrict__ g0, const float* __restrict__ be0,
                   const float* __restrict__ b1, const float* __restrict__ th1,
                   const float* __restrict__ g1, const float* __restrict__ be1,
                   float* __restrict__ out,
                   float* __restrict__ h0last, float* __restrict__ c0last,
                   float* __restrict__ h1last, float* __restrict__ c1last)
{
    extern __shared__ __align__(1024) char smem[];
    const int tid = threadIdx.x, wid = tid >> 5, lane = tid & 31;
    const int q  = wid >> 2;                    // quarter 0..3 (16 gate cols)
    const int rl = (wid & 3) * 32 + lane;       // local row 0..127
    const int gid = 1 + (wid & 3);              // named-barrier id for row-group
    const int row0 = blockIdx.x * 128;
    const int myrow = row0 + rl;

    float* fp   = (float*)(smem + OFF_PAR);
    float* bt0  = fp;          // 192
    float* bt1  = fp + 192;    // 192
    float* gm0  = fp + 384;    // 64
    float* bet0 = fp + 448;
    float* gm1  = fp + 512;
    float* bet1 = fp + 576;
    float* exg  = fp + 640;    // 3 x 512 (per-gate exchange)
    float* exs  = fp + 2176;   // 512 (LN sum)
    float* exss = fp + 2688;   // 512 (LN sum of squares)

    if (tid < NG) {
        bt0[tid] = b0[64 + tid] + th0[64 + tid];
        bt1[tid] = b1[64 + tid] + th1[64 + tid];
    }
    if (tid >= 192 && tid < 256) {
        int i = tid - 192;
        gm0[i] = g0[i]; bet0[i] = be0[i];
        gm1[i] = g1[i]; bet1[i] = be1[i];
    }

#ifdef HAS_TC
    constexpr int NC = 8;
    const uint32_t sb  = smem_u32(smem);
    const uint32_t mb  = sb + OFF_CTRL + 8;     // MMA commit barrier
    const uint32_t mbB = sb + OFF_CTRL + 16;    // B-tile TMA data barrier
    if (wid == 0) {
        asm volatile("tcgen05.alloc.cta_group::1.sync.aligned.shared::cta.b32 [%0], %1;"
                     :: "r"(sb + OFF_CTRL), "r"(256u) : "memory");
        asm volatile("tcgen05.relinquish_alloc_permit.cta_group::1.sync.aligned;");
    }
    if (tid == 0) {
        asm volatile("mbarrier.init.shared.b64 [%0], %1;" :: "r"(mb),  "r"(1u) : "memory");
        asm volatile("mbarrier.init.shared.b64 [%0], %1;" :: "r"(mbB), "r"(1u) : "memory");
    }
    __syncthreads();
    uint32_t tmem;
    asm volatile("ld.shared.b32 %0, [%1];" : "=r"(tmem) : "r"(sb + OFF_CTRL));

    const uint64_t aHd = sdesc(sb + OFF_A);
    const uint64_t aLd = sdesc(sb + OFF_A + 16384);
    const uint64_t bHd = sdesc(sb + OFF_B);
    const uint64_t bLd = sdesc(sb + OFF_B + B_HALF);
    char* ah = smem + OFF_A;
    char* al = smem + OFF_A + 16384;

    // ---------------- layer-0 K-chunk loop (B via bulk TMA) ----------------
    for (int c = 0; c < NC; c++) {
        if (c > 0) mbar_wait(mb, (c - 1) & 1);   // A & B buffers free

        if (tid == 0) {
            mbar_expect_tx(mbB, 2 * B_HALF);
            bulk_g2s(sb + OFF_B,          B0hi_g + (size_t)c * (NG * 64), B_HALF, mbB);
            bulk_g2s(sb + OFF_B + B_HALF, B0lo_g + (size_t)c * (NG * 64), B_HALF, mbB);
        }

        {   // A: fp32 -> bf16 hi/lo, SW128-swizzled STS (4 float4 / thread)
#pragma unroll
            for (int j = 0; j < 4; j++) {
                int idx = tid + j * NTHR;
                int r = idx >> 4, s = idx & 15;
                float4 v = *(const float4*)(x + (size_t)(row0 + r) * DDIM + c * 64 + s * 4);
                __nv_bfloat16 hx = __float2bfloat16(v.x);
                __nv_bfloat16 hy = __float2bfloat16(v.y);
                __nv_bfloat16 hz = __float2bfloat16(v.z);
                __nv_bfloat16 hw = __float2bfloat16(v.w);
                __nv_bfloat16 lx = __float2bfloat16(v.x - __bfloat162float(hx));
                __nv_bfloat16 ly = __float2bfloat16(v.y - __bfloat162float(hy));
                __nv_bfloat16 lz = __float2bfloat16(v.z - __bfloat162float(hz));
                __nv_bfloat16 lw = __float2bfloat16(v.w - __bfloat162float(hw));
                uint32_t off = (uint32_t)r * 128 + (uint32_t)s * 8;
                off ^= ((off >> 3) & 0x70);
                *(__nv_bfloat162*)(ah + off)     = __nv_bfloat162(hx, hy);
                *(__nv_bfloat162*)(ah + off + 4) = __nv_bfloat162(hz, hw);
                *(__nv_bfloat162*)(al + off)     = __nv_bfloat162(lx, ly);
                *(__nv_bfloat162*)(al + off + 4) = __nv_bfloat162(lz, lw);
            }
        }
        __syncthreads();                          // A tile complete

        if (wid == 0 && elect1()) {
            mbar_wait(mbB, c & 1);                // B tile delivered
            asm volatile("fence.proxy.async.shared::cta;" ::: "memory");
#pragma unroll
            for (int ks = 0; ks < 4; ks++)
                mma_bf16_ss(tmem, aHd + ks * 2, bHd + ks * 2, IDESC, !(c == 0 && ks == 0));
#pragma unroll
            for (int ks = 0; ks < 4; ks++)
                mma_bf16_ss(tmem, aHd + ks * 2, bLd + ks * 2, IDESC, true);
#pragma unroll
            for (int ks = 0; ks < 4; ks++)
                mma_bf16_ss(tmem, aLd + ks * 2, bHd + ks * 2, IDESC, true);
            asm volatile(
                "tcgen05.commit.cta_group::1.mbarrier::arrive::one.shared::cluster.b64 [%0];"
                :: "r"(mb) : "memory");
        }
    }

    mbar_wait(mb, (NC - 1) & 1);
    asm volatile("tcgen05.fence::after_thread_sync;" ::: "memory");

    // B1 via bulk TMA — overlaps the whole epilogue-0
    if (tid == 0) {
        mbar_expect_tx(mbB, 2 * B_HALF);
        bulk_g2s(sb + OFF_B,          B1hi_g, B_HALF, mbB);
        bulk_g2s(sb + OFF_B + B_HALF, B1lo_g, B_HALF, mbB);
    }

    // ---------------- epilogue 0 (writes layer-1 A tile) ----------------
    epilogue_quarter<true>(tmem, bt0, gm0, bet0, exg, exs, exss, ah, al,
                           nullptr, h0last, c0last, q, rl, gid, myrow);

    asm volatile("tcgen05.fence::before_thread_sync;" ::: "memory");
    __syncthreads();

    // ---------------- layer-1 GEMM (K=64, reuse TMEM cols 0-191) ----------
    if (wid == 0 && elect1()) {
        mbar_wait(mbB, NC & 1);                   // B1 delivered (9th -> parity 0)
        asm volatile("tcgen05.fence::after_thread_sync;" ::: "memory");
        asm volatile("fence.proxy.async.shared::cta;" ::: "memory");
#pragma unroll
        for (int ks = 0; ks < 4; ks++)
            mma_bf16_ss(tmem, aHd + ks * 2, bHd + ks * 2, IDESC, ks != 0);
#pragma unroll
        for (int ks = 0; ks < 4; ks++)
            mma_bf16_ss(tmem, aHd + ks * 2, bLd + ks * 2, IDESC, true);
#pragma unroll
        for (int ks = 0; ks < 4; ks++)
            mma_bf16_ss(tmem, aLd + ks * 2, bHd + ks * 2, IDESC, true);
        asm volatile(
            "tcgen05.commit.cta_group::1.mbarrier::arrive::one.shared::cluster.b64 [%0];"
            :: "r"(mb) : "memory");
    }
    mbar_wait(mb, NC & 1);      // 9th commit completion -> parity 0
    asm volatile("tcgen05.fence::after_thread_sync;" ::: "memory");

    // ---------------- epilogue 1 (writes final output) ----------------
    epilogue_quarter<false>(tmem, bt1, gm1, bet1, exg, exs, exss, nullptr, nullptr,
                            out, h1last, c1last, q, rl, gid, myrow);

    asm volatile("tcgen05.fence::before_thread_sync;" ::: "memory");
    __syncthreads();
    if (wid == 0) {
        asm volatile("tcgen05.dealloc.cta_group::1.sync.aligned.b32 %0, %1;"
                     :: "r"(tmem), "r"(256u));
    }

#else  // ---------------- scalar fallback (correctness-only) ----------------
    float* xs = (float*)smem;                    // [128][64] fp32 (0..32KB)
    float* ws = (float*)(smem + 32768);          // [192][64] fp32 (32..80KB)
    const int colbase = q * 16;
    const bool tail = (myrow >= NROWS - BB);
    const int tb = myrow - (NROWS - BB);
    __syncthreads();

    float z[48];
#pragma unroll
    for (int i = 0; i < 48; i++) z[i] = 0.0f;

    for (int kt = 0; kt < 8; kt++) {
        __syncthreads();
        for (int i = tid; i < 128 * 16; i += NTHR) {
            int r = i >> 4, s = i & 15;
            *(float4*)&xs[r * 64 + s * 4] =
                *(const float4*)(x + (size_t)(row0 + r) * DDIM + kt * 64 + s * 4);
        }
        for (int i = tid; i < 192 * 16; i += NTHR) {
            int n = i >> 4, s = i & 15;
            *(float4*)&ws[n * 64 + s * 4] =
                *(const float4*)(W0raw + (size_t)(64 + n) * (DDIM + HH) + kt * 64 + s * 4);
        }
        __syncthreads();
        for (int g = 0; g < 3; g++)
            for (int j = 0; j < 16; j++) {
                int n = g * 64 + colbase + j;
                float acc = z[g * 16 + j];
                for (int k = 0; k < 64; k++)
                    acc = fmaf(xs[rl * 64 + k], ws[n * 64 + k], acc);
                z[g * 16 + j] = acc;
            }
    }

    for (int layer = 0; layer < 2; layer++) {
        const float* bt  = layer ? bt1  : bt0;
        const float* gm  = layer ? gm1  : gm0;
        const float* bet = layer ? bet1 : bet0;
        float* hl = layer ? h1last : h0last;
        float* cl = layer ? c1last : c0last;
        float hv[16];
        for (int g = 0; g < 3; g++) {
            float cs[16];
            for (int j = 0; j < 16; j++)
                cs[j] = cosf(z[g * 16 + j] + bt[g * 64 + colbase + j]);
            for (int j = 1; j < 16; j++) cs[j] *= cs[j - 1];
            exg[g * 512 + q * 128 + rl] = cs[15];
            __syncthreads();
            if (q > 0) {
                float p = exg[g * 512 + rl];
                if (q >= 2) p *= exg[g * 512 + 128 + rl];
                if (q >= 3) p *= exg[g * 512 + 256 + rl];
                for (int j = 0; j < 16; j++) cs[j] *= p;
            }
            __syncthreads();
            if (g == 0)      for (int j = 0; j < 16; j++) hv[j] = 1.0f / (1.0f + expf(-cs[j]));
            else if (g == 1) {
                for (int j = 0; j < 16; j++) hv[j] *= tanhf(1.0f / (1.0f + expf(-cs[j])));
                if (tail) for (int j = 0; j < 16; j++) cl[(size_t)tb * HH + colbase + j] = hv[j];
            } else           for (int j = 0; j < 16; j++) hv[j] = (1.0f / (1.0f + expf(-cs[j]))) * tanhf(hv[j]);
        }
        float s = 0.0f, ssq = 0.0f;
        for (int j = 0; j < 16; j++) { s += hv[j]; ssq += hv[j] * hv[j]; }
        exs[q * 128 + rl] = s;
        exss[q * 128 + rl] = ssq;
        __syncthreads();
        float mu  = (exs[rl] + exs[128 + rl] + exs[256 + rl] + exs[384 + rl]) * (1.0f / 64.0f);
        float eh2 = (exss[rl] + exss[128 + rl] + exss[256 + rl] + exss[384 + rl]) * (1.0f / 64.0f);
        float rinv = rsqrtf(eh2 - mu * mu + EPSV);
        for (int j = 0; j < 16; j++)
            hv[j] = (hv[j] - mu) * rinv * gm[colbase + j] + bet[colbase + j];
        __syncthreads();

        if (layer == 0) {
            for (int j = 0; j < 16; j++) xs[rl * 64 + colbase + j] = hv[j];
            __syncthreads();
            for (int i = tid; i < 192 * 16; i += NTHR) {
                int n = i >> 4, sdx = i & 15;
                *(float4*)&ws[n * 64 + sdx * 4] =
                    *(const float4*)(W1raw + (size_t)(64 + n) * (HH + HH) + sdx * 4);
            }
            __syncthreads();
            for (int g = 0; g < 3; g++)
                for (int j = 0; j < 16; j++) {
                    int n = g * 64 + colbase + j;
                    float acc = 0.0f;
                    for (int k = 0; k < 64; k++)
                        acc = fmaf(xs[rl * 64 + k], ws[n * 64 + k], acc);
                    z[g * 16 + j] = acc;
                }
            if (tail)
                for (int j = 0; j < 16; j++) hl[(size_t)tb * HH + colbase + j] = hv[j];
        } else {
            for (int j = 0; j < 16; j++) out[(size_t)myrow * HH + colbase + j] = hv[j];
            if (tail) for (int j = 0; j < 16; j++) hl[(size_t)tb * HH + colbase + j] = hv[j];
        }
        __syncthreads();
    }
#endif // HAS_TC
}

// ================================================================ launch
extern "C" void kernel_launch(void* const* d_in, const int* in_sizes, int n_in,
                              void* d_out, int out_size) {
    const float* inputs = (const float*)d_in[0];
    const float* W0  = (const float*)d_in[1];
    const float* b0  = (const float*)d_in[2];
    const float* th0 = (const float*)d_in[3];
    const float* g0  = (const float*)d_in[4];
    const float* be0 = (const float*)d_in[5];
    const float* W1  = (const float*)d_in[6];
    const float* b1  = (const float*)d_in[7];
    const float* th1 = (const float*)d_in[8];
    const float* g1  = (const float*)d_in[9];
    const float* be1 = (const float*)d_in[10];

    float* out = (float*)d_out;
    const size_t out_main = (size_t)NROWS * HH;
    float* h0last = out + out_main;
    float* c0last = h0last + BB * HH;
    float* h1last = c0last + BB * HH;
    float* c1last = h1last + BB * HH;

    __nv_bfloat16 *b0hi, *b0lo, *b1hi, *b1lo;
    cudaGetSymbolAddress((void**)&b0hi, g_B0hi);
    cudaGetSymbolAddress((void**)&b0lo, g_B0lo);
    cudaGetSymbolAddress((void**)&b1hi, g_B1hi);
    cudaGetSymbolAddress((void**)&b1lo, g_B1lo);

    cudaFuncSetAttribute((const void*)qlstm_fused_kernel,
                         cudaFuncAttributeMaxDynamicSharedMemorySize, SMEM_TOTAL);

    prep_w_kernel<<<(8 * NG * 64 + 255) / 256, 256>>>(W0, W1);

    qlstm_fused_kernel<<<NROWS / 128, NTHR, SMEM_TOTAL>>>(
        inputs, W0, W1, b0hi, b0lo, b1hi, b1lo,
        b0, th0, g0, be0, b1, th1, g1, be1,
        out, h0last, c0last, h1last, c1last);
}

// round 14
// speedup vs baseline: 1.3248x; 1.0110x over previous
#include <cuda_runtime.h>
#include <cuda_bf16.h>
#include <math.h>
#include <stdint.h>

// ---------------------------------------------------------------- constants
#define TT     512
#define BB     128
#define DDIM   512
#define HH     64
#define NROWS  (TT * BB)          // 65536 independent (t,b) rows
#define NG     192                // 3 gates (i, g, o) x 64 qubits
#define EPSV   1e-5f
#define NTHR   512

// Arch-specific feature gate: tcgen05 exists only on sm_10xa targets.
#if defined(__CUDA_ARCH__) && (defined(__CUDA_ARCH_FEAT_SM103_ALL) || \
    defined(__CUDA_ARCH_FEAT_SM100_ALL) || defined(__CUDA_ARCH_SPECIFIC__))
#define HAS_TC 1
#endif

// dynamic SMEM layout:
//   A:       0 (hi 16KB) / 16384 (lo 16KB)
//   B:   32768 (hi 24KB) / 57344 (lo 24KB)
//   params/exchange: 81920 (12.8KB)
//   ctrl: 94720 (tmem ptr +0, mbar commit +8, mbar B-data +16)
#define OFF_A      0
#define OFF_B      32768
#define OFF_PAR    81920
#define OFF_CTRL   94720
#define SMEM_TOTAL 94784

// idesc: kind::f16, bf16 x bf16 -> f32, M=128, N=192
#define IDESC ((1u << 4) | (1u << 7) | (1u << 10) | ((NG / 8) << 17) | ((128 / 16) << 24))

#define B_HALF 24576u             // bytes per B half-tile (192 x 64 bf16)

// ---------------------------------------------------------------- scratch
__device__ __nv_bfloat16  g_B0hi[8 * NG * 64];   // W0: 8 K-chunks, SW128 swizzled
__device__ __nv_bfloat16  g_B0lo[8 * NG * 64];
__device__ __nv_bfloat16  g_B1hi[NG * 64];       // W1: 1 K-chunk
__device__ __nv_bfloat16  g_B1lo[NG * 64];

// ================================================================ prolog
// Vectorized: 4 weights/thread; 8B output blocks are swizzle-contiguous.
__global__ void prep_w_kernel(const float* __restrict__ W0,
                              const float* __restrict__ W1) {
#ifdef HAS_TC
    int idx = blockIdx.x * blockDim.x + threadIdx.x;
    if (idx < 8 * NG * 16) {
        int c   = idx / (NG * 16);
        int rem = idx % (NG * 16);
        int n = rem / 16, k4 = rem % 16;
        float4 w4 = *(const float4*)(W0 + (size_t)(64 + n) * (DDIM + HH) + c * 64 + k4 * 4);
        uint32_t h01, h23, l01, l23;
        asm("cvt.rn.bf16x2.f32 %0, %1, %2;" : "=r"(h01) : "f"(w4.y), "f"(w4.x));
        asm("cvt.rn.bf16x2.f32 %0, %1, %2;" : "=r"(h23) : "f"(w4.w), "f"(w4.z));
        float hx = __uint_as_float(h01 << 16);
        float hy = __uint_as_float(h01 & 0xffff0000u);
        float hz = __uint_as_float(h23 << 16);
        float hw = __uint_as_float(h23 & 0xffff0000u);
        asm("cvt.rn.bf16x2.f32 %0, %1, %2;" : "=r"(l01) : "f"(w4.y - hy), "f"(w4.x - hx));
        asm("cvt.rn.bf16x2.f32 %0, %1, %2;" : "=r"(l23) : "f"(w4.w - hw), "f"(w4.z - hz));
        uint32_t boff = ((uint32_t)(n >> 3)) * 1024 + ((uint32_t)(n & 7)) * 128
                      + (uint32_t)k4 * 8;
        boff ^= ((boff >> 3) & 0x70);
        *(uint2*)((char*)g_B0hi + (size_t)c * 24576 + boff) = make_uint2(h01, h23);
        *(uint2*)((char*)g_B0lo + (size_t)c * 24576 + boff) = make_uint2(l01, l23);
    }
    if (idx < NG * 16) {
        int n = idx / 16, k4 = idx % 16;
        float4 w4 = *(const float4*)(W1 + (size_t)(64 + n) * (HH + HH) + k4 * 4);
        uint32_t h01, h23, l01, l23;
        asm("cvt.rn.bf16x2.f32 %0, %1, %2;" : "=r"(h01) : "f"(w4.y), "f"(w4.x));
        asm("cvt.rn.bf16x2.f32 %0, %1, %2;" : "=r"(h23) : "f"(w4.w), "f"(w4.z));
        float hx = __uint_as_float(h01 << 16);
        float hy = __uint_as_float(h01 & 0xffff0000u);
        float hz = __uint_as_float(h23 << 16);
        float hw = __uint_as_float(h23 & 0xffff0000u);
        asm("cvt.rn.bf16x2.f32 %0, %1, %2;" : "=r"(l01) : "f"(w4.y - hy), "f"(w4.x - hx));
        asm("cvt.rn.bf16x2.f32 %0, %1, %2;" : "=r"(l23) : "f"(w4.w - hw), "f"(w4.z - hz));
        uint32_t boff = ((uint32_t)(n >> 3)) * 1024 + ((uint32_t)(n & 7)) * 128
                      + (uint32_t)k4 * 8;
        boff ^= ((boff >> 3) & 0x70);
        *(uint2*)((char*)g_B1hi + boff) = make_uint2(h01, h23);
        *(uint2*)((char*)g_B1lo + boff) = make_uint2(l01, l23);
    }
#endif
}

// ================================================================ PTX helpers
#ifdef HAS_TC
typedef unsigned long long u64q;

static __device__ __forceinline__ uint32_t smem_u32(const void* p) {
    uint32_t a;
    asm("{ .reg .u64 t; cvta.to.shared.u64 t, %1; cvt.u32.u64 %0, t; }"
        : "=r"(a) : "l"(p));
    return a;
}
static __device__ __forceinline__ uint32_t elect1() {
    uint32_t p;
    asm volatile("{\n .reg .pred p;\n elect.sync _|p, 0xFFFFFFFF;\n selp.b32 %0,1,0,p;\n}"
                 : "=r"(p));
    return p;
}
static __device__ __forceinline__ uint64_t sdesc(uint32_t addr) {
    return (2ull << 61) | (1ull << 46) | (64ull << 32) | (1ull << 16)
         | ((uint64_t)(addr >> 4) & 0x3FFF);
}
static __device__ __forceinline__ void mma_bf16_ss(uint32_t d, uint64_t ad, uint64_t bd,
                                                   uint32_t idesc, bool accum) {
    uint32_t en = accum ? 1u : 0u;
    asm volatile(
        "{\n\t"
        ".reg .pred p;\n\t"
        "setp.ne.u32 p, %5, 0;\n\t"
        "tcgen05.mma.cta_group::1.kind::f16 [%0], %1, %2, %3, {%4, %4, %4, %4}, p;\n\t"
        "}"
        :: "r"(d), "l"(ad), "l"(bd), "r"(idesc), "r"(0u), "r"(en)
        : "memory");
}
static __device__ __forceinline__ void mbar_wait(uint32_t mbar, uint32_t parity) {
    uint32_t done;
    asm volatile(
        "{\n .reg .pred p;\n"
        " mbarrier.try_wait.parity.acquire.cta.shared::cta.b64 p, [%1], %2;\n"
        " selp.b32 %0, 1, 0, p;\n}"
        : "=r"(done) : "r"(mbar), "r"(parity) : "memory");
    if (!done) {
        asm volatile(
            "{\n .reg .pred P1;\n"
            "WL%=:\n"
            " mbarrier.try_wait.parity.acquire.cta.shared::cta.b64 P1, [%0], %1, 0x989680;\n"
            " @P1 bra.uni WD%=;\n"
            " bra.uni WL%=;\n"
            "WD%=:\n}"
            :: "r"(mbar), "r"(parity) : "memory");
    }
}
static __device__ __forceinline__ void bulk_g2s(uint32_t dst, const void* src,
                                                uint32_t bytes, uint32_t mbar) {
    asm volatile(
        "cp.async.bulk.shared::cta.global.mbarrier::complete_tx::bytes [%0], [%1], %2, [%3];"
        :: "r"(dst), "l"(src), "r"(bytes), "r"(mbar) : "memory");
}
static __device__ __forceinline__ void mbar_expect_tx(uint32_t mbar, uint32_t bytes) {
    asm volatile("mbarrier.arrive.expect_tx.shared.b64 _, [%0], %1;"
                 :: "r"(mbar), "r"(bytes) : "memory");
}
static __device__ __forceinline__ void gbar(int id) {
    asm volatile("bar.sync %0, %1;" :: "r"(id), "r"(128) : "memory");
}
#define TC_WAIT_LD() asm volatile("tcgen05.wait::ld.sync.aligned;" ::: "memory")
#define LDTM_X16(r, addr)                                              \
    asm volatile(                                                       \
        "tcgen05.ld.sync.aligned.32x32b.x16.b32 "                       \
        "{%0, %1, %2, %3, %4, %5, %6, %7, "                             \
        " %8, %9, %10, %11, %12, %13, %14, %15}, [%16];"                \
        : "=r"((r)[0]),  "=r"((r)[1]),  "=r"((r)[2]),  "=r"((r)[3]),    \
          "=r"((r)[4]),  "=r"((r)[5]),  "=r"((r)[6]),  "=r"((r)[7]),    \
          "=r"((r)[8]),  "=r"((r)[9]),  "=r"((r)[10]), "=r"((r)[11]),   \
          "=r"((r)[12]), "=r"((r)[13]), "=r"((r)[14]), "=r"((r)[15])    \
        : "r"(addr))

// ---- packed f32x2 (SASS FFMA2/FMUL2/FADD2; PTX-only pattern) ----
static __device__ __forceinline__ u64q pk(float a, float b) {
    u64q r; asm("mov.b64 %0, {%1, %2};" : "=l"(r) : "f"(a), "f"(b)); return r;
}
static __device__ __forceinline__ u64q pk2(float c) { return pk(c, c); }
static __device__ __forceinline__ void upk(u64q v, float& a, float& b) {
    asm("mov.b64 {%0, %1}, %2;" : "=f"(a), "=f"(b) : "l"(v));
}
static __device__ __forceinline__ u64q fma2(u64q a, u64q b, u64q c) {
    u64q r; asm("fma.rn.f32x2 %0, %1, %2, %3;" : "=l"(r) : "l"(a), "l"(b), "l"(c)); return r;
}
static __device__ __forceinline__ u64q mul2(u64q a, u64q b) {
    u64q r; asm("mul.rn.f32x2 %0, %1, %2;" : "=l"(r) : "l"(a), "l"(b)); return r;
}
static __device__ __forceinline__ u64q add2(u64q a, u64q b) {
    u64q r; asm("add.rn.f32x2 %0, %1, %2;" : "=l"(r) : "l"(a), "l"(b)); return r;
}
static __device__ __forceinline__ float frcp(float x) {
    float y; asm("rcp.approx.f32 %0, %1;" : "=f"(y) : "f"(x)); return y;
}
// packed sigmoid(q), |q| <= 1: odd poly deg-11, FMA-only
static __device__ __forceinline__ u64q psig2(u64q q) {
    u64q u = mul2(q, q);
    u64q p = fma2(u, pk2(-2.1638741e-6f), pk2(2.1358436e-5f));
    p = fma2(u, p, pk2(-2.1081349e-4f));
    p = fma2(u, p, pk2(2.0833333e-3f));
    p = fma2(u, p, pk2(-2.0833333e-2f));
    p = fma2(u, p, pk2(0.25f));
    return fma2(q, p, pk2(0.5f));
}
// packed tanh(x), 0 <= x <= 0.75: Pade(7,6); SINGLE rcp via d0*d1 combine
static __device__ __forceinline__ u64q ptanh2(u64q x) {
    u64q u = mul2(x, x);
    u64q n = fma2(add2(u, pk2(378.0f)), u, pk2(17325.0f));
    n = fma2(n, u, pk2(135135.0f));
    u64q d = fma2(pk2(28.0f), u, pk2(3150.0f));
    d = fma2(d, u, pk2(62370.0f));
    d = fma2(d, u, pk2(135135.0f));
    float d0, d1; upk(d, d0, d1);
    float r = frcp(d0 * d1);               // one MUFU for both lanes
    return mul2(mul2(mul2(x, n), pk(d1, d0)), pk2(r));
}

// ---------------------------------------------------------------- epilogue quarter
template <bool L0>
static __device__ __forceinline__ void epilogue_quarter(
    uint32_t tmem, const float* __restrict__ bt,
    const float* __restrict__ gm, const float* __restrict__ bet,
    volatile float* exg, volatile float* exs, volatile float* exss,
    char* ahi, char* alo, float* __restrict__ outp,
    float* __restrict__ hlast, float* __restrict__ clast,
    int q, int rl, int gid, int myrow)
{
    u64q hvp[8];
    float cs[16];
    uint32_t* ru = (uint32_t*)cs;
    const int colbase = q * 16;
    const bool tail = (myrow >= NROWS - BB);
    const int tb = myrow - (NROWS - BB);

#pragma unroll
    for (int g = 0; g < 3; g++) {
        LDTM_X16(ru, tmem + g * 64 + colbase);
        TC_WAIT_LD();
#pragma unroll
        for (int j = 0; j < 16; j++)
            cs[j] = __cosf(__uint_as_float(ru[j]) + bt[g * 64 + colbase + j]);

        u64q pr[8];
#pragma unroll
        for (int j = 0; j < 8; j++) pr[j] = pk(cs[j], cs[8 + j]);
#pragma unroll
        for (int j = 1; j < 8; j++) pr[j] = mul2(pr[j], pr[j - 1]);
        float c0t, c1t; upk(pr[7], c0t, c1t);
        u64q spl = pk(1.0f, c0t);
#pragma unroll
        for (int j = 0; j < 8; j++) pr[j] = mul2(pr[j], spl);

        exg[g * 512 + q * 128 + rl] = c0t * c1t;
        gbar(gid);
        if (q > 0) {
            float p = exg[g * 512 + rl];
            if (q >= 2) p *= exg[g * 512 + 128 + rl];
            if (q >= 3) p *= exg[g * 512 + 256 + rl];
            u64q pp = pk2(p);
#pragma unroll
            for (int j = 0; j < 8; j++) pr[j] = mul2(pr[j], pp);
        }

        if (g == 0) {
#pragma unroll
            for (int j = 0; j < 8; j++) hvp[j] = psig2(pr[j]);
        } else if (g == 1) {
#pragma unroll
            for (int j = 0; j < 8; j++)
                hvp[j] = mul2(hvp[j], ptanh2(psig2(pr[j])));     // c
            if (tail) {
                float h[16];
#pragma unroll
                for (int j = 0; j < 8; j++) upk(hvp[j], h[j], h[8 + j]);
                float4* cd = (float4*)(clast + (size_t)tb * HH) + q * 4;
#pragma unroll
                for (int j = 0; j < 4; j++)
                    cd[j] = make_float4(h[4*j], h[4*j+1], h[4*j+2], h[4*j+3]);
            }
        } else {
#pragma unroll
            for (int j = 0; j < 8; j++)
                hvp[j] = mul2(psig2(pr[j]), ptanh2(hvp[j]));     // h
        }
    }

    // layernorm: packed partial sums, one exchange round
    u64q ps = hvp[0], pss = mul2(hvp[0], hvp[0]);
#pragma unroll
    for (int j = 1; j < 8; j++) {
        ps  = add2(ps, hvp[j]);
        pss = fma2(hvp[j], hvp[j], pss);
    }
    float sa, sb, qa, qb;
    upk(ps, sa, sb); upk(pss, qa, qb);
    exs[q * 128 + rl]  = sa + sb;
    exss[q * 128 + rl] = qa + qb;
    gbar(gid);
    float mu  = (exs[rl] + exs[128 + rl] + exs[256 + rl] + exs[384 + rl]) * (1.0f / 64.0f);
    float eh2 = (exss[rl] + exss[128 + rl] + exss[256 + rl] + exss[384 + rl]) * (1.0f / 64.0f);
    float rinv = rsqrtf(fmaf(-mu, mu, eh2) + EPSV);

    u64q rp  = pk2(rinv);
    u64q mrp = pk2(-mu * rinv);
    float h[16];
#pragma unroll
    for (int j = 0; j < 8; j++) {
        u64q t   = fma2(hvp[j], rp, mrp);
        u64q gmp = pk(gm[colbase + j],  gm[colbase + 8 + j]);
        u64q bep = pk(bet[colbase + j], bet[colbase + 8 + j]);
        u64q r   = fma2(t, gmp, bep);
        upk(r, h[j], h[8 + j]);
    }

    if (L0) {
#pragma unroll
        for (int j8 = 0; j8 < 2; j8++) {
            uint32_t hw[4], lw[4];
#pragma unroll
            for (int p2 = 0; p2 < 4; p2++) {
                float v0 = h[j8 * 8 + p2 * 2], v1 = h[j8 * 8 + p2 * 2 + 1];
                asm("cvt.rn.bf16x2.f32 %0, %1, %2;" : "=r"(hw[p2]) : "f"(v1), "f"(v0));
                float h0f = __uint_as_float(hw[p2] << 16);
                float h1f = __uint_as_float(hw[p2] & 0xffff0000u);
                asm("cvt.rn.bf16x2.f32 %0, %1, %2;" : "=r"(lw[p2])
                    : "f"(v1 - h1f), "f"(v0 - h0f));
            }
            uint32_t off = (uint32_t)rl * 128 + (uint32_t)q * 32 + j8 * 16;
            off ^= ((off >> 3) & 0x70);
            *(uint4*)(ahi + off) = make_uint4(hw[0], hw[1], hw[2], hw[3]);
            *(uint4*)(alo + off) = make_uint4(lw[0], lw[1], lw[2], lw[3]);
        }
        if (tail) {
            float4* hd = (float4*)(hlast + (size_t)tb * HH) + q * 4;
#pragma unroll
            for (int j = 0; j < 4; j++)
                hd[j] = make_float4(h[4*j], h[4*j+1], h[4*j+2], h[4*j+3]);
        }
    } else {
        float4* od = (float4*)(outp + (size_t)myrow * HH) + q * 4;
#pragma unroll
        for (int j = 0; j < 4; j++)
            od[j] = make_float4(h[4*j], h[4*j+1], h[4*j+2], h[4*j+3]);
        if (tail) {
            float4* hd = (float4*)(hlast + (size_t)tb * HH) + q * 4;
#pragma unroll
            for (int j = 0; j < 4; j++)
                hd[j] = make_float4(h[4*j], h[4*j+1], h[4*j+2], h[4*j+3]);
        }
    }
}
#endif // HAS_TC

// ================================================================ fused kernel
__global__ void __launch_bounds__(NTHR, 2)
qlstm_fused_kernel(const float* __restrict__ x,
                   const float* __restrict__ W0raw,
                   const float* __restrict__ W1raw,
                   const __nv_bfloat16* __restrict__ B0hi_g,
                   const __nv_bfloat16* __restrict__ B0lo_g,
                   const __nv_bfloat16* __restrict__ B1hi_g,
                   const __nv_bfloat16* __restrict__ B1lo_g,
                   const float* __restrict__ b0, const float* __restrict__ th0,
                   const float* __restrict__ g0, const float* __restrict__ be0,
                   const float* __restrict__ b1, const float* __restrict__ th1,
                   const float* __restrict__ g1, const float* __restrict__ be1,
                   float* __restrict__ out,
                   float* __restrict__ h0last, float* __restrict__ c0last,
                   float* __restrict__ h1last, float* __restrict__ c1last)
{
    extern __shared__ __align__(1024) char smem[];
    const int tid = threadIdx.x, wid = tid >> 5, lane = tid & 31;
    const int q  = wid >> 2;                    // quarter 0..3 (16 gate cols)
    const int rl = (wid & 3) * 32 + lane;       // local row 0..127
    const int gid = 1 + (wid & 3);              // named-barrier id for row-group
    const int row0 = blockIdx.x * 128;
    const int myrow = row0 + rl;

    float* fp   = (float*)(smem + OFF_PAR);
    float* bt0  = fp;          // 192
    float* bt1  = fp + 192;    // 192
    float* gm0  = fp + 384;    // 64
    float* bet0 = fp + 448;
    float* gm1  = fp + 512;
    float* bet1 = fp + 576;
    float* exg  = fp + 640;    // 3 x 512 (per-gate exchange)
    float* exs  = fp + 2176;   // 512 (LN sum)
    float* exss = fp + 2688;   // 512 (LN sum of squares)

    if (tid < NG) {
        bt0[tid] = b0[64 + tid] + th0[64 + tid];
        bt1[tid] = b1[64 + tid] + th1[64 + tid];
    }
    if (tid >= 192 && tid < 256) {
        int i = tid - 192;
        gm0[i] = g0[i]; bet0[i] = be0[i];
        gm1[i] = g1[i]; bet1[i] = be1[i];
    }

#ifdef HAS_TC
    constexpr int NC = 8;
    const uint32_t sb  = smem_u32(smem);
    const uint32_t mb  = sb + OFF_CTRL + 8;     // MMA commit barrier
    const uint32_t mbB = sb + OFF_CTRL + 16;    // B-tile TMA data barrier
    if (wid == 0) {
        asm volatile("tcgen05.alloc.cta_group::1.sync.aligned.shared::cta.b32 [%0], %1;"
                     :: "r"(sb + OFF_CTRL), "r"(256u) : "memory");
        asm volatile("tcgen05.relinquish_alloc_permit.cta_group::1.sync.aligned;");
    }
    if (tid == 0) {
        asm volatile("mbarrier.init.shared.b64 [%0], %1;" :: "r"(mb),  "r"(1u) : "memory");
        asm volatile("mbarrier.init.shared.b64 [%0], %1;" :: "r"(mbB), "r"(1u) : "memory");
    }
    __syncthreads();
    uint32_t tmem;
    asm volatile("ld.shared.b32 %0, [%1];" : "=r"(tmem) : "r"(sb + OFF_CTRL));

    const uint64_t aHd = sdesc(sb + OFF_A);
    const uint64_t aLd = sdesc(sb + OFF_A + 16384);
    const uint64_t bHd = sdesc(sb + OFF_B);
    const uint64_t bLd = sdesc(sb + OFF_B + B_HALF);
    char* ah = smem + OFF_A;
    char* al = smem + OFF_A + 16384;

    // ---------------- layer-0 K-chunk loop (B via bulk TMA) ----------------
    for (int c = 0; c < NC; c++) {
        if (c > 0) mbar_wait(mb, (c - 1) & 1);   // A & B buffers free

        if (tid == 0) {
            mbar_expect_tx(mbB, 2 * B_HALF);
            bulk_g2s(sb + OFF_B,          B0hi_g + (size_t)c * (NG * 64), B_HALF, mbB);
            bulk_g2s(sb + OFF_B + B_HALF, B0lo_g + (size_t)c * (NG * 64), B_HALF, mbB);
        }

        {   // A: fp32 -> bf16 hi/lo via cvt.bf16x2, STS.64 (4 float4 / thread)
#pragma unroll
            for (int j = 0; j < 4; j++) {
                int idx = tid + j * NTHR;
                int r = idx >> 4, s = idx & 15;
                float4 v = *(const float4*)(x + (size_t)(row0 + r) * DDIM + c * 64 + s * 4);
                uint32_t h01, h23, l01, l23;
                asm("cvt.rn.bf16x2.f32 %0, %1, %2;" : "=r"(h01) : "f"(v.y), "f"(v.x));
                asm("cvt.rn.bf16x2.f32 %0, %1, %2;" : "=r"(h23) : "f"(v.w), "f"(v.z));
                float hx = __uint_as_float(h01 << 16);
                float hy = __uint_as_float(h01 & 0xffff0000u);
                float hz = __uint_as_float(h23 << 16);
                float hw = __uint_as_float(h23 & 0xffff0000u);
                asm("cvt.rn.bf16x2.f32 %0, %1, %2;" : "=r"(l01) : "f"(v.y - hy), "f"(v.x - hx));
                asm("cvt.rn.bf16x2.f32 %0, %1, %2;" : "=r"(l23) : "f"(v.w - hw), "f"(v.z - hz));
                uint32_t off = (uint32_t)r * 128 + (uint32_t)s * 8;
                off ^= ((off >> 3) & 0x70);
                *(uint2*)(ah + off) = make_uint2(h01, h23);
                *(uint2*)(al + off) = make_uint2(l01, l23);
            }
        }
        __syncthreads();                          // A tile complete

        if (wid == 0 && elect1()) {
            mbar_wait(mbB, c & 1);                // B tile delivered
            asm volatile("fence.proxy.async.shared::cta;" ::: "memory");
#pragma unroll
            for (int ks = 0; ks < 4; ks++)
                mma_bf16_ss(tmem, aHd + ks * 2, bHd + ks * 2, IDESC, !(c == 0 && ks == 0));
#pragma unroll
            for (int ks = 0; ks < 4; ks++)
                mma_bf16_ss(tmem, aHd + ks * 2, bLd + ks * 2, IDESC, true);
#pragma unroll
            for (int ks = 0; ks < 4; ks++)
                mma_bf16_ss(tmem, aLd + ks * 2, bHd + ks * 2, IDESC, true);
            asm volatile(
                "tcgen05.commit.cta_group::1.mbarrier::arrive::one.shared::cluster.b64 [%0];"
                :: "r"(mb) : "memory");
        }
    }

    mbar_wait(mb, (NC - 1) & 1);
    asm volatile("tcgen05.fence::after_thread_sync;" ::: "memory");

    // B1 via bulk TMA — overlaps the whole epilogue-0
    if (tid == 0) {
        mbar_expect_tx(mbB, 2 * B_HALF);
        bulk_g2s(sb + OFF_B,          B1hi_g, B_HALF, mbB);
        bulk_g2s(sb + OFF_B + B_HALF, B1lo_g, B_HALF, mbB);
    }

    // ---------------- epilogue 0 (writes layer-1 A tile) ----------------
    epilogue_quarter<true>(tmem, bt0, gm0, bet0, exg, exs, exss, ah, al,
                           nullptr, h0last, c0last, q, rl, gid, myrow);

    asm volatile("tcgen05.fence::before_thread_sync;" ::: "memory");
    __syncthreads();

    // ---------------- layer-1 GEMM (K=64, reuse TMEM cols 0-191) ----------
    if (wid == 0 && elect1()) {
        mbar_wait(mbB, NC & 1);                   // B1 delivered (9th -> parity 0)
        asm volatile("tcgen05.fence::after_thread_sync;" ::: "memory");
        asm volatile("fence.proxy.async.shared::cta;" ::: "memory");
#pragma unroll
        for (int ks = 0; ks < 4; ks++)
            mma_bf16_ss(tmem, aHd + ks * 2, bHd + ks * 2, IDESC, ks != 0);
#pragma unroll
        for (int ks = 0; ks < 4; ks++)
            mma_bf16_ss(tmem, aHd + ks * 2, bLd + ks * 2, IDESC, true);
#pragma unroll
        for (int ks = 0; ks < 4; ks++)
            mma_bf16_ss(tmem, aLd + ks * 2, bHd + ks * 2, IDESC, true);
        asm volatile(
            "tcgen05.commit.cta_group::1.mbarrier::arrive::one.shared::cluster.b64 [%0];"
            :: "r"(mb) : "memory");
    }
    mbar_wait(mb, NC & 1);      // 9th commit completion -> parity 0
    asm volatile("tcgen05.fence::after_thread_sync;" ::: "memory");

    // ---------------- epilogue 1 (writes final output) ----------------
    epilogue_quarter<false>(tmem, bt1, gm1, bet1, exg, exs, exss, nullptr, nullptr,
                            out, h1last, c1last, q, rl, gid, myrow);

    asm volatile("tcgen05.fence::before_thread_sync;" ::: "memory");
    __syncthreads();
    if (wid == 0) {
        asm volatile("tcgen05.dealloc.cta_group::1.sync.aligned.b32 %0, %1;"
                     :: "r"(tmem), "r"(256u));
    }

#else  // ---------------- scalar fallback (correctness-only) ----------------
    float* xs = (float*)smem;                    // [128][64] fp32 (0..32KB)
    float* ws = (float*)(smem + 32768);          // [192][64] fp32 (32..80KB)
    const int colbase = q * 16;
    const bool tail = (myrow >= NROWS - BB);
    const int tb = myrow - (NROWS - BB);
    __syncthreads();

    float z[48];
#pragma unroll
    for (int i = 0; i < 48; i++) z[i] = 0.0f;

    for (int kt = 0; kt < 8; kt++) {
        __syncthreads();
        for (int i = tid; i < 128 * 16; i += NTHR) {
            int r = i >> 4, s = i & 15;
            *(float4*)&xs[r * 64 + s * 4] =
                *(const float4*)(x + (size_t)(row0 + r) * DDIM + kt * 64 + s * 4);
        }
        for (int i = tid; i < 192 * 16; i += NTHR) {
            int n = i >> 4, s = i & 15;
            *(float4*)&ws[n * 64 + s * 4] =
                *(const float4*)(W0raw + (size_t)(64 + n) * (DDIM + HH) + kt * 64 + s * 4);
        }
        __syncthreads();
        for (int g = 0; g < 3; g++)
            for (int j = 0; j < 16; j++) {
                int n = g * 64 + colbase + j;
                float acc = z[g * 16 + j];
                for (int k = 0; k < 64; k++)
                    acc = fmaf(xs[rl * 64 + k], ws[n * 64 + k], acc);
                z[g * 16 + j] = acc;
            }
    }

    for (int layer = 0; layer < 2; layer++) {
        const float* bt  = layer ? bt1  : bt0;
        const float* gm  = layer ? gm1  : gm0;
        const float* bet = layer ? bet1 : bet0;
        float* hl = layer ? h1last : h0last;
        float* cl = layer ? c1last : c0last;
        float hv[16];
        for (int g = 0; g < 3; g++) {
            float cs[16];
            for (int j = 0; j < 16; j++)
                cs[j] = cosf(z[g * 16 + j] + bt[g * 64 + colbase + j]);
            for (int j = 1; j < 16; j++) cs[j] *= cs[j - 1];
            exg[g * 512 + q * 128 + rl] = cs[15];
            __syncthreads();
            if (q > 0) {
                float p = exg[g * 512 + rl];
                if (q >= 2) p *= exg[g * 512 + 128 + rl];
                if (q >= 3) p *= exg[g * 512 + 256 + rl];
                for (int j = 0; j < 16; j++) cs[j] *= p;
            }
            __syncthreads();
            if (g == 0)      for (int j = 0; j < 16; j++) hv[j] = 1.0f / (1.0f + expf(-cs[j]));
            else if (g == 1) {
                for (int j = 0; j < 16; j++) hv[j] *= tanhf(1.0f / (1.0f + expf(-cs[j])));
                if (tail) for (int j = 0; j < 16; j++) cl[(size_t)tb * HH + colbase + j] = hv[j];
            } else           for (int j = 0; j < 16; j++) hv[j] = (1.0f / (1.0f + expf(-cs[j]))) * tanhf(hv[j]);
        }
        float s = 0.0f, ssq = 0.0f;
        for (int j = 0; j < 16; j++) { s += hv[j]; ssq += hv[j] * hv[j]; }
        exs[q * 128 + rl] = s;
        exss[q * 128 + rl] = ssq;
        __syncthreads();
        float mu  = (exs[rl] + exs[128 + rl] + exs[256 + rl] + exs[384 + rl]) * (1.0f / 64.0f);
        float eh2 = (exss[rl] + exss[128 + rl] + exss[256 + rl] + exss[384 + rl]) * (1.0f / 64.0f);
        float rinv = rsqrtf(eh2 - mu * mu + EPSV);
        for (int j = 0; j < 16; j++)
            hv[j] = (hv[j] - mu) * rinv * gm[colbase + j] + bet[colbase + j];
        __syncthreads();

        if (layer == 0) {
            for (int j = 0; j < 16; j++) xs[rl * 64 + colbase + j] = hv[j];
            __syncthreads();
            for (int i = tid; i < 192 * 16; i += NTHR) {
                int n = i >> 4, sdx = i & 15;
                *(float4*)&ws[n * 64 + sdx * 4] =
                    *(const float4*)(W1raw + (size_t)(64 + n) * (HH + HH) + sdx * 4);
            }
            __syncthreads();
            for (int g = 0; g < 3; g++)
                for (int j = 0; j < 16; j++) {
                    int n = g * 64 + colbase + j;
                    float acc = 0.0f;
                    for (int k = 0; k < 64; k++)
                        acc = fmaf(xs[rl * 64 + k], ws[n * 64 + k], acc);
                    z[g * 16 + j] = acc;
                }
            if (tail)
                for (int j = 0; j < 16; j++) hl[(size_t)tb * HH + colbase + j] = hv[j];
        } else {
            for (int j = 0; j < 16; j++) out[(size_t)myrow * HH + colbase + j] = hv[j];
            if (tail) for (int j = 0; j < 16; j++) hl[(size_t)tb * HH + colbase + j] = hv[j];
        }
        __syncthreads();
    }
#endif // HAS_TC
}

// ================================================================ launch
extern "C" void kernel_launch(void* const* d_in, const int* in_sizes, int n_in,
                              void* d_out, int out_size) {
    const float* inputs = (const float*)d_in[0];
    const float* W0  = (const float*)d_in[1];
    const float* b0  = (const float*)d_in[2];
    const float* th0 = (const float*)d_in[3];
    const float* g0  = (const float*)d_in[4];
    const float* be0 = (const float*)d_in[5];
    const float* W1  = (const float*)d_in[6];
    const float* b1  = (const float*)d_in[7];
    const float* th1 = (const float*)d_in[8];
    const float* g1  = (const float*)d_in[9];
    const float* be1 = (const float*)d_in[10];

    float* out = (float*)d_out;
    const size_t out_main = (size_t)NROWS * HH;
    float* h0last = out + out_main;
    float* c0last = h0last + BB * HH;
    float* h1last = c0last + BB * HH;
    float* c1last = h1last + BB * HH;

    __nv_bfloat16 *b0hi, *b0lo, *b1hi, *b1lo;
    cudaGetSymbolAddress((void**)&b0hi, g_B0hi);
    cudaGetSymbolAddress((void**)&b0lo, g_B0lo);
    cudaGetSymbolAddress((void**)&b1hi, g_B1hi);
    cudaGetSymbolAddress((void**)&b1lo, g_B1lo);

    cudaFuncSetAttribute((const void*)qlstm_fused_kernel,
                         cudaFuncAttributeMaxDynamicSharedMemorySize, SMEM_TOTAL);

    prep_w_kernel<<<(8 * NG * 16 + 255) / 256, 256>>>(W0, W1);

    qlstm_fused_kernel<<<NROWS / 128, NTHR, SMEM_TOTAL>>>(
        inputs, W0, W1, b0hi, b0lo, b1hi, b1lo,
        b0, th0, g0, be0, b1, th1, g1, be1,
        out, h0last, c0last, h1last, c1last);
}